// round 7
// baseline (speedup 1.0000x reference)
#include <cuda_runtime.h>
#include <cuda_bf16.h>
#include <cstdint>
#include <math.h>

// ---------------- problem constants ----------------
#define L_TOT   13294          // 10000 + 2500 + 625 + 169
#define BATCH   4
#define MROWS   (BATCH * L_TOT)   // 53176
#define DMODEL  256
#define DFFN    1024
#define NLAYERS_C 6
#define NHEADS  8

// weight-pair layout offsets (elements) within one layer block
#define OFF_VP    0
#define OFF_SOAW  65536          // combined so(256) + aw(128) rows => [384,256]
#define OFF_OP    163840
#define OFF_F1    229376
#define OFF_F2    491520
#define LW_STRIDE 753664

// ---------------- device scratch (static, allowed) ----------------
__device__ __align__(16) float g_src  [MROWS * DMODEL];
__device__ __align__(16) float g_pos  [MROWS * DMODEL];
__device__ __align__(16) float g_val  [MROWS * DMODEL];
__device__ __align__(16) float g_offaw[MROWS * 384];
__device__ __align__(16) float g_tmp  [MROWS * DMODEL];

__device__ __align__(16) __nv_bfloat16 g_src_hi [MROWS * DMODEL];
__device__ __align__(16) __nv_bfloat16 g_src_lo [MROWS * DMODEL];
__device__ __align__(16) __nv_bfloat16 g_q_hi   [MROWS * DMODEL];
__device__ __align__(16) __nv_bfloat16 g_q_lo   [MROWS * DMODEL];
__device__ __align__(16) __nv_bfloat16 g_attn_hi[MROWS * DMODEL];
__device__ __align__(16) __nv_bfloat16 g_attn_lo[MROWS * DMODEL];
__device__ __align__(16) __nv_bfloat16 g_h_hi   [(size_t)MROWS * DFFN];
__device__ __align__(16) __nv_bfloat16 g_h_lo   [(size_t)MROWS * DFFN];
__device__ __align__(16) __nv_bfloat16 g_w_hi   [NLAYERS_C * LW_STRIDE];
__device__ __align__(16) __nv_bfloat16 g_w_lo   [NLAYERS_C * LW_STRIDE];

// ---------------- helpers ----------------
__device__ __forceinline__ uint32_t smem_u32(const void* p) {
    uint32_t a;
    asm("{ .reg .u64 t; cvta.to.shared.u64 t, %1; cvt.u32.u64 %0, t; }" : "=r"(a) : "l"(p));
    return a;
}

__device__ __forceinline__ void split_bf16(float x, __nv_bfloat16& h, __nv_bfloat16& l) {
    h = __float2bfloat16(x);
    l = __float2bfloat16(x - __bfloat162float(h));
}

#define LDMX4(r, addr) \
    asm volatile("ldmatrix.sync.aligned.m8n8.x4.shared.b16 {%0,%1,%2,%3}, [%4];" \
        : "=r"((r)[0]), "=r"((r)[1]), "=r"((r)[2]), "=r"((r)[3]) : "r"(addr))

__device__ __forceinline__ void mma16816(float* c, const uint32_t* a, const uint32_t* b) {
    asm volatile(
        "mma.sync.aligned.m16n8k16.row.col.f32.bf16.bf16.f32 "
        "{%0,%1,%2,%3}, {%4,%5,%6,%7}, {%8,%9}, {%0,%1,%2,%3};\n"
        : "+f"(c[0]), "+f"(c[1]), "+f"(c[2]), "+f"(c[3])
        : "r"(a[0]), "r"(a[1]), "r"(a[2]), "r"(a[3]), "r"(b[0]), "r"(b[1]));
}

#define CP_ASYNC16(dst, src, sz) \
    asm volatile("cp.async.cg.shared.global [%0], [%1], 16, %2;" \
        :: "r"(dst), "l"(src), "r"(sz))
#define CP_COMMIT() asm volatile("cp.async.commit_group;" ::: "memory")
#define CP_WAIT0()  asm volatile("cp.async.wait_group 0;" ::: "memory")

// ---------------- weight prep (all layers in one launch per weight type) -----------
// W fp32 [nlayers, K, N] -> dst hi/lo bf16 [nlayers(dst_stride), N, K]
__global__ void wprep_kernel(const float* __restrict__ W,
                             __nv_bfloat16* __restrict__ oh, __nv_bfloat16* __restrict__ ol,
                             int K, int N, int nlayers, size_t dst_stride)
{
    int idx = blockIdx.x * blockDim.x + threadIdx.x;
    int per = K * N;
    if (idx >= per * nlayers) return;
    int l = idx / per;
    int rem = idx - l * per;
    int n = rem / K, k = rem - n * K;
    float x = __ldg(W + (size_t)l * per + (size_t)k * N + n);
    __nv_bfloat16 h, lo;
    split_bf16(x, h, lo);
    size_t d = (size_t)l * dst_stride + (size_t)n * K + k;
    oh[d] = h;
    ol[d] = lo;
}

// ---------------- flatten: (B,D,H,W) -> (B,L,D); emits src pair + q pair -----------
__global__ void flatten_kernel(const float* __restrict__ s0, const float* __restrict__ s1,
                               const float* __restrict__ s2, const float* __restrict__ s3,
                               const float* __restrict__ p0, const float* __restrict__ p1,
                               const float* __restrict__ p2, const float* __restrict__ p3,
                               const float* __restrict__ lvl_emb)
{
    long long idx = (long long)blockIdx.x * blockDim.x + threadIdx.x;
    const long long tot = (long long)MROWS * DMODEL;
    if (idx >= tot) return;
    int d = (int)(idx & 255);
    int m = (int)(idx >> 8);
    int b = m / L_TOT;
    int n = m - b * L_TOT;
    int lvl, hw, HW;
    const float *sp, *pp;
    if (n < 10000)      { lvl = 0; hw = n;         HW = 10000; sp = s0; pp = p0; }
    else if (n < 12500) { lvl = 1; hw = n - 10000; HW = 2500;  sp = s1; pp = p1; }
    else if (n < 13125) { lvl = 2; hw = n - 12500; HW = 625;   sp = s2; pp = p2; }
    else                { lvl = 3; hw = n - 13125; HW = 169;   sp = s3; pp = p3; }
    size_t sidx = ((size_t)b * DMODEL + d) * HW + hw;
    float sv = __ldg(sp + sidx);
    float pv = __ldg(pp + sidx) + __ldg(lvl_emb + lvl * DMODEL + d);
    g_src[idx] = sv;
    g_pos[idx] = pv;
    __nv_bfloat16 h, l;
    split_bf16(sv, h, l);
    g_src_hi[idx] = h; g_src_lo[idx] = l;
    split_bf16(sv + pv, h, l);
    g_q_hi[idx] = h; g_q_lo[idx] = l;
}

// ---------------- HMMA split-bf16 GEMM, cp.async double-buffered, CTA 128x128 -------
// C[M,N] = A[M,K] @ W[K,N] + bias.  A bf16 hi/lo [M,K]; W bf16 hi/lo [N,K].
// 8 warps (4m x 2n), warp tile 32x64 (2 m16 x 8 n8).  BK=32.
// bias col<bias_split -> bias[col], else bias2[col-split].
// OUTMODE 0: fp32 out (opt RELU); OUTMODE 1: bf16 hi/lo out (opt RELU).
template<bool RELU, int OUTMODE>
__global__ __launch_bounds__(256)
void mma_gemm(const __nv_bfloat16* __restrict__ Ah, const __nv_bfloat16* __restrict__ Al,
              const __nv_bfloat16* __restrict__ Bh, const __nv_bfloat16* __restrict__ Bl,
              const float* __restrict__ bias, const float* __restrict__ bias2, int bias_split,
              float* __restrict__ Cf,
              __nv_bfloat16* __restrict__ Chi, __nv_bfloat16* __restrict__ Clo,
              int Mr, int K, int N)
{
    extern __shared__ char smem[];
    // per stage: AsH[128][40] AsL[128][40] BsH[128][40] BsL[128][40] (bf16, 80B rows)
    const int ASZ = 128 * 80;          // 10240 B
    const int BSZ = 128 * 80;          // 10240 B
    const int STG = 2 * ASZ + 2 * BSZ; // 40960 B

    const int tid  = threadIdx.x;
    const int lane = tid & 31;
    const int warp = tid >> 5;
    const int wm   = warp & 3;          // 0..3, 32 rows each
    const int wn   = warp >> 2;         // 0..1, 64 cols each
    const int row0 = blockIdx.x * 128;
    const int col0 = blockIdx.y * 128;

    const uint32_t smem_base = smem_u32(smem);

    const int ldRow = tid >> 2;           // 0..63 (rows ldRow, ldRow+64)
    const int ldOff = (tid & 3) << 3;     // element offset 0,8,16,24

    float acc[2][8][4];
    #pragma unroll
    for (int i = 0; i < 2; i++)
        #pragma unroll
        for (int j = 0; j < 8; j++)
            #pragma unroll
            for (int k = 0; k < 4; k++) acc[i][j][k] = 0.f;

    const int nch = K >> 5;

    auto load_chunk = [&](int ch, int stage) {
        const int kb = ch << 5;
        const uint32_t sb = smem_base + stage * STG;
        #pragma unroll
        for (int r = 0; r < 2; r++) {
            const int ar = ldRow + r * 64;
            // A rows (guarded)
            {
                const int ok = (row0 + ar < Mr) ? 16 : 0;
                const size_t g = (size_t)(row0 + ar) * K + kb + ldOff;
                const uint32_t so = sb + ar * 80 + ldOff * 2;
                CP_ASYNC16(so,       Ah + g, ok);
                CP_ASYNC16(so + ASZ, Al + g, ok);
            }
            // B rows (always valid: weight rows exist for all N)
            {
                const size_t g = (size_t)(col0 + ar) * K + kb + ldOff;
                const uint32_t so = sb + 2 * ASZ + ar * 80 + ldOff * 2;
                CP_ASYNC16(so,       Bh + g, 16);
                CP_ASYNC16(so + BSZ, Bl + g, 16);
            }
        }
    };

    load_chunk(0, 0);
    CP_COMMIT();

    for (int ch = 0; ch < nch; ch++) {
        const int buf = ch & 1;
        CP_WAIT0();
        __syncthreads();
        if (ch + 1 < nch) {
            load_chunk(ch + 1, buf ^ 1);
            CP_COMMIT();
        }
        const uint32_t sb = smem_base + buf * STG;

        #pragma unroll
        for (int ks = 0; ks < 2; ks++) {
            const int k0 = ks << 4;
            uint32_t afh[2][4], afl[2][4];
            #pragma unroll
            for (int mt = 0; mt < 2; mt++) {
                const int arow = wm * 32 + mt * 16 + (lane & 15);
                const int acol = k0 + ((lane >> 4) << 3);
                const uint32_t ad = sb + arow * 80 + acol * 2;
                LDMX4(afh[mt], ad);
                LDMX4(afl[mt], ad + ASZ);
            }
            #pragma unroll
            for (int np = 0; np < 4; np++) {
                const int tr = wn * 64 + np * 16 + ((lane >> 4) << 3) + (lane & 7);
                const int tc = k0 + (((lane >> 3) & 1) << 3);
                const uint32_t bd = sb + 2 * ASZ + tr * 80 + tc * 2;
                uint32_t bh[2][2], bl[2][2], t[4];
                LDMX4(t, bd);
                bh[0][0] = t[0]; bh[0][1] = t[1];
                bh[1][0] = t[2]; bh[1][1] = t[3];
                LDMX4(t, bd + BSZ);
                bl[0][0] = t[0]; bl[0][1] = t[1];
                bl[1][0] = t[2]; bl[1][1] = t[3];
                #pragma unroll
                for (int mt = 0; mt < 2; mt++)
                    #pragma unroll
                    for (int sub = 0; sub < 2; sub++) {
                        float* a = acc[mt][np * 2 + sub];
                        mma16816(a, afh[mt], bh[sub]);
                        mma16816(a, afh[mt], bl[sub]);
                        mma16816(a, afl[mt], bh[sub]);
                    }
            }
        }
        __syncthreads();
    }

    // epilogue
    const int g  = lane >> 2;
    const int tg = lane & 3;
    #pragma unroll
    for (int mt = 0; mt < 2; mt++) {
        #pragma unroll
        for (int nt = 0; nt < 8; nt++) {
            const int col = col0 + wn * 64 + nt * 8 + tg * 2;
            float b0, b1;
            if (col < bias_split) {
                b0 = __ldg(bias + col);
                b1 = __ldg(bias + col + 1);
            } else {
                b0 = __ldg(bias2 + col - bias_split);
                b1 = __ldg(bias2 + col - bias_split + 1);
            }
            #pragma unroll
            for (int half = 0; half < 2; half++) {
                const int row = row0 + wm * 32 + mt * 16 + g + half * 8;
                if (row < Mr) {
                    float v0 = acc[mt][nt][half * 2 + 0] + b0;
                    float v1 = acc[mt][nt][half * 2 + 1] + b1;
                    if (RELU) { v0 = fmaxf(v0, 0.f); v1 = fmaxf(v1, 0.f); }
                    if (OUTMODE == 0) {
                        *reinterpret_cast<float2*>(Cf + (size_t)row * N + col) = make_float2(v0, v1);
                    } else {
                        __nv_bfloat16 h0, l0, h1, l1;
                        split_bf16(v0, h0, l0);
                        split_bf16(v1, h1, l1);
                        size_t co = (size_t)row * N + col;
                        *reinterpret_cast<__nv_bfloat162*>(Chi + co) = __halves2bfloat162(h0, h1);
                        *reinterpret_cast<__nv_bfloat162*>(Clo + co) = __halves2bfloat162(l0, l1);
                    }
                }
            }
        }
    }
}

// ---------------- deformable attention sampling (one warp per (b,q,head)) -----------
// offaw row layout: [0,256) = offsets (h*32 each), [256,384) = aw logits (h*16 each)
__global__ void deform_kernel(const float* __restrict__ value,
                              const float* __restrict__ offaw,
                              __nv_bfloat16* __restrict__ out_hi,
                              __nv_bfloat16* __restrict__ out_lo)
{
    int gw = (int)((blockIdx.x * blockDim.x + threadIdx.x) >> 5);
    if (gw >= MROWS * NHEADS) return;
    int lane = threadIdx.x & 31;
    int h = gw & 7;
    int m = gw >> 3;
    int b = m / L_TOT;
    int q = m - b * L_TOT;

    float ref_x, ref_y;
    {
        int idx, Wl, Hl;
        if (q < 10000)      { idx = q;         Wl = 100; Hl = 100; }
        else if (q < 12500) { idx = q - 10000; Wl = 50;  Hl = 50;  }
        else if (q < 13125) { idx = q - 12500; Wl = 25;  Hl = 25;  }
        else                { idx = q - 13125; Wl = 13;  Hl = 13;  }
        int yy = idx / Wl, xx = idx - yy * Wl;
        ref_x = (xx + 0.5f) / (float)Wl;
        ref_y = (yy + 0.5f) / (float)Hl;
    }

    const float* awp = offaw + (size_t)m * 384 + 256 + h * 16;
    float e[16];
    float mx = -1e30f;
    #pragma unroll
    for (int i = 0; i < 16; i++) { e[i] = __ldg(awp + i); mx = fmaxf(mx, e[i]); }
    float ssum = 0.f;
    #pragma unroll
    for (int i = 0; i < 16; i++) { e[i] = __expf(e[i] - mx); ssum += e[i]; }
    float inv = 1.f / ssum;

    const float* offp  = offaw + (size_t)m * 384 + h * 32;
    const float* vbase = value + (size_t)b * L_TOT * 256 + h * 32 + lane;

    const int Ws[4]     = {100, 50, 25, 13};
    const int Hs[4]     = {100, 50, 25, 13};
    const int starts[4] = {0, 10000, 12500, 13125};

    float acc = 0.f;
    #pragma unroll
    for (int l = 0; l < 4; l++) {
        const int   Wl = Ws[l], Hl = Hs[l], st = starts[l];
        const float fW = (float)Wl, fH = (float)Hl;
        #pragma unroll
        for (int p = 0; p < 4; p++) {
            float ox = __ldg(offp + l * 8 + p * 2);
            float oy = __ldg(offp + l * 8 + p * 2 + 1);
            float px = ref_x * fW + ox - 0.5f;
            float py = ref_y * fH + oy - 0.5f;
            float x0f = floorf(px), y0f = floorf(py);
            float wx1 = px - x0f, wy1 = py - y0f;
            int x0 = (int)x0f, y0 = (int)y0f;
            float wgt = e[l * 4 + p] * inv;
            #pragma unroll
            for (int t = 0; t < 4; t++) {
                int xi = x0 + (t & 1);
                int yi = y0 + (t >> 1);
                float w = ((t & 1) ? wx1 : 1.f - wx1) * ((t >> 1) ? wy1 : 1.f - wy1);
                if (xi >= 0 && xi < Wl && yi >= 0 && yi < Hl && w != 0.f) {
                    acc = fmaf(wgt * w,
                               __ldg(vbase + (size_t)(st + yi * Wl + xi) * 256),
                               acc);
                }
            }
        }
    }
    size_t oidx = (size_t)m * 256 + h * 32 + lane;
    __nv_bfloat16 hh, ll;
    split_bf16(acc, hh, ll);
    out_hi[oidx] = hh;
    out_lo[oidx] = ll;
}

// ---------------- fused residual add + LayerNorm (one warp per row) -----------------
// emits fp32 out + bf16 pair; if pos != nullptr also emits q pair = split(out + pos)
__global__ void add_ln_kernel(const float* __restrict__ X, const float* __restrict__ R,
                              const float* __restrict__ w, const float* __restrict__ b,
                              const float* __restrict__ pos,
                              float* __restrict__ out,
                              __nv_bfloat16* __restrict__ out_hi,
                              __nv_bfloat16* __restrict__ out_lo,
                              __nv_bfloat16* __restrict__ q_hi,
                              __nv_bfloat16* __restrict__ q_lo)
{
    int row = (int)((blockIdx.x * blockDim.x + threadIdx.x) >> 5);
    if (row >= MROWS) return;
    int lane = threadIdx.x & 31;
    const float* x = X + (size_t)row * DMODEL;
    const float* r = R + (size_t)row * DMODEL;
    float v[8];
    float s = 0.f;
    #pragma unroll
    for (int j = 0; j < 8; j++) {
        int c = lane + j * 32;
        v[j] = x[c] + r[c];
        s += v[j];
    }
    #pragma unroll
    for (int o = 16; o > 0; o >>= 1) s += __shfl_xor_sync(0xFFFFFFFFu, s, o);
    float mean = s * (1.f / 256.f);
    float qv = 0.f;
    #pragma unroll
    for (int j = 0; j < 8; j++) { float d = v[j] - mean; qv += d * d; }
    #pragma unroll
    for (int o = 16; o > 0; o >>= 1) qv += __shfl_xor_sync(0xFFFFFFFFu, qv, o);
    float invs = rsqrtf(qv * (1.f / 256.f) + 1e-5f);
    #pragma unroll
    for (int j = 0; j < 8; j++) {
        int c = lane + j * 32;
        float o = (v[j] - mean) * invs * __ldg(w + c) + __ldg(b + c);
        size_t oi = (size_t)row * DMODEL + c;
        out[oi] = o;
        __nv_bfloat16 hh, ll;
        split_bf16(o, hh, ll);
        out_hi[oi] = hh;
        out_lo[oi] = ll;
        if (pos != nullptr) {
            split_bf16(o + __ldg(pos + oi), hh, ll);
            q_hi[oi] = hh;
            q_lo[oi] = ll;
        }
    }
}

// ---------------- output write: src then level_start_index (as floats) -------------
__global__ void write_out_kernel(float* __restrict__ out, int n)
{
    long long i = (long long)blockIdx.x * blockDim.x + threadIdx.x;
    if (i >= n) return;
    const long long tot = (long long)MROWS * DMODEL;
    if (i < tot) {
        out[i] = g_src[i];
    } else {
        int k = (int)(i - tot);
        float st;
        switch (k) {
            case 0: st = 0.f;      break;
            case 1: st = 10000.f;  break;
            case 2: st = 12500.f;  break;
            case 3: st = 13125.f;  break;
            default: st = 0.f;     break;
        }
        out[i] = st;
    }
}

// ---------------- host launch ----------------
extern "C" void kernel_launch(void* const* d_in, const int* in_sizes, int n_in,
                              void* d_out, int out_size)
{
    // setup_inputs() dict order is INTERLEAVED: src0, pos0, src1, pos1, ...
    const float* s0 = (const float*)d_in[0];
    const float* p0 = (const float*)d_in[1];
    const float* s1 = (const float*)d_in[2];
    const float* p1 = (const float*)d_in[3];
    const float* s2 = (const float*)d_in[4];
    const float* p2 = (const float*)d_in[5];
    const float* s3 = (const float*)d_in[6];
    const float* p3 = (const float*)d_in[7];
    const float* lvl_emb = (const float*)d_in[8];
    const float* so_w = (const float*)d_in[9];
    const float* so_b = (const float*)d_in[10];
    const float* aw_w = (const float*)d_in[11];
    const float* aw_b = (const float*)d_in[12];
    const float* vp_w = (const float*)d_in[13];
    const float* vp_b = (const float*)d_in[14];
    const float* op_w = (const float*)d_in[15];
    const float* op_b = (const float*)d_in[16];
    const float* n1_w = (const float*)d_in[17];
    const float* n1_b = (const float*)d_in[18];
    const float* f1_w = (const float*)d_in[19];
    const float* f1_b = (const float*)d_in[20];
    const float* f2_w = (const float*)d_in[21];
    const float* f2_b = (const float*)d_in[22];
    const float* n2_w = (const float*)d_in[23];
    const float* n2_b = (const float*)d_in[24];

    float *pg_src, *pg_pos, *pg_val, *pg_offaw, *pg_tmp;
    __nv_bfloat16 *pg_src_hi, *pg_src_lo, *pg_q_hi, *pg_q_lo;
    __nv_bfloat16 *pg_attn_hi, *pg_attn_lo, *pg_h_hi, *pg_h_lo, *pg_w_hi, *pg_w_lo;
    cudaGetSymbolAddress((void**)&pg_src,   g_src);
    cudaGetSymbolAddress((void**)&pg_pos,   g_pos);
    cudaGetSymbolAddress((void**)&pg_val,   g_val);
    cudaGetSymbolAddress((void**)&pg_offaw, g_offaw);
    cudaGetSymbolAddress((void**)&pg_tmp,   g_tmp);
    cudaGetSymbolAddress((void**)&pg_src_hi, g_src_hi);
    cudaGetSymbolAddress((void**)&pg_src_lo, g_src_lo);
    cudaGetSymbolAddress((void**)&pg_q_hi,   g_q_hi);
    cudaGetSymbolAddress((void**)&pg_q_lo,   g_q_lo);
    cudaGetSymbolAddress((void**)&pg_attn_hi, g_attn_hi);
    cudaGetSymbolAddress((void**)&pg_attn_lo, g_attn_lo);
    cudaGetSymbolAddress((void**)&pg_h_hi,   g_h_hi);
    cudaGetSymbolAddress((void**)&pg_h_lo,   g_h_lo);
    cudaGetSymbolAddress((void**)&pg_w_hi,   g_w_hi);
    cudaGetSymbolAddress((void**)&pg_w_lo,   g_w_lo);

    // dynamic smem for GEMM: 2 stages x 40960 B
    const int GEMM_SMEM = 81920;
    cudaFuncSetAttribute(mma_gemm<false, 0>, cudaFuncAttributeMaxDynamicSharedMemorySize, GEMM_SMEM);
    cudaFuncSetAttribute(mma_gemm<true, 1>,  cudaFuncAttributeMaxDynamicSharedMemorySize, GEMM_SMEM);

    const long long totElem = (long long)MROWS * DMODEL;
    const int ew_grid = (int)((totElem + 255) / 256);

    // ---- weight prep: 6 launches, all layers each ----
    wprep_kernel<<<(NLAYERS_C * 65536 + 255) / 256, 256>>>(vp_w, pg_w_hi + OFF_VP, pg_w_lo + OFF_VP, 256, 256, NLAYERS_C, LW_STRIDE);
    wprep_kernel<<<(NLAYERS_C * 65536 + 255) / 256, 256>>>(so_w, pg_w_hi + OFF_SOAW, pg_w_lo + OFF_SOAW, 256, 256, NLAYERS_C, LW_STRIDE);
    wprep_kernel<<<(NLAYERS_C * 32768 + 255) / 256, 256>>>(aw_w, pg_w_hi + OFF_SOAW + 65536, pg_w_lo + OFF_SOAW + 65536, 256, 128, NLAYERS_C, LW_STRIDE);
    wprep_kernel<<<(NLAYERS_C * 65536 + 255) / 256, 256>>>(op_w, pg_w_hi + OFF_OP, pg_w_lo + OFF_OP, 256, 256, NLAYERS_C, LW_STRIDE);
    wprep_kernel<<<(NLAYERS_C * 262144 + 255) / 256, 256>>>(f1_w, pg_w_hi + OFF_F1, pg_w_lo + OFF_F1, 256, 1024, NLAYERS_C, LW_STRIDE);
    wprep_kernel<<<(NLAYERS_C * 262144 + 255) / 256, 256>>>(f2_w, pg_w_hi + OFF_F2, pg_w_lo + OFF_F2, 1024, 256, NLAYERS_C, LW_STRIDE);

    flatten_kernel<<<ew_grid, 256>>>(s0, s1, s2, s3, p0, p1, p2, p3, lvl_emb);

    const int mblk = (MROWS + 127) / 128;   // 416
    const dim3 blk(256);
    const int ln_grid = (MROWS * 32 + 255) / 256;
    const int deform_grid = (MROWS * NHEADS * 32 + 255) / 256;

    for (int i = 0; i < NLAYERS_C; i++) {
        size_t wb = (size_t)i * LW_STRIDE;
        const __nv_bfloat16* vp_h = pg_w_hi + wb + OFF_VP;   const __nv_bfloat16* vp_l = pg_w_lo + wb + OFF_VP;
        const __nv_bfloat16* sa_h = pg_w_hi + wb + OFF_SOAW; const __nv_bfloat16* sa_l = pg_w_lo + wb + OFF_SOAW;
        const __nv_bfloat16* op_h = pg_w_hi + wb + OFF_OP;   const __nv_bfloat16* op_l = pg_w_lo + wb + OFF_OP;
        const __nv_bfloat16* f1_h = pg_w_hi + wb + OFF_F1;   const __nv_bfloat16* f1_l = pg_w_lo + wb + OFF_F1;
        const __nv_bfloat16* f2_h = pg_w_hi + wb + OFF_F2;   const __nv_bfloat16* f2_l = pg_w_lo + wb + OFF_F2;

        // value = src @ vp_w + vp_b  (fp32 out)
        mma_gemm<false, 0><<<dim3(mblk, 2), blk, GEMM_SMEM>>>(
            pg_src_hi, pg_src_lo, vp_h, vp_l, vp_b + (size_t)i * 256, vp_b + (size_t)i * 256, 256,
            pg_val, nullptr, nullptr, MROWS, 256, 256);
        // [offsets | aw] = q @ [so_w | aw_w] + [so_b | aw_b]  (N=384 fused)
        mma_gemm<false, 0><<<dim3(mblk, 3), blk, GEMM_SMEM>>>(
            pg_q_hi, pg_q_lo, sa_h, sa_l, so_b + (size_t)i * 256, aw_b + (size_t)i * 128, 256,
            pg_offaw, nullptr, nullptr, MROWS, 256, 384);
        // deformable sampling -> attn pair
        deform_kernel<<<deform_grid, 256>>>(pg_val, pg_offaw, pg_attn_hi, pg_attn_lo);
        // output proj
        mma_gemm<false, 0><<<dim3(mblk, 2), blk, GEMM_SMEM>>>(
            pg_attn_hi, pg_attn_lo, op_h, op_l, op_b + (size_t)i * 256, op_b + (size_t)i * 256, 256,
            pg_tmp, nullptr, nullptr, MROWS, 256, 256);
        // src = LN(src + attn_proj)  (no q emission)
        add_ln_kernel<<<ln_grid, 256>>>(pg_src, pg_tmp,
                                        n1_w + (size_t)i * DMODEL, n1_b + (size_t)i * DMODEL,
                                        nullptr, pg_src, pg_src_hi, pg_src_lo, nullptr, nullptr);
        // h = relu(src @ f1_w + f1_b)  (bf16 pair out)
        mma_gemm<true, 1><<<dim3(mblk, 8), blk, GEMM_SMEM>>>(
            pg_src_hi, pg_src_lo, f1_h, f1_l, f1_b + (size_t)i * DFFN, f1_b + (size_t)i * DFFN, DFFN,
            nullptr, pg_h_hi, pg_h_lo, MROWS, 256, DFFN);
        // tmp = h @ f2_w + f2_b
        mma_gemm<false, 0><<<dim3(mblk, 2), blk, GEMM_SMEM>>>(
            pg_h_hi, pg_h_lo, f2_h, f2_l, f2_b + (size_t)i * 256, f2_b + (size_t)i * 256, 256,
            pg_tmp, nullptr, nullptr, MROWS, 1024, 256);
        // src = LN(src + ffn), also emit q pair for next layer
        add_ln_kernel<<<ln_grid, 256>>>(pg_src, pg_tmp,
                                        n2_w + (size_t)i * DMODEL, n2_b + (size_t)i * DMODEL,
                                        pg_pos, pg_src, pg_src_hi, pg_src_lo, pg_q_hi, pg_q_lo);
    }

    write_out_kernel<<<(out_size + 255) / 256, 256>>>((float*)d_out, out_size);
}

// round 8
// speedup vs baseline: 1.1540x; 1.1540x over previous
#include <cuda_runtime.h>
#include <cuda_fp16.h>
#include <cstdint>
#include <math.h>

// ---------------- problem constants ----------------
#define L_TOT   13294          // 10000 + 2500 + 625 + 169
#define BATCH   4
#define MROWS   (BATCH * L_TOT)   // 53176
#define DMODEL  256
#define DFFN    1024
#define NLAYERS_C 6
#define NHEADS  8

// weight layout offsets (elements) within one layer block
#define OFF_VP    0
#define OFF_SOAW  65536          // combined so(256) + aw(128) rows => [384,256]
#define OFF_OP    163840
#define OFF_F1    229376
#define OFF_F2    491520
#define LW_STRIDE 753664

// ---------------- device scratch (static, allowed) ----------------
__device__ __align__(16) float g_src  [MROWS * DMODEL];
__device__ __align__(16) float g_pos  [MROWS * DMODEL];
__device__ __align__(16) float g_val  [MROWS * DMODEL];
__device__ __align__(16) float g_offaw[MROWS * 384];
__device__ __align__(16) float g_tmp  [MROWS * DMODEL];

__device__ __align__(16) __half g_src_hi [MROWS * DMODEL];
__device__ __align__(16) __half g_src_lo [MROWS * DMODEL];
__device__ __align__(16) __half g_q_hi   [MROWS * DMODEL];
__device__ __align__(16) __half g_q_lo   [MROWS * DMODEL];
__device__ __align__(16) __half g_attn_hi[MROWS * DMODEL];
__device__ __align__(16) __half g_attn_lo[MROWS * DMODEL];
__device__ __align__(16) __half g_h_hi   [(size_t)MROWS * DFFN];
__device__ __align__(16) __half g_h_lo   [(size_t)MROWS * DFFN];
__device__ __align__(16) __half g_w      [NLAYERS_C * LW_STRIDE];

// ---------------- helpers ----------------
__device__ __forceinline__ uint32_t smem_u32(const void* p) {
    uint32_t a;
    asm("{ .reg .u64 t; cvta.to.shared.u64 t, %1; cvt.u32.u64 %0, t; }" : "=r"(a) : "l"(p));
    return a;
}

__device__ __forceinline__ void split_half(float x, __half& h, __half& l) {
    h = __float2half(x);
    l = __float2half(x - __half2float(h));
}

#define LDMX4(r, addr) \
    asm volatile("ldmatrix.sync.aligned.m8n8.x4.shared.b16 {%0,%1,%2,%3}, [%4];" \
        : "=r"((r)[0]), "=r"((r)[1]), "=r"((r)[2]), "=r"((r)[3]) : "r"(addr))

__device__ __forceinline__ void mma16816(float* c, const uint32_t* a, const uint32_t* b) {
    asm volatile(
        "mma.sync.aligned.m16n8k16.row.col.f32.f16.f16.f32 "
        "{%0,%1,%2,%3}, {%4,%5,%6,%7}, {%8,%9}, {%0,%1,%2,%3};\n"
        : "+f"(c[0]), "+f"(c[1]), "+f"(c[2]), "+f"(c[3])
        : "r"(a[0]), "r"(a[1]), "r"(a[2]), "r"(a[3]), "r"(b[0]), "r"(b[1]));
}

#define CP_ASYNC16(dst, src, sz) \
    asm volatile("cp.async.cg.shared.global [%0], [%1], 16, %2;" \
        :: "r"(dst), "l"(src), "r"(sz))
#define CP_COMMIT() asm volatile("cp.async.commit_group;" ::: "memory")
#define CP_WAIT0()  asm volatile("cp.async.wait_group 0;" ::: "memory")

// ---------------- weight prep: ALL weight types + layers, one launch ----------------
// sources fp32 [nlayers, K, N] -> g_w fp16 [nlayers(LW_STRIDE), N, K] per group
__global__ void wprep_all_kernel(const float* __restrict__ vp, const float* __restrict__ so,
                                 const float* __restrict__ aw, const float* __restrict__ op,
                                 const float* __restrict__ f1, const float* __restrict__ f2,
                                 __half* __restrict__ dst)
{
    int idx = blockIdx.x * blockDim.x + threadIdx.x;
    if (idx >= NLAYERS_C * LW_STRIDE) return;
    int l = idx / LW_STRIDE;
    int r = idx - l * LW_STRIDE;
    const float* W;
    int K, N, r0;
    if (r < 131072) {
        if (r < 65536) { W = vp; K = 256; N = 256; r0 = r; }
        else           { W = so; K = 256; N = 256; r0 = r - 65536; }
    } else if (r < 229376) {
        if (r < 163840) { W = aw; K = 256; N = 128; r0 = r - 131072; }
        else            { W = op; K = 256; N = 256; r0 = r - 163840; }
    } else {
        if (r < 491520) { W = f1; K = 256;  N = 1024; r0 = r - 229376; }
        else            { W = f2; K = 1024; N = 256;  r0 = r - 491520; }
    }
    int n = r0 / K, k = r0 - n * K;
    dst[idx] = __float2half(__ldg(W + (size_t)l * K * N + (size_t)k * N + n));
}

// ---------------- flatten: (B,D,H,W) -> (B,L,D); emits src pair + q pair -----------
__global__ void flatten_kernel(const float* __restrict__ s0, const float* __restrict__ s1,
                               const float* __restrict__ s2, const float* __restrict__ s3,
                               const float* __restrict__ p0, const float* __restrict__ p1,
                               const float* __restrict__ p2, const float* __restrict__ p3,
                               const float* __restrict__ lvl_emb)
{
    long long idx = (long long)blockIdx.x * blockDim.x + threadIdx.x;
    const long long tot = (long long)MROWS * DMODEL;
    if (idx >= tot) return;
    int d = (int)(idx & 255);
    int m = (int)(idx >> 8);
    int b = m / L_TOT;
    int n = m - b * L_TOT;
    int lvl, hw, HW;
    const float *sp, *pp;
    if (n < 10000)      { lvl = 0; hw = n;         HW = 10000; sp = s0; pp = p0; }
    else if (n < 12500) { lvl = 1; hw = n - 10000; HW = 2500;  sp = s1; pp = p1; }
    else if (n < 13125) { lvl = 2; hw = n - 12500; HW = 625;   sp = s2; pp = p2; }
    else                { lvl = 3; hw = n - 13125; HW = 169;   sp = s3; pp = p3; }
    size_t sidx = ((size_t)b * DMODEL + d) * HW + hw;
    float sv = __ldg(sp + sidx);
    float pv = __ldg(pp + sidx) + __ldg(lvl_emb + lvl * DMODEL + d);
    g_src[idx] = sv;
    g_pos[idx] = pv;
    __half h, l;
    split_half(sv, h, l);
    g_src_hi[idx] = h; g_src_lo[idx] = l;
    split_half(sv + pv, h, l);
    g_q_hi[idx] = h; g_q_lo[idx] = l;
}

// ---------------- HMMA split-fp16 GEMM, cp.async double-buffered, CTA 128x64 --------
// C[M,N] = A[M,K] @ W[K,N] + bias.  A fp16 hi/lo [M,K]; W fp16 [N,K].
// C = Ah*W + Al*W (fp32 accum).  8 warps (4m x 2n), warp tile 32x32, BK=32.
// bias col<bias_split -> bias[col], else bias2[col-split].
// OUTMODE 0: fp32 out (opt RELU); OUTMODE 1: fp16 hi/lo out (opt RELU).
template<bool RELU, int OUTMODE>
__global__ __launch_bounds__(256)
void mma_gemm(const __half* __restrict__ Ah, const __half* __restrict__ Al,
              const __half* __restrict__ B,
              const float* __restrict__ bias, const float* __restrict__ bias2, int bias_split,
              float* __restrict__ Cf,
              __half* __restrict__ Chi, __half* __restrict__ Clo,
              int Mr, int K, int N)
{
    extern __shared__ char smem[];
    // per stage: AsH[128][40] AsL[128][40] Bs[64][40] (fp16, 80B rows)
    const int ASZ = 128 * 80;          // 10240 B
    const int BSZ = 64 * 80;           // 5120 B
    const int STG = 2 * ASZ + BSZ;     // 25600 B

    const int tid  = threadIdx.x;
    const int lane = tid & 31;
    const int warp = tid >> 5;
    const int wm   = warp & 3;          // 0..3 (32 rows each)
    const int wn   = warp >> 2;         // 0..1 (32 cols each)
    const int row0 = blockIdx.x * 128;
    const int col0 = blockIdx.y * 64;

    const uint32_t smem_base = smem_u32(smem);

    const int aRow = tid >> 2;            // 0..63 (rows aRow, aRow+64)
    const int aOff = (tid & 3) << 3;      // 0,8,16,24

    float acc[2][4][4];
    #pragma unroll
    for (int i = 0; i < 2; i++)
        #pragma unroll
        for (int j = 0; j < 4; j++)
            #pragma unroll
            for (int k = 0; k < 4; k++) acc[i][j][k] = 0.f;

    const int nch = K >> 5;

    auto load_chunk = [&](int ch, int stage) {
        const int kb = ch << 5;
        const uint32_t sb = smem_base + stage * STG;
        // A hi/lo: rows aRow and aRow+64
        #pragma unroll
        for (int r = 0; r < 2; r++) {
            const int ar = aRow + r * 64;
            const int ok = (row0 + ar < Mr) ? 16 : 0;
            const size_t g = (size_t)(row0 + ar) * K + kb + aOff;
            const uint32_t so = sb + ar * 80 + aOff * 2;
            CP_ASYNC16(so,       Ah + g, ok);
            CP_ASYNC16(so + ASZ, Al + g, ok);
        }
        // B single
        {
            const size_t g = (size_t)(col0 + aRow) * K + kb + aOff;
            const uint32_t so = sb + 2 * ASZ + aRow * 80 + aOff * 2;
            CP_ASYNC16(so, B + g, 16);
        }
    };

    load_chunk(0, 0);
    CP_COMMIT();

    for (int ch = 0; ch < nch; ch++) {
        const int buf = ch & 1;
        CP_WAIT0();
        __syncthreads();
        if (ch + 1 < nch) {
            load_chunk(ch + 1, buf ^ 1);
            CP_COMMIT();
        }
        const uint32_t sb = smem_base + buf * STG;

        #pragma unroll
        for (int ks = 0; ks < 2; ks++) {
            const int k0 = ks << 4;
            uint32_t afh[2][4], afl[2][4];
            #pragma unroll
            for (int mt = 0; mt < 2; mt++) {
                const int arow = wm * 32 + mt * 16 + (lane & 15);
                const int acol = k0 + ((lane >> 4) << 3);
                const uint32_t ad = sb + arow * 80 + acol * 2;
                LDMX4(afh[mt], ad);
                LDMX4(afl[mt], ad + ASZ);
            }
            uint32_t bf[4][2];
            #pragma unroll
            for (int np = 0; np < 2; np++) {
                const int tr = wn * 32 + np * 16 + ((lane >> 4) << 3) + (lane & 7);
                const int tc = k0 + (((lane >> 3) & 1) << 3);
                const uint32_t bd = sb + 2 * ASZ + tr * 80 + tc * 2;
                uint32_t t[4];
                LDMX4(t, bd);
                bf[np * 2][0] = t[0]; bf[np * 2][1] = t[1];
                bf[np * 2 + 1][0] = t[2]; bf[np * 2 + 1][1] = t[3];
            }
            #pragma unroll
            for (int mt = 0; mt < 2; mt++)
                #pragma unroll
                for (int nt = 0; nt < 4; nt++) {
                    mma16816(acc[mt][nt], afh[mt], bf[nt]);
                    mma16816(acc[mt][nt], afl[mt], bf[nt]);
                }
        }
        __syncthreads();
    }

    // epilogue
    const int g  = lane >> 2;
    const int tg = lane & 3;
    #pragma unroll
    for (int mt = 0; mt < 2; mt++) {
        #pragma unroll
        for (int nt = 0; nt < 4; nt++) {
            const int col = col0 + wn * 32 + nt * 8 + tg * 2;
            float b0, b1;
            if (col < bias_split) {
                b0 = __ldg(bias + col);
                b1 = __ldg(bias + col + 1);
            } else {
                b0 = __ldg(bias2 + col - bias_split);
                b1 = __ldg(bias2 + col - bias_split + 1);
            }
            #pragma unroll
            for (int half_i = 0; half_i < 2; half_i++) {
                const int row = row0 + wm * 32 + mt * 16 + g + half_i * 8;
                if (row < Mr) {
                    float v0 = acc[mt][nt][half_i * 2 + 0] + b0;
                    float v1 = acc[mt][nt][half_i * 2 + 1] + b1;
                    if (RELU) { v0 = fmaxf(v0, 0.f); v1 = fmaxf(v1, 0.f); }
                    if (OUTMODE == 0) {
                        *reinterpret_cast<float2*>(Cf + (size_t)row * N + col) = make_float2(v0, v1);
                    } else {
                        __half h0, l0, h1, l1;
                        split_half(v0, h0, l0);
                        split_half(v1, h1, l1);
                        size_t co = (size_t)row * N + col;
                        *reinterpret_cast<__half2*>(Chi + co) = __halves2half2(h0, h1);
                        *reinterpret_cast<__half2*>(Clo + co) = __halves2half2(l0, l1);
                    }
                }
            }
        }
    }
}

// ---------------- deformable attention sampling (one warp per (b,q,head)) -----------
// offaw row layout: [0,256) = offsets (h*32 each), [256,384) = aw logits (h*16 each)
__global__ void deform_kernel(const float* __restrict__ value,
                              const float* __restrict__ offaw,
                              __half* __restrict__ out_hi,
                              __half* __restrict__ out_lo)
{
    int gw = (int)((blockIdx.x * blockDim.x + threadIdx.x) >> 5);
    if (gw >= MROWS * NHEADS) return;
    int lane = threadIdx.x & 31;
    int h = gw & 7;
    int m = gw >> 3;
    int b = m / L_TOT;
    int q = m - b * L_TOT;

    float ref_x, ref_y;
    {
        int idx, Wl, Hl;
        if (q < 10000)      { idx = q;         Wl = 100; Hl = 100; }
        else if (q < 12500) { idx = q - 10000; Wl = 50;  Hl = 50;  }
        else if (q < 13125) { idx = q - 12500; Wl = 25;  Hl = 25;  }
        else                { idx = q - 13125; Wl = 13;  Hl = 13;  }
        int yy = idx / Wl, xx = idx - yy * Wl;
        ref_x = (xx + 0.5f) / (float)Wl;
        ref_y = (yy + 0.5f) / (float)Hl;
    }

    const float* awp = offaw + (size_t)m * 384 + 256 + h * 16;
    float e[16];
    float mx = -1e30f;
    #pragma unroll
    for (int i = 0; i < 16; i++) { e[i] = __ldg(awp + i); mx = fmaxf(mx, e[i]); }
    float ssum = 0.f;
    #pragma unroll
    for (int i = 0; i < 16; i++) { e[i] = __expf(e[i] - mx); ssum += e[i]; }
    float inv = 1.f / ssum;

    const float* offp  = offaw + (size_t)m * 384 + h * 32;
    const float* vbase = value + (size_t)b * L_TOT * 256 + h * 32 + lane;

    const int Ws[4]     = {100, 50, 25, 13};
    const int Hs[4]     = {100, 50, 25, 13};
    const int starts[4] = {0, 10000, 12500, 13125};

    float acc = 0.f;
    #pragma unroll
    for (int l = 0; l < 4; l++) {
        const int   Wl = Ws[l], Hl = Hs[l], st = starts[l];
        const float fW = (float)Wl, fH = (float)Hl;
        #pragma unroll
        for (int p = 0; p < 4; p++) {
            float ox = __ldg(offp + l * 8 + p * 2);
            float oy = __ldg(offp + l * 8 + p * 2 + 1);
            float px = ref_x * fW + ox - 0.5f;
            float py = ref_y * fH + oy - 0.5f;
            float x0f = floorf(px), y0f = floorf(py);
            float wx1 = px - x0f, wy1 = py - y0f;
            int x0 = (int)x0f, y0 = (int)y0f;
            float wgt = e[l * 4 + p] * inv;
            #pragma unroll
            for (int t = 0; t < 4; t++) {
                int xi = x0 + (t & 1);
                int yi = y0 + (t >> 1);
                float w = ((t & 1) ? wx1 : 1.f - wx1) * ((t >> 1) ? wy1 : 1.f - wy1);
                if (xi >= 0 && xi < Wl && yi >= 0 && yi < Hl && w != 0.f) {
                    acc = fmaf(wgt * w,
                               __ldg(vbase + (size_t)(st + yi * Wl + xi) * 256),
                               acc);
                }
            }
        }
    }
    size_t oidx = (size_t)m * 256 + h * 32 + lane;
    __half hh, ll;
    split_half(acc, hh, ll);
    out_hi[oidx] = hh;
    out_lo[oidx] = ll;
}

// ---------------- fused residual add + LayerNorm (one warp per row) -----------------
// emits fp32 out + fp16 pair; if pos != nullptr also emits q pair = split(out + pos)
__global__ void add_ln_kernel(const float* __restrict__ X, const float* __restrict__ R,
                              const float* __restrict__ w, const float* __restrict__ b,
                              const float* __restrict__ pos,
                              float* __restrict__ out,
                              __half* __restrict__ out_hi,
                              __half* __restrict__ out_lo,
                              __half* __restrict__ q_hi,
                              __half* __restrict__ q_lo)
{
    int row = (int)((blockIdx.x * blockDim.x + threadIdx.x) >> 5);
    if (row >= MROWS) return;
    int lane = threadIdx.x & 31;
    const float* x = X + (size_t)row * DMODEL;
    const float* r = R + (size_t)row * DMODEL;
    float v[8];
    float s = 0.f;
    #pragma unroll
    for (int j = 0; j < 8; j++) {
        int c = lane + j * 32;
        v[j] = x[c] + r[c];
        s += v[j];
    }
    #pragma unroll
    for (int o = 16; o > 0; o >>= 1) s += __shfl_xor_sync(0xFFFFFFFFu, s, o);
    float mean = s * (1.f / 256.f);
    float qv = 0.f;
    #pragma unroll
    for (int j = 0; j < 8; j++) { float d = v[j] - mean; qv += d * d; }
    #pragma unroll
    for (int o = 16; o > 0; o >>= 1) qv += __shfl_xor_sync(0xFFFFFFFFu, qv, o);
    float invs = rsqrtf(qv * (1.f / 256.f) + 1e-5f);
    #pragma unroll
    for (int j = 0; j < 8; j++) {
        int c = lane + j * 32;
        float o = (v[j] - mean) * invs * __ldg(w + c) + __ldg(b + c);
        size_t oi = (size_t)row * DMODEL + c;
        out[oi] = o;
        __half hh, ll;
        split_half(o, hh, ll);
        out_hi[oi] = hh;
        out_lo[oi] = ll;
        if (pos != nullptr) {
            split_half(o + __ldg(pos + oi), hh, ll);
            q_hi[oi] = hh;
            q_lo[oi] = ll;
        }
    }
}

// ---------------- output write: src then level_start_index (as floats) -------------
__global__ void write_out_kernel(float* __restrict__ out, int n)
{
    long long i = (long long)blockIdx.x * blockDim.x + threadIdx.x;
    if (i >= n) return;
    const long long tot = (long long)MROWS * DMODEL;
    if (i < tot) {
        out[i] = g_src[i];
    } else {
        int k = (int)(i - tot);
        float st;
        switch (k) {
            case 0: st = 0.f;      break;
            case 1: st = 10000.f;  break;
            case 2: st = 12500.f;  break;
            case 3: st = 13125.f;  break;
            default: st = 0.f;     break;
        }
        out[i] = st;
    }
}

// ---------------- host launch ----------------
extern "C" void kernel_launch(void* const* d_in, const int* in_sizes, int n_in,
                              void* d_out, int out_size)
{
    // setup_inputs() dict order is INTERLEAVED: src0, pos0, src1, pos1, ...
    const float* s0 = (const float*)d_in[0];
    const float* p0 = (const float*)d_in[1];
    const float* s1 = (const float*)d_in[2];
    const float* p1 = (const float*)d_in[3];
    const float* s2 = (const float*)d_in[4];
    const float* p2 = (const float*)d_in[5];
    const float* s3 = (const float*)d_in[6];
    const float* p3 = (const float*)d_in[7];
    const float* lvl_emb = (const float*)d_in[8];
    const float* so_w = (const float*)d_in[9];
    const float* so_b = (const float*)d_in[10];
    const float* aw_w = (const float*)d_in[11];
    const float* aw_b = (const float*)d_in[12];
    const float* vp_w = (const float*)d_in[13];
    const float* vp_b = (const float*)d_in[14];
    const float* op_w = (const float*)d_in[15];
    const float* op_b = (const float*)d_in[16];
    const float* n1_w = (const float*)d_in[17];
    const float* n1_b = (const float*)d_in[18];
    const float* f1_w = (const float*)d_in[19];
    const float* f1_b = (const float*)d_in[20];
    const float* f2_w = (const float*)d_in[21];
    const float* f2_b = (const float*)d_in[22];
    const float* n2_w = (const float*)d_in[23];
    const float* n2_b = (const float*)d_in[24];

    float *pg_src, *pg_pos, *pg_val, *pg_offaw, *pg_tmp;
    __half *pg_src_hi, *pg_src_lo, *pg_q_hi, *pg_q_lo;
    __half *pg_attn_hi, *pg_attn_lo, *pg_h_hi, *pg_h_lo, *pg_w;
    cudaGetSymbolAddress((void**)&pg_src,   g_src);
    cudaGetSymbolAddress((void**)&pg_pos,   g_pos);
    cudaGetSymbolAddress((void**)&pg_val,   g_val);
    cudaGetSymbolAddress((void**)&pg_offaw, g_offaw);
    cudaGetSymbolAddress((void**)&pg_tmp,   g_tmp);
    cudaGetSymbolAddress((void**)&pg_src_hi, g_src_hi);
    cudaGetSymbolAddress((void**)&pg_src_lo, g_src_lo);
    cudaGetSymbolAddress((void**)&pg_q_hi,   g_q_hi);
    cudaGetSymbolAddress((void**)&pg_q_lo,   g_q_lo);
    cudaGetSymbolAddress((void**)&pg_attn_hi, g_attn_hi);
    cudaGetSymbolAddress((void**)&pg_attn_lo, g_attn_lo);
    cudaGetSymbolAddress((void**)&pg_h_hi,   g_h_hi);
    cudaGetSymbolAddress((void**)&pg_h_lo,   g_h_lo);
    cudaGetSymbolAddress((void**)&pg_w,      g_w);

    // dynamic smem for GEMM: 2 stages x 25600 B
    const int GEMM_SMEM = 51200;
    cudaFuncSetAttribute(mma_gemm<false, 0>, cudaFuncAttributeMaxDynamicSharedMemorySize, GEMM_SMEM);
    cudaFuncSetAttribute(mma_gemm<true, 1>,  cudaFuncAttributeMaxDynamicSharedMemorySize, GEMM_SMEM);

    const long long totElem = (long long)MROWS * DMODEL;
    const int ew_grid = (int)((totElem + 255) / 256);

    // launch 1: all weight prep
    wprep_all_kernel<<<(NLAYERS_C * LW_STRIDE + 255) / 256, 256>>>(
        vp_w, so_w, aw_w, op_w, f1_w, f2_w, pg_w);
    // launch 2: flatten
    flatten_kernel<<<ew_grid, 256>>>(s0, s1, s2, s3, p0, p1, p2, p3, lvl_emb);

    const int mblk = (MROWS + 127) / 128;   // 416
    const dim3 blk(256);
    const int ln_grid = (MROWS * 32 + 255) / 256;
    const int deform_grid = (MROWS * NHEADS * 32 + 255) / 256;

    for (int i = 0; i < NLAYERS_C; i++) {
        size_t wb = (size_t)i * LW_STRIDE;
        const __half* vp_h = pg_w + wb + OFF_VP;
        const __half* sa_h = pg_w + wb + OFF_SOAW;
        const __half* op_h = pg_w + wb + OFF_OP;
        const __half* f1_h = pg_w + wb + OFF_F1;
        const __half* f2_h = pg_w + wb + OFF_F2;

        // value = src @ vp_w + vp_b  (fp32 out)                 [layer0: launch 3]
        mma_gemm<false, 0><<<dim3(mblk, 4), blk, GEMM_SMEM>>>(
            pg_src_hi, pg_src_lo, vp_h, vp_b + (size_t)i * 256, vp_b + (size_t)i * 256, 256,
            pg_val, nullptr, nullptr, MROWS, 256, 256);
        // [offsets | aw] = q @ [so_w | aw_w] (N=384 fused)      [layer0: launch 4]
        mma_gemm<false, 0><<<dim3(mblk, 6), blk, GEMM_SMEM>>>(
            pg_q_hi, pg_q_lo, sa_h, so_b + (size_t)i * 256, aw_b + (size_t)i * 128, 256,
            pg_offaw, nullptr, nullptr, MROWS, 256, 384);
        // deformable sampling -> attn pair                      [layer0: launch 5]
        deform_kernel<<<deform_grid, 256>>>(pg_val, pg_offaw, pg_attn_hi, pg_attn_lo);
        // output proj                                           [layer0: launch 6 -> ncu]
        mma_gemm<false, 0><<<dim3(mblk, 4), blk, GEMM_SMEM>>>(
            pg_attn_hi, pg_attn_lo, op_h, op_b + (size_t)i * 256, op_b + (size_t)i * 256, 256,
            pg_tmp, nullptr, nullptr, MROWS, 256, 256);
        // src = LN(src + attn_proj)
        add_ln_kernel<<<ln_grid, 256>>>(pg_src, pg_tmp,
                                        n1_w + (size_t)i * DMODEL, n1_b + (size_t)i * DMODEL,
                                        nullptr, pg_src, pg_src_hi, pg_src_lo, nullptr, nullptr);
        // h = relu(src @ f1_w + f1_b)  (fp16 pair out)
        mma_gemm<true, 1><<<dim3(mblk, 16), blk, GEMM_SMEM>>>(
            pg_src_hi, pg_src_lo, f1_h, f1_b + (size_t)i * DFFN, f1_b + (size_t)i * DFFN, DFFN,
            nullptr, pg_h_hi, pg_h_lo, MROWS, 256, DFFN);
        // tmp = h @ f2_w + f2_b
        mma_gemm<false, 0><<<dim3(mblk, 4), blk, GEMM_SMEM>>>(
            pg_h_hi, pg_h_lo, f2_h, f2_b + (size_t)i * 256, f2_b + (size_t)i * 256, 256,
            pg_tmp, nullptr, nullptr, MROWS, 1024, 256);
        // src = LN(src + ffn), also emit q pair for next layer
        add_ln_kernel<<<ln_grid, 256>>>(pg_src, pg_tmp,
                                        n2_w + (size_t)i * DMODEL, n2_b + (size_t)i * DMODEL,
                                        pg_pos, pg_src, pg_src_hi, pg_src_lo, pg_q_hi, pg_q_lo);
    }

    write_out_kernel<<<(out_size + 255) / 256, 256>>>((float*)d_out, out_size);
}

// round 9
// speedup vs baseline: 1.4474x; 1.2543x over previous
#include <cuda_runtime.h>
#include <cuda_fp16.h>
#include <cstdint>
#include <math.h>

// ---------------- problem constants ----------------
#define L_TOT   13294          // 10000 + 2500 + 625 + 169
#define BATCH   4
#define MROWS   (BATCH * L_TOT)   // 53176
#define DMODEL  256
#define DFFN    1024
#define NLAYERS_C 6
#define NHEADS  8

// weight layout offsets (elements) within one layer block
#define OFF_VP    0
#define OFF_SOAW  65536          // combined so(256) + aw(128) rows => [384,256]
#define OFF_OP    163840
#define OFF_F1    229376
#define OFF_F2    491520
#define LW_STRIDE 753664

// ---------------- device scratch (static, allowed) ----------------
__device__ __align__(16) float g_src  [MROWS * DMODEL];
__device__ __align__(16) float g_pos  [MROWS * DMODEL];
__device__ __align__(16) float g_val  [MROWS * DMODEL];
__device__ __align__(16) float g_offaw[MROWS * 384];
__device__ __align__(16) float g_tmp  [MROWS * DMODEL];

__device__ __align__(16) __half g_src_h [MROWS * DMODEL];
__device__ __align__(16) __half g_q_h   [MROWS * DMODEL];
__device__ __align__(16) __half g_attn_h[MROWS * DMODEL];
__device__ __align__(16) __half g_h_h   [(size_t)MROWS * DFFN];
__device__ __align__(16) __half g_w     [NLAYERS_C * LW_STRIDE];

// ---------------- helpers ----------------
__device__ __forceinline__ uint32_t smem_u32(const void* p) {
    uint32_t a;
    asm("{ .reg .u64 t; cvta.to.shared.u64 t, %1; cvt.u32.u64 %0, t; }" : "=r"(a) : "l"(p));
    return a;
}

#define LDMX4(r, addr) \
    asm volatile("ldmatrix.sync.aligned.m8n8.x4.shared.b16 {%0,%1,%2,%3}, [%4];" \
        : "=r"((r)[0]), "=r"((r)[1]), "=r"((r)[2]), "=r"((r)[3]) : "r"(addr))

__device__ __forceinline__ void mma16816(float* c, const uint32_t* a, const uint32_t* b) {
    asm volatile(
        "mma.sync.aligned.m16n8k16.row.col.f32.f16.f16.f32 "
        "{%0,%1,%2,%3}, {%4,%5,%6,%7}, {%8,%9}, {%0,%1,%2,%3};\n"
        : "+f"(c[0]), "+f"(c[1]), "+f"(c[2]), "+f"(c[3])
        : "r"(a[0]), "r"(a[1]), "r"(a[2]), "r"(a[3]), "r"(b[0]), "r"(b[1]));
}

#define CP_ASYNC16(dst, src, sz) \
    asm volatile("cp.async.cg.shared.global [%0], [%1], 16, %2;" \
        :: "r"(dst), "l"(src), "r"(sz))
#define CP_COMMIT() asm volatile("cp.async.commit_group;" ::: "memory")
#define CP_WAIT0()  asm volatile("cp.async.wait_group 0;" ::: "memory")

// ---------------- weight prep: ALL weight types + layers, one launch ----------------
// sources fp32 [nlayers, K, N] -> g_w fp16 [nlayers(LW_STRIDE), N, K] per group
__global__ void wprep_all_kernel(const float* __restrict__ vp, const float* __restrict__ so,
                                 const float* __restrict__ aw, const float* __restrict__ op,
                                 const float* __restrict__ f1, const float* __restrict__ f2,
                                 __half* __restrict__ dst)
{
    int idx = blockIdx.x * blockDim.x + threadIdx.x;
    if (idx >= NLAYERS_C * LW_STRIDE) return;
    int l = idx / LW_STRIDE;
    int r = idx - l * LW_STRIDE;
    const float* W;
    int K, N, r0;
    if (r < 131072) {
        if (r < 65536) { W = vp; K = 256; N = 256; r0 = r; }
        else           { W = so; K = 256; N = 256; r0 = r - 65536; }
    } else if (r < 229376) {
        if (r < 163840) { W = aw; K = 256; N = 128; r0 = r - 131072; }
        else            { W = op; K = 256; N = 256; r0 = r - 163840; }
    } else {
        if (r < 491520) { W = f1; K = 256;  N = 1024; r0 = r - 229376; }
        else            { W = f2; K = 1024; N = 256;  r0 = r - 491520; }
    }
    int n = r0 / K, k = r0 - n * K;
    dst[idx] = __float2half(__ldg(W + (size_t)l * K * N + (size_t)k * N + n));
}

// ---------------- flatten: (B,D,H,W) -> (B,L,D); emits src fp16 + q fp16 -----------
__global__ void flatten_kernel(const float* __restrict__ s0, const float* __restrict__ s1,
                               const float* __restrict__ s2, const float* __restrict__ s3,
                               const float* __restrict__ p0, const float* __restrict__ p1,
                               const float* __restrict__ p2, const float* __restrict__ p3,
                               const float* __restrict__ lvl_emb)
{
    long long idx = (long long)blockIdx.x * blockDim.x + threadIdx.x;
    const long long tot = (long long)MROWS * DMODEL;
    if (idx >= tot) return;
    int d = (int)(idx & 255);
    int m = (int)(idx >> 8);
    int b = m / L_TOT;
    int n = m - b * L_TOT;
    int lvl, hw, HW;
    const float *sp, *pp;
    if (n < 10000)      { lvl = 0; hw = n;         HW = 10000; sp = s0; pp = p0; }
    else if (n < 12500) { lvl = 1; hw = n - 10000; HW = 2500;  sp = s1; pp = p1; }
    else if (n < 13125) { lvl = 2; hw = n - 12500; HW = 625;   sp = s2; pp = p2; }
    else                { lvl = 3; hw = n - 13125; HW = 169;   sp = s3; pp = p3; }
    size_t sidx = ((size_t)b * DMODEL + d) * HW + hw;
    float sv = __ldg(sp + sidx);
    float pv = __ldg(pp + sidx) + __ldg(lvl_emb + lvl * DMODEL + d);
    g_src[idx] = sv;
    g_pos[idx] = pv;
    g_src_h[idx] = __float2half(sv);
    g_q_h[idx]   = __float2half(sv + pv);
}

// ---------------- HMMA fp16 GEMM, cp.async double-buffered, CTA 128x64 --------------
// C[M,N] = A[M,K] @ W[K,N] + bias.  A fp16 [M,K]; W fp16 [N,K].  fp32 accumulate.
// 8 warps (4m x 2n), warp tile 32x32, BK=32.
// bias col<bias_split -> bias[col], else bias2[col-split].
// OUTMODE 0: fp32 out (opt RELU); OUTMODE 1: fp16 out (opt RELU).
template<bool RELU, int OUTMODE>
__global__ __launch_bounds__(256)
void mma_gemm(const __half* __restrict__ A,
              const __half* __restrict__ B,
              const float* __restrict__ bias, const float* __restrict__ bias2, int bias_split,
              float* __restrict__ Cf,
              __half* __restrict__ Ch,
              int Mr, int K, int N)
{
    extern __shared__ char smem[];
    // per stage: As[128][40] Bs[64][40] (fp16, 80B rows)
    const int ASZ = 128 * 80;          // 10240 B
    const int BSZ = 64 * 80;           // 5120 B
    const int STG = ASZ + BSZ;         // 15360 B

    const int tid  = threadIdx.x;
    const int lane = tid & 31;
    const int warp = tid >> 5;
    const int wm   = warp & 3;          // 0..3 (32 rows each)
    const int wn   = warp >> 2;         // 0..1 (32 cols each)
    const int row0 = blockIdx.x * 128;
    const int col0 = blockIdx.y * 64;

    const uint32_t smem_base = smem_u32(smem);

    const int aRow = tid >> 2;            // 0..63 (rows aRow, aRow+64)
    const int aOff = (tid & 3) << 3;      // 0,8,16,24

    float acc[2][4][4];
    #pragma unroll
    for (int i = 0; i < 2; i++)
        #pragma unroll
        for (int j = 0; j < 4; j++)
            #pragma unroll
            for (int k = 0; k < 4; k++) acc[i][j][k] = 0.f;

    const int nch = K >> 5;

    auto load_chunk = [&](int ch, int stage) {
        const int kb = ch << 5;
        const uint32_t sb = smem_base + stage * STG;
        // A: rows aRow and aRow+64
        #pragma unroll
        for (int r = 0; r < 2; r++) {
            const int ar = aRow + r * 64;
            const int ok = (row0 + ar < Mr) ? 16 : 0;
            const size_t g = (size_t)(row0 + ar) * K + kb + aOff;
            CP_ASYNC16(sb + ar * 80 + aOff * 2, A + g, ok);
        }
        // B
        {
            const size_t g = (size_t)(col0 + aRow) * K + kb + aOff;
            CP_ASYNC16(sb + ASZ + aRow * 80 + aOff * 2, B + g, 16);
        }
    };

    load_chunk(0, 0);
    CP_COMMIT();

    for (int ch = 0; ch < nch; ch++) {
        const int buf = ch & 1;
        CP_WAIT0();
        __syncthreads();
        if (ch + 1 < nch) {
            load_chunk(ch + 1, buf ^ 1);
            CP_COMMIT();
        }
        const uint32_t sb = smem_base + buf * STG;

        #pragma unroll
        for (int ks = 0; ks < 2; ks++) {
            const int k0 = ks << 4;
            uint32_t af[2][4];
            #pragma unroll
            for (int mt = 0; mt < 2; mt++) {
                const int arow = wm * 32 + mt * 16 + (lane & 15);
                const int acol = k0 + ((lane >> 4) << 3);
                LDMX4(af[mt], sb + arow * 80 + acol * 2);
            }
            uint32_t bf[4][2];
            #pragma unroll
            for (int np = 0; np < 2; np++) {
                const int tr = wn * 32 + np * 16 + ((lane >> 4) << 3) + (lane & 7);
                const int tc = k0 + (((lane >> 3) & 1) << 3);
                uint32_t t[4];
                LDMX4(t, sb + ASZ + tr * 80 + tc * 2);
                bf[np * 2][0] = t[0]; bf[np * 2][1] = t[1];
                bf[np * 2 + 1][0] = t[2]; bf[np * 2 + 1][1] = t[3];
            }
            #pragma unroll
            for (int mt = 0; mt < 2; mt++)
                #pragma unroll
                for (int nt = 0; nt < 4; nt++)
                    mma16816(acc[mt][nt], af[mt], bf[nt]);
        }
        __syncthreads();
    }

    // epilogue
    const int g  = lane >> 2;
    const int tg = lane & 3;
    #pragma unroll
    for (int mt = 0; mt < 2; mt++) {
        #pragma unroll
        for (int nt = 0; nt < 4; nt++) {
            const int col = col0 + wn * 32 + nt * 8 + tg * 2;
            float b0, b1;
            if (col < bias_split) {
                b0 = __ldg(bias + col);
                b1 = __ldg(bias + col + 1);
            } else {
                b0 = __ldg(bias2 + col - bias_split);
                b1 = __ldg(bias2 + col - bias_split + 1);
            }
            #pragma unroll
            for (int half_i = 0; half_i < 2; half_i++) {
                const int row = row0 + wm * 32 + mt * 16 + g + half_i * 8;
                if (row < Mr) {
                    float v0 = acc[mt][nt][half_i * 2 + 0] + b0;
                    float v1 = acc[mt][nt][half_i * 2 + 1] + b1;
                    if (RELU) { v0 = fmaxf(v0, 0.f); v1 = fmaxf(v1, 0.f); }
                    if (OUTMODE == 0) {
                        *reinterpret_cast<float2*>(Cf + (size_t)row * N + col) = make_float2(v0, v1);
                    } else {
                        *reinterpret_cast<__half2*>(Ch + (size_t)row * N + col) =
                            __halves2half2(__float2half(v0), __float2half(v1));
                    }
                }
            }
        }
    }
}

// ---------------- deformable attention sampling (one warp per (b,q,head)) -----------
// offaw row layout: [0,256) = offsets (h*32 each), [256,384) = aw logits (h*16 each)
__global__ void deform_kernel(const float* __restrict__ value,
                              const float* __restrict__ offaw,
                              __half* __restrict__ out_h)
{
    int gw = (int)((blockIdx.x * blockDim.x + threadIdx.x) >> 5);
    if (gw >= MROWS * NHEADS) return;
    int lane = threadIdx.x & 31;
    int h = gw & 7;
    int m = gw >> 3;
    int b = m / L_TOT;
    int q = m - b * L_TOT;

    float ref_x, ref_y;
    {
        int idx, Wl, Hl;
        if (q < 10000)      { idx = q;         Wl = 100; Hl = 100; }
        else if (q < 12500) { idx = q - 10000; Wl = 50;  Hl = 50;  }
        else if (q < 13125) { idx = q - 12500; Wl = 25;  Hl = 25;  }
        else                { idx = q - 13125; Wl = 13;  Hl = 13;  }
        int yy = idx / Wl, xx = idx - yy * Wl;
        ref_x = (xx + 0.5f) / (float)Wl;
        ref_y = (yy + 0.5f) / (float)Hl;
    }

    const float* awp = offaw + (size_t)m * 384 + 256 + h * 16;
    float e[16];
    float mx = -1e30f;
    #pragma unroll
    for (int i = 0; i < 16; i++) { e[i] = __ldg(awp + i); mx = fmaxf(mx, e[i]); }
    float ssum = 0.f;
    #pragma unroll
    for (int i = 0; i < 16; i++) { e[i] = __expf(e[i] - mx); ssum += e[i]; }
    float inv = 1.f / ssum;

    const float* offp  = offaw + (size_t)m * 384 + h * 32;
    const float* vbase = value + (size_t)b * L_TOT * 256 + h * 32 + lane;

    const int Ws[4]     = {100, 50, 25, 13};
    const int Hs[4]     = {100, 50, 25, 13};
    const int starts[4] = {0, 10000, 12500, 13125};

    float acc = 0.f;
    #pragma unroll
    for (int l = 0; l < 4; l++) {
        const int   Wl = Ws[l], Hl = Hs[l], st = starts[l];
        const float fW = (float)Wl, fH = (float)Hl;
        #pragma unroll
        for (int p = 0; p < 4; p++) {
            float ox = __ldg(offp + l * 8 + p * 2);
            float oy = __ldg(offp + l * 8 + p * 2 + 1);
            float px = ref_x * fW + ox - 0.5f;
            float py = ref_y * fH + oy - 0.5f;
            float x0f = floorf(px), y0f = floorf(py);
            float wx1 = px - x0f, wy1 = py - y0f;
            int x0 = (int)x0f, y0 = (int)y0f;
            float wgt = e[l * 4 + p] * inv;
            #pragma unroll
            for (int t = 0; t < 4; t++) {
                int xi = x0 + (t & 1);
                int yi = y0 + (t >> 1);
                float w = ((t & 1) ? wx1 : 1.f - wx1) * ((t >> 1) ? wy1 : 1.f - wy1);
                if (xi >= 0 && xi < Wl && yi >= 0 && yi < Hl && w != 0.f) {
                    acc = fmaf(wgt * w,
                               __ldg(vbase + (size_t)(st + yi * Wl + xi) * 256),
                               acc);
                }
            }
        }
    }
    out_h[(size_t)m * 256 + h * 32 + lane] = __float2half(acc);
}

// ---------------- fused residual add + LayerNorm (one warp per row) -----------------
// emits fp32 out + fp16; if pos != nullptr also emits q fp16 = fp16(out + pos)
__global__ void add_ln_kernel(const float* __restrict__ X, const float* __restrict__ R,
                              const float* __restrict__ w, const float* __restrict__ b,
                              const float* __restrict__ pos,
                              float* __restrict__ out,
                              __half* __restrict__ out_h,
                              __half* __restrict__ q_h)
{
    int row = (int)((blockIdx.x * blockDim.x + threadIdx.x) >> 5);
    if (row >= MROWS) return;
    int lane = threadIdx.x & 31;
    const float* x = X + (size_t)row * DMODEL;
    const float* r = R + (size_t)row * DMODEL;
    float v[8];
    float s = 0.f;
    #pragma unroll
    for (int j = 0; j < 8; j++) {
        int c = lane + j * 32;
        v[j] = x[c] + r[c];
        s += v[j];
    }
    #pragma unroll
    for (int o = 16; o > 0; o >>= 1) s += __shfl_xor_sync(0xFFFFFFFFu, s, o);
    float mean = s * (1.f / 256.f);
    float qv = 0.f;
    #pragma unroll
    for (int j = 0; j < 8; j++) { float d = v[j] - mean; qv += d * d; }
    #pragma unroll
    for (int o = 16; o > 0; o >>= 1) qv += __shfl_xor_sync(0xFFFFFFFFu, qv, o);
    float invs = rsqrtf(qv * (1.f / 256.f) + 1e-5f);
    #pragma unroll
    for (int j = 0; j < 8; j++) {
        int c = lane + j * 32;
        float o = (v[j] - mean) * invs * __ldg(w + c) + __ldg(b + c);
        size_t oi = (size_t)row * DMODEL + c;
        out[oi] = o;
        out_h[oi] = __float2half(o);
        if (pos != nullptr) q_h[oi] = __float2half(o + __ldg(pos + oi));
    }
}

// ---------------- output write: src then level_start_index (as floats) -------------
__global__ void write_out_kernel(float* __restrict__ out, int n)
{
    long long i = (long long)blockIdx.x * blockDim.x + threadIdx.x;
    if (i >= n) return;
    const long long tot = (long long)MROWS * DMODEL;
    if (i < tot) {
        out[i] = g_src[i];
    } else {
        int k = (int)(i - tot);
        float st;
        switch (k) {
            case 0: st = 0.f;      break;
            case 1: st = 10000.f;  break;
            case 2: st = 12500.f;  break;
            case 3: st = 13125.f;  break;
            default: st = 0.f;     break;
        }
        out[i] = st;
    }
}

// ---------------- host launch ----------------
extern "C" void kernel_launch(void* const* d_in, const int* in_sizes, int n_in,
                              void* d_out, int out_size)
{
    // setup_inputs() dict order is INTERLEAVED: src0, pos0, src1, pos1, ...
    const float* s0 = (const float*)d_in[0];
    const float* p0 = (const float*)d_in[1];
    const float* s1 = (const float*)d_in[2];
    const float* p1 = (const float*)d_in[3];
    const float* s2 = (const float*)d_in[4];
    const float* p2 = (const float*)d_in[5];
    const float* s3 = (const float*)d_in[6];
    const float* p3 = (const float*)d_in[7];
    const float* lvl_emb = (const float*)d_in[8];
    const float* so_w = (const float*)d_in[9];
    const float* so_b = (const float*)d_in[10];
    const float* aw_w = (const float*)d_in[11];
    const float* aw_b = (const float*)d_in[12];
    const float* vp_w = (const float*)d_in[13];
    const float* vp_b = (const float*)d_in[14];
    const float* op_w = (const float*)d_in[15];
    const float* op_b = (const float*)d_in[16];
    const float* n1_w = (const float*)d_in[17];
    const float* n1_b = (const float*)d_in[18];
    const float* f1_w = (const float*)d_in[19];
    const float* f1_b = (const float*)d_in[20];
    const float* f2_w = (const float*)d_in[21];
    const float* f2_b = (const float*)d_in[22];
    const float* n2_w = (const float*)d_in[23];
    const float* n2_b = (const float*)d_in[24];

    float *pg_src, *pg_pos, *pg_val, *pg_offaw, *pg_tmp;
    __half *pg_src_h, *pg_q_h, *pg_attn_h, *pg_h_h, *pg_w;
    cudaGetSymbolAddress((void**)&pg_src,   g_src);
    cudaGetSymbolAddress((void**)&pg_pos,   g_pos);
    cudaGetSymbolAddress((void**)&pg_val,   g_val);
    cudaGetSymbolAddress((void**)&pg_offaw, g_offaw);
    cudaGetSymbolAddress((void**)&pg_tmp,   g_tmp);
    cudaGetSymbolAddress((void**)&pg_src_h, g_src_h);
    cudaGetSymbolAddress((void**)&pg_q_h,   g_q_h);
    cudaGetSymbolAddress((void**)&pg_attn_h, g_attn_h);
    cudaGetSymbolAddress((void**)&pg_h_h,   g_h_h);
    cudaGetSymbolAddress((void**)&pg_w,     g_w);

    // dynamic smem for GEMM: 2 stages x 15360 B
    const int GEMM_SMEM = 30720;
    cudaFuncSetAttribute(mma_gemm<false, 0>, cudaFuncAttributeMaxDynamicSharedMemorySize, GEMM_SMEM);
    cudaFuncSetAttribute(mma_gemm<true, 1>,  cudaFuncAttributeMaxDynamicSharedMemorySize, GEMM_SMEM);

    const long long totElem = (long long)MROWS * DMODEL;
    const int ew_grid = (int)((totElem + 255) / 256);

    // launch 1: all weight prep
    wprep_all_kernel<<<(NLAYERS_C * LW_STRIDE + 255) / 256, 256>>>(
        vp_w, so_w, aw_w, op_w, f1_w, f2_w, pg_w);
    // launch 2: flatten
    flatten_kernel<<<ew_grid, 256>>>(s0, s1, s2, s3, p0, p1, p2, p3, lvl_emb);

    const int mblk = (MROWS + 127) / 128;   // 416
    const dim3 blk(256);
    const int ln_grid = (MROWS * 32 + 255) / 256;
    const int deform_grid = (MROWS * NHEADS * 32 + 255) / 256;

    for (int i = 0; i < NLAYERS_C; i++) {
        size_t wb = (size_t)i * LW_STRIDE;
        const __half* vp_h = pg_w + wb + OFF_VP;
        const __half* sa_h = pg_w + wb + OFF_SOAW;
        const __half* op_h = pg_w + wb + OFF_OP;
        const __half* f1_h = pg_w + wb + OFF_F1;
        const __half* f2_h = pg_w + wb + OFF_F2;

        // value = src @ vp_w + vp_b  (fp32 out)
        mma_gemm<false, 0><<<dim3(mblk, 4), blk, GEMM_SMEM>>>(
            pg_src_h, vp_h, vp_b + (size_t)i * 256, vp_b + (size_t)i * 256, 256,
            pg_val, nullptr, MROWS, 256, 256);
        // [offsets | aw] = q @ [so_w | aw_w] (N=384 fused)
        mma_gemm<false, 0><<<dim3(mblk, 6), blk, GEMM_SMEM>>>(
            pg_q_h, sa_h, so_b + (size_t)i * 256, aw_b + (size_t)i * 128, 256,
            pg_offaw, nullptr, MROWS, 256, 384);
        // deformable sampling -> attn fp16
        deform_kernel<<<deform_grid, 256>>>(pg_val, pg_offaw, pg_attn_h);
        // output proj                                            [layer0: launch 6 -> ncu]
        mma_gemm<false, 0><<<dim3(mblk, 4), blk, GEMM_SMEM>>>(
            pg_attn_h, op_h, op_b + (size_t)i * 256, op_b + (size_t)i * 256, 256,
            pg_tmp, nullptr, MROWS, 256, 256);
        // src = LN(src + attn_proj)
        add_ln_kernel<<<ln_grid, 256>>>(pg_src, pg_tmp,
                                        n1_w + (size_t)i * DMODEL, n1_b + (size_t)i * DMODEL,
                                        nullptr, pg_src, pg_src_h, nullptr);
        // h = relu(src @ f1_w + f1_b)  (fp16 out)
        mma_gemm<true, 1><<<dim3(mblk, 16), blk, GEMM_SMEM>>>(
            pg_src_h, f1_h, f1_b + (size_t)i * DFFN, f1_b + (size_t)i * DFFN, DFFN,
            nullptr, pg_h_h, MROWS, 256, DFFN);
        // tmp = h @ f2_w + f2_b
        mma_gemm<false, 0><<<dim3(mblk, 4), blk, GEMM_SMEM>>>(
            pg_h_h, f2_h, f2_b + (size_t)i * 256, f2_b + (size_t)i * 256, 256,
            pg_tmp, nullptr, MROWS, 1024, 256);
        // src = LN(src + ffn), also emit q fp16 for next layer
        add_ln_kernel<<<ln_grid, 256>>>(pg_src, pg_tmp,
                                        n2_w + (size_t)i * DMODEL, n2_b + (size_t)i * DMODEL,
                                        pg_pos, pg_src, pg_src_h, pg_q_h);
    }

    write_out_kernel<<<(out_size + 255) / 256, 256>>>((float*)d_out, out_size);
}

// round 10
// speedup vs baseline: 1.4617x; 1.0099x over previous
#include <cuda_runtime.h>
#include <cuda_fp16.h>
#include <cstdint>
#include <math.h>

// ---------------- problem constants ----------------
#define L_TOT   13294          // 10000 + 2500 + 625 + 169
#define BATCH   4
#define MROWS   (BATCH * L_TOT)   // 53176
#define DMODEL  256
#define DFFN    1024
#define NLAYERS_C 6
#define NHEADS  8

// weight layout offsets (elements) within one layer block
#define OFF_VP    0
#define OFF_SOAW  65536          // combined so(256) + aw(128) rows => [384,256]
#define OFF_OP    163840
#define OFF_F1    229376
#define OFF_F2    491520
#define LW_STRIDE 753664

// ---------------- device scratch (static, allowed) ----------------
__device__ __align__(16) float g_src  [MROWS * DMODEL];
__device__ __align__(16) float g_pos  [MROWS * DMODEL];
__device__ __align__(16) float g_offaw[MROWS * 384];
__device__ __align__(16) float g_tmp  [MROWS * DMODEL];

__device__ __align__(16) __half g_val_h [MROWS * DMODEL];
__device__ __align__(16) __half g_src_h [MROWS * DMODEL];
__device__ __align__(16) __half g_q_h   [MROWS * DMODEL];
__device__ __align__(16) __half g_attn_h[MROWS * DMODEL];
__device__ __align__(16) __half g_h_h   [(size_t)MROWS * DFFN];
__device__ __align__(16) __half g_w     [NLAYERS_C * LW_STRIDE];

// ---------------- helpers ----------------
__device__ __forceinline__ uint32_t smem_u32(const void* p) {
    uint32_t a;
    asm("{ .reg .u64 t; cvta.to.shared.u64 t, %1; cvt.u32.u64 %0, t; }" : "=r"(a) : "l"(p));
    return a;
}

#define LDMX4(r, addr) \
    asm volatile("ldmatrix.sync.aligned.m8n8.x4.shared.b16 {%0,%1,%2,%3}, [%4];" \
        : "=r"((r)[0]), "=r"((r)[1]), "=r"((r)[2]), "=r"((r)[3]) : "r"(addr))

__device__ __forceinline__ void mma16816(float* c, const uint32_t* a, const uint32_t* b) {
    asm volatile(
        "mma.sync.aligned.m16n8k16.row.col.f32.f16.f16.f32 "
        "{%0,%1,%2,%3}, {%4,%5,%6,%7}, {%8,%9}, {%0,%1,%2,%3};\n"
        : "+f"(c[0]), "+f"(c[1]), "+f"(c[2]), "+f"(c[3])
        : "r"(a[0]), "r"(a[1]), "r"(a[2]), "r"(a[3]), "r"(b[0]), "r"(b[1]));
}

#define CP_ASYNC16(dst, src, sz) \
    asm volatile("cp.async.cg.shared.global [%0], [%1], 16, %2;" \
        :: "r"(dst), "l"(src), "r"(sz))
#define CP_COMMIT() asm volatile("cp.async.commit_group;" ::: "memory")
#define CP_WAIT0()  asm volatile("cp.async.wait_group 0;" ::: "memory")
#define CP_WAIT1()  asm volatile("cp.async.wait_group 1;" ::: "memory")

// ---------------- weight prep: ALL weight types + layers, one launch ----------------
// sources fp32 [nlayers, K, N] -> g_w fp16 [nlayers(LW_STRIDE), N, K] per group
__global__ void wprep_all_kernel(const float* __restrict__ vp, const float* __restrict__ so,
                                 const float* __restrict__ aw, const float* __restrict__ op,
                                 const float* __restrict__ f1, const float* __restrict__ f2,
                                 __half* __restrict__ dst)
{
    int idx = blockIdx.x * blockDim.x + threadIdx.x;
    if (idx >= NLAYERS_C * LW_STRIDE) return;
    int l = idx / LW_STRIDE;
    int r = idx - l * LW_STRIDE;
    const float* W;
    int K, N, r0;
    if (r < 131072) {
        if (r < 65536) { W = vp; K = 256; N = 256; r0 = r; }
        else           { W = so; K = 256; N = 256; r0 = r - 65536; }
    } else if (r < 229376) {
        if (r < 163840) { W = aw; K = 256; N = 128; r0 = r - 131072; }
        else            { W = op; K = 256; N = 256; r0 = r - 163840; }
    } else {
        if (r < 491520) { W = f1; K = 256;  N = 1024; r0 = r - 229376; }
        else            { W = f2; K = 1024; N = 256;  r0 = r - 491520; }
    }
    int n = r0 / K, k = r0 - n * K;
    dst[idx] = __float2half(__ldg(W + (size_t)l * K * N + (size_t)k * N + n));
}

// ---------------- flatten: (B,D,H,W) -> (B,L,D); emits src fp16 + q fp16 -----------
__global__ void flatten_kernel(const float* __restrict__ s0, const float* __restrict__ s1,
                               const float* __restrict__ s2, const float* __restrict__ s3,
                               const float* __restrict__ p0, const float* __restrict__ p1,
                               const float* __restrict__ p2, const float* __restrict__ p3,
                               const float* __restrict__ lvl_emb)
{
    long long idx = (long long)blockIdx.x * blockDim.x + threadIdx.x;
    const long long tot = (long long)MROWS * DMODEL;
    if (idx >= tot) return;
    int d = (int)(idx & 255);
    int m = (int)(idx >> 8);
    int b = m / L_TOT;
    int n = m - b * L_TOT;
    int lvl, hw, HW;
    const float *sp, *pp;
    if (n < 10000)      { lvl = 0; hw = n;         HW = 10000; sp = s0; pp = p0; }
    else if (n < 12500) { lvl = 1; hw = n - 10000; HW = 2500;  sp = s1; pp = p1; }
    else if (n < 13125) { lvl = 2; hw = n - 12500; HW = 625;   sp = s2; pp = p2; }
    else                { lvl = 3; hw = n - 13125; HW = 169;   sp = s3; pp = p3; }
    size_t sidx = ((size_t)b * DMODEL + d) * HW + hw;
    float sv = __ldg(sp + sidx);
    float pv = __ldg(pp + sidx) + __ldg(lvl_emb + lvl * DMODEL + d);
    g_src[idx] = sv;
    g_pos[idx] = pv;
    g_src_h[idx] = __float2half(sv);
    g_q_h[idx]   = __float2half(sv + pv);
}

// ---------------- HMMA fp16 GEMM, cp.async 3-stage pipeline, CTA 128x64 -------------
// C[M,N] = A[M,K] @ W[K,N] + bias.  A fp16 [M,K]; W fp16 [N,K].  fp32 accumulate.
// 8 warps (4m x 2n), warp tile 32x32, BK=32.
// bias col<bias_split -> bias[col], else bias2[col-split].
// OUTMODE 0: fp32 out (opt RELU); OUTMODE 1: fp16 out (opt RELU).
template<bool RELU, int OUTMODE>
__global__ __launch_bounds__(256)
void mma_gemm(const __half* __restrict__ A,
              const __half* __restrict__ B,
              const float* __restrict__ bias, const float* __restrict__ bias2, int bias_split,
              float* __restrict__ Cf,
              __half* __restrict__ Ch,
              int Mr, int K, int N)
{
    extern __shared__ char smem[];
    // per stage: As[128][40] Bs[64][40] (fp16, 80B rows)
    const int ASZ = 128 * 80;          // 10240 B
    const int BSZ = 64 * 80;           // 5120 B
    const int STG = ASZ + BSZ;         // 15360 B

    const int tid  = threadIdx.x;
    const int lane = tid & 31;
    const int warp = tid >> 5;
    const int wm   = warp & 3;          // 0..3 (32 rows each)
    const int wn   = warp >> 2;         // 0..1 (32 cols each)
    const int row0 = blockIdx.x * 128;
    const int col0 = blockIdx.y * 64;

    const uint32_t smem_base = smem_u32(smem);

    const int aRow = tid >> 2;            // 0..63 (rows aRow, aRow+64)
    const int aOff = (tid & 3) << 3;      // 0,8,16,24

    float acc[2][4][4];
    #pragma unroll
    for (int i = 0; i < 2; i++)
        #pragma unroll
        for (int j = 0; j < 4; j++)
            #pragma unroll
            for (int k = 0; k < 4; k++) acc[i][j][k] = 0.f;

    const int nch = K >> 5;   // >= 8 always

    auto load_chunk = [&](int ch, int stage) {
        const int kb = ch << 5;
        const uint32_t sb = smem_base + stage * STG;
        #pragma unroll
        for (int r = 0; r < 2; r++) {
            const int ar = aRow + r * 64;
            const int ok = (row0 + ar < Mr) ? 16 : 0;
            const size_t g = (size_t)(row0 + ar) * K + kb + aOff;
            CP_ASYNC16(sb + ar * 80 + aOff * 2, A + g, ok);
        }
        {
            const size_t g = (size_t)(col0 + aRow) * K + kb + aOff;
            CP_ASYNC16(sb + ASZ + aRow * 80 + aOff * 2, B + g, 16);
        }
    };

    load_chunk(0, 0); CP_COMMIT();
    load_chunk(1, 1); CP_COMMIT();

    int stage = 0;
    for (int ch = 0; ch < nch; ch++) {
        if (ch + 2 < nch) CP_WAIT1(); else CP_WAIT0();
        __syncthreads();
        if (ch + 2 < nch) {
            int ns = stage + 2; if (ns >= 3) ns -= 3;
            load_chunk(ch + 2, ns);
            CP_COMMIT();
        }
        const uint32_t sb = smem_base + stage * STG;

        #pragma unroll
        for (int ks = 0; ks < 2; ks++) {
            const int k0 = ks << 4;
            uint32_t af[2][4];
            #pragma unroll
            for (int mt = 0; mt < 2; mt++) {
                const int arow = wm * 32 + mt * 16 + (lane & 15);
                const int acol = k0 + ((lane >> 4) << 3);
                LDMX4(af[mt], sb + arow * 80 + acol * 2);
            }
            uint32_t bf[4][2];
            #pragma unroll
            for (int np = 0; np < 2; np++) {
                const int tr = wn * 32 + np * 16 + ((lane >> 4) << 3) + (lane & 7);
                const int tc = k0 + (((lane >> 3) & 1) << 3);
                uint32_t t[4];
                LDMX4(t, sb + ASZ + tr * 80 + tc * 2);
                bf[np * 2][0] = t[0]; bf[np * 2][1] = t[1];
                bf[np * 2 + 1][0] = t[2]; bf[np * 2 + 1][1] = t[3];
            }
            #pragma unroll
            for (int mt = 0; mt < 2; mt++)
                #pragma unroll
                for (int nt = 0; nt < 4; nt++)
                    mma16816(acc[mt][nt], af[mt], bf[nt]);
        }
        if (++stage >= 3) stage = 0;
    }

    // epilogue
    const int g  = lane >> 2;
    const int tg = lane & 3;
    #pragma unroll
    for (int mt = 0; mt < 2; mt++) {
        #pragma unroll
        for (int nt = 0; nt < 4; nt++) {
            const int col = col0 + wn * 32 + nt * 8 + tg * 2;
            float b0, b1;
            if (col < bias_split) {
                b0 = __ldg(bias + col);
                b1 = __ldg(bias + col + 1);
            } else {
                b0 = __ldg(bias2 + col - bias_split);
                b1 = __ldg(bias2 + col - bias_split + 1);
            }
            #pragma unroll
            for (int half_i = 0; half_i < 2; half_i++) {
                const int row = row0 + wm * 32 + mt * 16 + g + half_i * 8;
                if (row < Mr) {
                    float v0 = acc[mt][nt][half_i * 2 + 0] + b0;
                    float v1 = acc[mt][nt][half_i * 2 + 1] + b1;
                    if (RELU) { v0 = fmaxf(v0, 0.f); v1 = fmaxf(v1, 0.f); }
                    if (OUTMODE == 0) {
                        *reinterpret_cast<float2*>(Cf + (size_t)row * N + col) = make_float2(v0, v1);
                    } else {
                        *reinterpret_cast<__half2*>(Ch + (size_t)row * N + col) =
                            __halves2half2(__float2half(v0), __float2half(v1));
                    }
                }
            }
        }
    }
}

// ---------------- deformable attention sampling (one warp per (b,q,head)) -----------
// value is fp16; offaw row: [0,256) offsets (h*32 each), [256,384) aw logits (h*16)
__global__ void deform_kernel(const __half* __restrict__ value,
                              const float* __restrict__ offaw,
                              __half* __restrict__ out_h)
{
    int gw = (int)((blockIdx.x * blockDim.x + threadIdx.x) >> 5);
    if (gw >= MROWS * NHEADS) return;
    int lane = threadIdx.x & 31;
    int h = gw & 7;
    int m = gw >> 3;
    int b = m / L_TOT;
    int q = m - b * L_TOT;

    float ref_x, ref_y;
    {
        int idx, Wl, Hl;
        if (q < 10000)      { idx = q;         Wl = 100; Hl = 100; }
        else if (q < 12500) { idx = q - 10000; Wl = 50;  Hl = 50;  }
        else if (q < 13125) { idx = q - 12500; Wl = 25;  Hl = 25;  }
        else                { idx = q - 13125; Wl = 13;  Hl = 13;  }
        int yy = idx / Wl, xx = idx - yy * Wl;
        ref_x = (xx + 0.5f) / (float)Wl;
        ref_y = (yy + 0.5f) / (float)Hl;
    }

    const float* awp = offaw + (size_t)m * 384 + 256 + h * 16;
    float e[16];
    float mx = -1e30f;
    #pragma unroll
    for (int i = 0; i < 16; i++) { e[i] = __ldg(awp + i); mx = fmaxf(mx, e[i]); }
    float ssum = 0.f;
    #pragma unroll
    for (int i = 0; i < 16; i++) { e[i] = __expf(e[i] - mx); ssum += e[i]; }
    float inv = 1.f / ssum;

    const float*  offp  = offaw + (size_t)m * 384 + h * 32;
    const __half* vbase = value + (size_t)b * L_TOT * 256 + h * 32 + lane;

    const int Ws[4]     = {100, 50, 25, 13};
    const int Hs[4]     = {100, 50, 25, 13};
    const int starts[4] = {0, 10000, 12500, 13125};

    float acc = 0.f;
    #pragma unroll
    for (int l = 0; l < 4; l++) {
        const int   Wl = Ws[l], Hl = Hs[l], st = starts[l];
        const float fW = (float)Wl, fH = (float)Hl;
        #pragma unroll
        for (int p = 0; p < 4; p++) {
            float ox = __ldg(offp + l * 8 + p * 2);
            float oy = __ldg(offp + l * 8 + p * 2 + 1);
            float px = ref_x * fW + ox - 0.5f;
            float py = ref_y * fH + oy - 0.5f;
            float x0f = floorf(px), y0f = floorf(py);
            float wx1 = px - x0f, wy1 = py - y0f;
            int x0 = (int)x0f, y0 = (int)y0f;
            float wgt = e[l * 4 + p] * inv;
            #pragma unroll
            for (int t = 0; t < 4; t++) {
                int xi = x0 + (t & 1);
                int yi = y0 + (t >> 1);
                float w = ((t & 1) ? wx1 : 1.f - wx1) * ((t >> 1) ? wy1 : 1.f - wy1);
                if (xi >= 0 && xi < Wl && yi >= 0 && yi < Hl && w != 0.f) {
                    acc = fmaf(wgt * w,
                               __half2float(__ldg(vbase + (size_t)(st + yi * Wl + xi) * 256)),
                               acc);
                }
            }
        }
    }
    out_h[(size_t)m * 256 + h * 32 + lane] = __float2half(acc);
}

// ---------------- fused residual add + LayerNorm (one warp per row) -----------------
// emits fp32 out + fp16; if pos != nullptr also emits q fp16 = fp16(out + pos)
__global__ void add_ln_kernel(const float* __restrict__ X, const float* __restrict__ R,
                              const float* __restrict__ w, const float* __restrict__ b,
                              const float* __restrict__ pos,
                              float* __restrict__ out,
                              __half* __restrict__ out_h,
                              __half* __restrict__ q_h)
{
    int row = (int)((blockIdx.x * blockDim.x + threadIdx.x) >> 5);
    if (row >= MROWS) return;
    int lane = threadIdx.x & 31;
    const float* x = X + (size_t)row * DMODEL;
    const float* r = R + (size_t)row * DMODEL;
    float v[8];
    float s = 0.f;
    #pragma unroll
    for (int j = 0; j < 8; j++) {
        int c = lane + j * 32;
        v[j] = x[c] + r[c];
        s += v[j];
    }
    #pragma unroll
    for (int o = 16; o > 0; o >>= 1) s += __shfl_xor_sync(0xFFFFFFFFu, s, o);
    float mean = s * (1.f / 256.f);
    float qv = 0.f;
    #pragma unroll
    for (int j = 0; j < 8; j++) { float d = v[j] - mean; qv += d * d; }
    #pragma unroll
    for (int o = 16; o > 0; o >>= 1) qv += __shfl_xor_sync(0xFFFFFFFFu, qv, o);
    float invs = rsqrtf(qv * (1.f / 256.f) + 1e-5f);
    #pragma unroll
    for (int j = 0; j < 8; j++) {
        int c = lane + j * 32;
        float o = (v[j] - mean) * invs * __ldg(w + c) + __ldg(b + c);
        size_t oi = (size_t)row * DMODEL + c;
        out[oi] = o;
        out_h[oi] = __float2half(o);
        if (pos != nullptr) q_h[oi] = __float2half(o + __ldg(pos + oi));
    }
}

// ---------------- output write: src then level_start_index (as floats) -------------
__global__ void write_out_kernel(float* __restrict__ out, int n)
{
    long long i = (long long)blockIdx.x * blockDim.x + threadIdx.x;
    if (i >= n) return;
    const long long tot = (long long)MROWS * DMODEL;
    if (i < tot) {
        out[i] = g_src[i];
    } else {
        int k = (int)(i - tot);
        float st;
        switch (k) {
            case 0: st = 0.f;      break;
            case 1: st = 10000.f;  break;
            case 2: st = 12500.f;  break;
            case 3: st = 13125.f;  break;
            default: st = 0.f;     break;
        }
        out[i] = st;
    }
}

// ---------------- host launch ----------------
extern "C" void kernel_launch(void* const* d_in, const int* in_sizes, int n_in,
                              void* d_out, int out_size)
{
    // setup_inputs() dict order is INTERLEAVED: src0, pos0, src1, pos1, ...
    const float* s0 = (const float*)d_in[0];
    const float* p0 = (const float*)d_in[1];
    const float* s1 = (const float*)d_in[2];
    const float* p1 = (const float*)d_in[3];
    const float* s2 = (const float*)d_in[4];
    const float* p2 = (const float*)d_in[5];
    const float* s3 = (const float*)d_in[6];
    const float* p3 = (const float*)d_in[7];
    const float* lvl_emb = (const float*)d_in[8];
    const float* so_w = (const float*)d_in[9];
    const float* so_b = (const float*)d_in[10];
    const float* aw_w = (const float*)d_in[11];
    const float* aw_b = (const float*)d_in[12];
    const float* vp_w = (const float*)d_in[13];
    const float* vp_b = (const float*)d_in[14];
    const float* op_w = (const float*)d_in[15];
    const float* op_b = (const float*)d_in[16];
    const float* n1_w = (const float*)d_in[17];
    const float* n1_b = (const float*)d_in[18];
    const float* f1_w = (const float*)d_in[19];
    const float* f1_b = (const float*)d_in[20];
    const float* f2_w = (const float*)d_in[21];
    const float* f2_b = (const float*)d_in[22];
    const float* n2_w = (const float*)d_in[23];
    const float* n2_b = (const float*)d_in[24];

    float *pg_src, *pg_pos, *pg_offaw, *pg_tmp;
    __half *pg_val_h, *pg_src_h, *pg_q_h, *pg_attn_h, *pg_h_h, *pg_w;
    cudaGetSymbolAddress((void**)&pg_src,   g_src);
    cudaGetSymbolAddress((void**)&pg_pos,   g_pos);
    cudaGetSymbolAddress((void**)&pg_offaw, g_offaw);
    cudaGetSymbolAddress((void**)&pg_tmp,   g_tmp);
    cudaGetSymbolAddress((void**)&pg_val_h, g_val_h);
    cudaGetSymbolAddress((void**)&pg_src_h, g_src_h);
    cudaGetSymbolAddress((void**)&pg_q_h,   g_q_h);
    cudaGetSymbolAddress((void**)&pg_attn_h, g_attn_h);
    cudaGetSymbolAddress((void**)&pg_h_h,   g_h_h);
    cudaGetSymbolAddress((void**)&pg_w,     g_w);

    // dynamic smem for GEMM: 3 stages x 15360 B
    const int GEMM_SMEM = 46080;
    cudaFuncSetAttribute(mma_gemm<false, 0>, cudaFuncAttributeMaxDynamicSharedMemorySize, GEMM_SMEM);
    cudaFuncSetAttribute(mma_gemm<false, 1>, cudaFuncAttributeMaxDynamicSharedMemorySize, GEMM_SMEM);
    cudaFuncSetAttribute(mma_gemm<true, 1>,  cudaFuncAttributeMaxDynamicSharedMemorySize, GEMM_SMEM);

    const long long totElem = (long long)MROWS * DMODEL;
    const int ew_grid = (int)((totElem + 255) / 256);

    // launch 1: all weight prep
    wprep_all_kernel<<<(NLAYERS_C * LW_STRIDE + 255) / 256, 256>>>(
        vp_w, so_w, aw_w, op_w, f1_w, f2_w, pg_w);
    // launch 2: flatten
    flatten_kernel<<<ew_grid, 256>>>(s0, s1, s2, s3, p0, p1, p2, p3, lvl_emb);

    const int mblk = (MROWS + 127) / 128;   // 416
    const dim3 blk(256);
    const int ln_grid = (MROWS * 32 + 255) / 256;
    const int deform_grid = (MROWS * NHEADS * 32 + 255) / 256;

    for (int i = 0; i < NLAYERS_C; i++) {
        size_t wb = (size_t)i * LW_STRIDE;
        const __half* vp_h = pg_w + wb + OFF_VP;
        const __half* sa_h = pg_w + wb + OFF_SOAW;
        const __half* op_h = pg_w + wb + OFF_OP;
        const __half* f1_h = pg_w + wb + OFF_F1;
        const __half* f2_h = pg_w + wb + OFF_F2;

        // value = src @ vp_w + vp_b  (fp16 out)
        mma_gemm<false, 1><<<dim3(mblk, 4), blk, GEMM_SMEM>>>(
            pg_src_h, vp_h, vp_b + (size_t)i * 256, vp_b + (size_t)i * 256, 256,
            nullptr, pg_val_h, MROWS, 256, 256);
        // [offsets | aw] = q @ [so_w | aw_w] (N=384 fused)
        mma_gemm<false, 0><<<dim3(mblk, 6), blk, GEMM_SMEM>>>(
            pg_q_h, sa_h, so_b + (size_t)i * 256, aw_b + (size_t)i * 128, 256,
            pg_offaw, nullptr, MROWS, 256, 384);
        // deformable sampling -> attn fp16
        deform_kernel<<<deform_grid, 256>>>(pg_val_h, pg_offaw, pg_attn_h);
        // output proj                                            [layer0: launch 6 -> ncu]
        mma_gemm<false, 0><<<dim3(mblk, 4), blk, GEMM_SMEM>>>(
            pg_attn_h, op_h, op_b + (size_t)i * 256, op_b + (size_t)i * 256, 256,
            pg_tmp, nullptr, MROWS, 256, 256);
        // src = LN(src + attn_proj)
        add_ln_kernel<<<ln_grid, 256>>>(pg_src, pg_tmp,
                                        n1_w + (size_t)i * DMODEL, n1_b + (size_t)i * DMODEL,
                                        nullptr, pg_src, pg_src_h, nullptr);
        // h = relu(src @ f1_w + f1_b)  (fp16 out)
        mma_gemm<true, 1><<<dim3(mblk, 16), blk, GEMM_SMEM>>>(
            pg_src_h, f1_h, f1_b + (size_t)i * DFFN, f1_b + (size_t)i * DFFN, DFFN,
            nullptr, pg_h_h, MROWS, 256, DFFN);
        // tmp = h @ f2_w + f2_b
        mma_gemm<false, 0><<<dim3(mblk, 4), blk, GEMM_SMEM>>>(
            pg_h_h, f2_h, f2_b + (size_t)i * 256, f2_b + (size_t)i * 256, 256,
            pg_tmp, nullptr, MROWS, 1024, 256);
        // src = LN(src + ffn), also emit q fp16 for next layer
        add_ln_kernel<<<ln_grid, 256>>>(pg_src, pg_tmp,
                                        n2_w + (size_t)i * DMODEL, n2_b + (size_t)i * DMODEL,
                                        pg_pos, pg_src, pg_src_h, pg_q_h);
    }

    write_out_kernel<<<(out_size + 255) / 256, 256>>>((float*)d_out, out_size);
}

// round 11
// speedup vs baseline: 1.5214x; 1.0409x over previous
#include <cuda_runtime.h>
#include <cuda_fp16.h>
#include <cstdint>
#include <math.h>

// ---------------- problem constants ----------------
#define L_TOT   13294          // 10000 + 2500 + 625 + 169
#define BATCH   4
#define MROWS   (BATCH * L_TOT)   // 53176
#define DMODEL  256
#define DFFN    1024
#define NLAYERS_C 6
#define NHEADS  8

// weight layout offsets (elements) within one layer block
#define OFF_VP    0
#define OFF_SOAW  65536          // combined so(256) + aw(128) rows => [384,256]
#define OFF_OP    163840
#define OFF_F1    229376
#define OFF_F2    491520
#define LW_STRIDE 753664

// ---------------- device scratch (static, allowed) ----------------
__device__ __align__(16) float g_src  [MROWS * DMODEL];
__device__ __align__(16) float g_pos  [MROWS * DMODEL];
__device__ __align__(16) float g_offaw[MROWS * 384];
__device__ __align__(16) float g_tmp  [MROWS * DMODEL];

__device__ __align__(16) __half g_val_h [MROWS * DMODEL];
__device__ __align__(16) __half g_src_h [MROWS * DMODEL];
__device__ __align__(16) __half g_q_h   [MROWS * DMODEL];
__device__ __align__(16) __half g_attn_h[MROWS * DMODEL];
__device__ __align__(16) __half g_h_h   [(size_t)MROWS * DFFN];
__device__ __align__(16) __half g_w     [NLAYERS_C * LW_STRIDE];

// ---------------- helpers ----------------
__device__ __forceinline__ uint32_t smem_u32(const void* p) {
    uint32_t a;
    asm("{ .reg .u64 t; cvta.to.shared.u64 t, %1; cvt.u32.u64 %0, t; }" : "=r"(a) : "l"(p));
    return a;
}

#define LDMX4(r, addr) \
    asm volatile("ldmatrix.sync.aligned.m8n8.x4.shared.b16 {%0,%1,%2,%3}, [%4];" \
        : "=r"((r)[0]), "=r"((r)[1]), "=r"((r)[2]), "=r"((r)[3]) : "r"(addr))

__device__ __forceinline__ void mma16816(float* c, const uint32_t* a, const uint32_t* b) {
    asm volatile(
        "mma.sync.aligned.m16n8k16.row.col.f32.f16.f16.f32 "
        "{%0,%1,%2,%3}, {%4,%5,%6,%7}, {%8,%9}, {%0,%1,%2,%3};\n"
        : "+f"(c[0]), "+f"(c[1]), "+f"(c[2]), "+f"(c[3])
        : "r"(a[0]), "r"(a[1]), "r"(a[2]), "r"(a[3]), "r"(b[0]), "r"(b[1]));
}

#define CP_ASYNC16(dst, src, sz) \
    asm volatile("cp.async.cg.shared.global [%0], [%1], 16, %2;" \
        :: "r"(dst), "l"(src), "r"(sz))
#define CP_COMMIT() asm volatile("cp.async.commit_group;" ::: "memory")
#define CP_WAIT0()  asm volatile("cp.async.wait_group 0;" ::: "memory")
#define CP_WAIT1()  asm volatile("cp.async.wait_group 1;" ::: "memory")

// ---------------- weight prep: ALL weight types + layers, one launch ----------------
// sources fp32 [nlayers, K, N] -> g_w fp16 [nlayers(LW_STRIDE), N, K] per group
__global__ void wprep_all_kernel(const float* __restrict__ vp, const float* __restrict__ so,
                                 const float* __restrict__ aw, const float* __restrict__ op,
                                 const float* __restrict__ f1, const float* __restrict__ f2,
                                 __half* __restrict__ dst)
{
    int idx = blockIdx.x * blockDim.x + threadIdx.x;
    if (idx >= NLAYERS_C * LW_STRIDE) return;
    int l = idx / LW_STRIDE;
    int r = idx - l * LW_STRIDE;
    const float* W;
    int K, N, r0;
    if (r < 131072) {
        if (r < 65536) { W = vp; K = 256; N = 256; r0 = r; }
        else           { W = so; K = 256; N = 256; r0 = r - 65536; }
    } else if (r < 229376) {
        if (r < 163840) { W = aw; K = 256; N = 128; r0 = r - 131072; }
        else            { W = op; K = 256; N = 256; r0 = r - 163840; }
    } else {
        if (r < 491520) { W = f1; K = 256;  N = 1024; r0 = r - 229376; }
        else            { W = f2; K = 1024; N = 256;  r0 = r - 491520; }
    }
    int n = r0 / K, k = r0 - n * K;
    dst[idx] = __float2half(__ldg(W + (size_t)l * K * N + (size_t)k * N + n));
}

// ---------------- flatten: (B,D,H,W) -> (B,L,D); emits src fp16 + q fp16 -----------
__global__ void flatten_kernel(const float* __restrict__ s0, const float* __restrict__ s1,
                               const float* __restrict__ s2, const float* __restrict__ s3,
                               const float* __restrict__ p0, const float* __restrict__ p1,
                               const float* __restrict__ p2, const float* __restrict__ p3,
                               const float* __restrict__ lvl_emb)
{
    long long idx = (long long)blockIdx.x * blockDim.x + threadIdx.x;
    const long long tot = (long long)MROWS * DMODEL;
    if (idx >= tot) return;
    int d = (int)(idx & 255);
    int m = (int)(idx >> 8);
    int b = m / L_TOT;
    int n = m - b * L_TOT;
    int lvl, hw, HW;
    const float *sp, *pp;
    if (n < 10000)      { lvl = 0; hw = n;         HW = 10000; sp = s0; pp = p0; }
    else if (n < 12500) { lvl = 1; hw = n - 10000; HW = 2500;  sp = s1; pp = p1; }
    else if (n < 13125) { lvl = 2; hw = n - 12500; HW = 625;   sp = s2; pp = p2; }
    else                { lvl = 3; hw = n - 13125; HW = 169;   sp = s3; pp = p3; }
    size_t sidx = ((size_t)b * DMODEL + d) * HW + hw;
    float sv = __ldg(sp + sidx);
    float pv = __ldg(pp + sidx) + __ldg(lvl_emb + lvl * DMODEL + d);
    g_src[idx] = sv;
    g_pos[idx] = pv;
    g_src_h[idx] = __float2half(sv);
    g_q_h[idx]   = __float2half(sv + pv);
}

// ---------------- HMMA fp16 GEMM, cp.async 3-stage, CTA 128x128 ---------------------
// C[M,N] = A[M,K] @ W[K,N] + bias.  A fp16 [M,K]; W fp16 [N,K].  fp32 accumulate.
// 8 warps (4m x 2n), warp tile 32x64 (2 m16 x 8 n8), BK=32.
// bias col<bias_split -> bias[col], else bias2[col-split].
// OUTMODE 0: fp32 out (opt RELU); OUTMODE 1: fp16 out (opt RELU).
template<bool RELU, int OUTMODE>
__global__ __launch_bounds__(256, 2)
void mma_gemm(const __half* __restrict__ A,
              const __half* __restrict__ B,
              const float* __restrict__ bias, const float* __restrict__ bias2, int bias_split,
              float* __restrict__ Cf,
              __half* __restrict__ Ch,
              int Mr, int K, int N)
{
    extern __shared__ char smem[];
    // per stage: As[128][40] Bs[128][40] (fp16, 80B rows)
    const int ASZ = 128 * 80;          // 10240 B
    const int BSZ = 128 * 80;          // 10240 B
    const int STG = ASZ + BSZ;         // 20480 B

    const int tid  = threadIdx.x;
    const int lane = tid & 31;
    const int warp = tid >> 5;
    const int wm   = warp & 3;          // 0..3 (32 rows each)
    const int wn   = warp >> 2;         // 0..1 (64 cols each)
    const int row0 = blockIdx.x * 128;
    const int col0 = blockIdx.y * 128;

    const uint32_t smem_base = smem_u32(smem);

    const int ldRow = tid >> 2;           // 0..63 (rows ldRow, ldRow+64)
    const int ldOff = (tid & 3) << 3;     // 0,8,16,24

    float acc[2][8][4];
    #pragma unroll
    for (int i = 0; i < 2; i++)
        #pragma unroll
        for (int j = 0; j < 8; j++)
            #pragma unroll
            for (int k = 0; k < 4; k++) acc[i][j][k] = 0.f;

    const int nch = K >> 5;   // >= 8

    auto load_chunk = [&](int ch, int stage) {
        const int kb = ch << 5;
        const uint32_t sb = smem_base + stage * STG;
        #pragma unroll
        for (int r = 0; r < 2; r++) {
            const int ar = ldRow + r * 64;
            // A rows (guarded)
            {
                const int ok = (row0 + ar < Mr) ? 16 : 0;
                const size_t g = (size_t)(row0 + ar) * K + kb + ldOff;
                CP_ASYNC16(sb + ar * 80 + ldOff * 2, A + g, ok);
            }
            // B rows
            {
                const size_t g = (size_t)(col0 + ar) * K + kb + ldOff;
                CP_ASYNC16(sb + ASZ + ar * 80 + ldOff * 2, B + g, 16);
            }
        }
    };

    load_chunk(0, 0); CP_COMMIT();
    load_chunk(1, 1); CP_COMMIT();

    int stage = 0;
    for (int ch = 0; ch < nch; ch++) {
        if (ch + 2 < nch) CP_WAIT1(); else CP_WAIT0();
        __syncthreads();
        if (ch + 2 < nch) {
            int ns = stage + 2; if (ns >= 3) ns -= 3;
            load_chunk(ch + 2, ns);
            CP_COMMIT();
        }
        const uint32_t sb = smem_base + stage * STG;

        #pragma unroll
        for (int ks = 0; ks < 2; ks++) {
            const int k0 = ks << 4;
            uint32_t af[2][4];
            #pragma unroll
            for (int mt = 0; mt < 2; mt++) {
                const int arow = wm * 32 + mt * 16 + (lane & 15);
                const int acol = k0 + ((lane >> 4) << 3);
                LDMX4(af[mt], sb + arow * 80 + acol * 2);
            }
            #pragma unroll
            for (int np = 0; np < 4; np++) {
                const int tr = wn * 64 + np * 16 + ((lane >> 4) << 3) + (lane & 7);
                const int tc = k0 + (((lane >> 3) & 1) << 3);
                uint32_t t[4];
                LDMX4(t, sb + ASZ + tr * 80 + tc * 2);
                uint32_t b0[2] = { t[0], t[1] };
                uint32_t b1[2] = { t[2], t[3] };
                #pragma unroll
                for (int mt = 0; mt < 2; mt++) {
                    mma16816(acc[mt][np * 2 + 0], af[mt], b0);
                    mma16816(acc[mt][np * 2 + 1], af[mt], b1);
                }
            }
        }
        if (++stage >= 3) stage = 0;
    }

    // epilogue
    const int g  = lane >> 2;
    const int tg = lane & 3;
    #pragma unroll
    for (int mt = 0; mt < 2; mt++) {
        #pragma unroll
        for (int nt = 0; nt < 8; nt++) {
            const int col = col0 + wn * 64 + nt * 8 + tg * 2;
            float b0, b1;
            if (col < bias_split) {
                b0 = __ldg(bias + col);
                b1 = __ldg(bias + col + 1);
            } else {
                b0 = __ldg(bias2 + col - bias_split);
                b1 = __ldg(bias2 + col - bias_split + 1);
            }
            #pragma unroll
            for (int half_i = 0; half_i < 2; half_i++) {
                const int row = row0 + wm * 32 + mt * 16 + g + half_i * 8;
                if (row < Mr) {
                    float v0 = acc[mt][nt][half_i * 2 + 0] + b0;
                    float v1 = acc[mt][nt][half_i * 2 + 1] + b1;
                    if (RELU) { v0 = fmaxf(v0, 0.f); v1 = fmaxf(v1, 0.f); }
                    if (OUTMODE == 0) {
                        *reinterpret_cast<float2*>(Cf + (size_t)row * N + col) = make_float2(v0, v1);
                    } else {
                        *reinterpret_cast<__half2*>(Ch + (size_t)row * N + col) =
                            __halves2half2(__float2half(v0), __float2half(v1));
                    }
                }
            }
        }
    }
}

// ---------------- deformable attention sampling (one warp per (b,q,head)) -----------
// value is fp16; offaw row: [0,256) offsets (h*32 each), [256,384) aw logits (h*16)
__global__ void deform_kernel(const __half* __restrict__ value,
                              const float* __restrict__ offaw,
                              __half* __restrict__ out_h)
{
    int gw = (int)((blockIdx.x * blockDim.x + threadIdx.x) >> 5);
    if (gw >= MROWS * NHEADS) return;
    int lane = threadIdx.x & 31;
    int h = gw & 7;
    int m = gw >> 3;
    int b = m / L_TOT;
    int q = m - b * L_TOT;

    float ref_x, ref_y;
    {
        int idx, Wl, Hl;
        if (q < 10000)      { idx = q;         Wl = 100; Hl = 100; }
        else if (q < 12500) { idx = q - 10000; Wl = 50;  Hl = 50;  }
        else if (q < 13125) { idx = q - 12500; Wl = 25;  Hl = 25;  }
        else                { idx = q - 13125; Wl = 13;  Hl = 13;  }
        int yy = idx / Wl, xx = idx - yy * Wl;
        ref_x = (xx + 0.5f) / (float)Wl;
        ref_y = (yy + 0.5f) / (float)Hl;
    }

    const float* awp = offaw + (size_t)m * 384 + 256 + h * 16;
    float e[16];
    float mx = -1e30f;
    #pragma unroll
    for (int i = 0; i < 16; i++) { e[i] = __ldg(awp + i); mx = fmaxf(mx, e[i]); }
    float ssum = 0.f;
    #pragma unroll
    for (int i = 0; i < 16; i++) { e[i] = __expf(e[i] - mx); ssum += e[i]; }
    float inv = 1.f / ssum;

    const float*  offp  = offaw + (size_t)m * 384 + h * 32;
    const __half* vbase = value + (size_t)b * L_TOT * 256 + h * 32 + lane;

    const int Ws[4]     = {100, 50, 25, 13};
    const int Hs[4]     = {100, 50, 25, 13};
    const int starts[4] = {0, 10000, 12500, 13125};

    float acc = 0.f;
    #pragma unroll
    for (int l = 0; l < 4; l++) {
        const int   Wl = Ws[l], Hl = Hs[l], st = starts[l];
        const float fW = (float)Wl, fH = (float)Hl;
        #pragma unroll
        for (int p = 0; p < 4; p++) {
            float ox = __ldg(offp + l * 8 + p * 2);
            float oy = __ldg(offp + l * 8 + p * 2 + 1);
            float px = ref_x * fW + ox - 0.5f;
            float py = ref_y * fH + oy - 0.5f;
            float x0f = floorf(px), y0f = floorf(py);
            float wx1 = px - x0f, wy1 = py - y0f;
            int x0 = (int)x0f, y0 = (int)y0f;
            float wgt = e[l * 4 + p] * inv;
            #pragma unroll
            for (int t = 0; t < 4; t++) {
                int xi = x0 + (t & 1);
                int yi = y0 + (t >> 1);
                float w = ((t & 1) ? wx1 : 1.f - wx1) * ((t >> 1) ? wy1 : 1.f - wy1);
                if (xi >= 0 && xi < Wl && yi >= 0 && yi < Hl && w != 0.f) {
                    acc = fmaf(wgt * w,
                               __half2float(__ldg(vbase + (size_t)(st + yi * Wl + xi) * 256)),
                               acc);
                }
            }
        }
    }
    out_h[(size_t)m * 256 + h * 32 + lane] = __float2half(acc);
}

// ---------------- fused residual add + LayerNorm (one warp per row) -----------------
// emits fp32 out + fp16; if pos != nullptr also emits q fp16 = fp16(out + pos)
__global__ void add_ln_kernel(const float* __restrict__ X, const float* __restrict__ R,
                              const float* __restrict__ w, const float* __restrict__ b,
                              const float* __restrict__ pos,
                              float* __restrict__ out,
                              __half* __restrict__ out_h,
                              __half* __restrict__ q_h)
{
    int row = (int)((blockIdx.x * blockDim.x + threadIdx.x) >> 5);
    if (row >= MROWS) return;
    int lane = threadIdx.x & 31;
    const float* x = X + (size_t)row * DMODEL;
    const float* r = R + (size_t)row * DMODEL;
    float v[8];
    float s = 0.f;
    #pragma unroll
    for (int j = 0; j < 8; j++) {
        int c = lane + j * 32;
        v[j] = x[c] + r[c];
        s += v[j];
    }
    #pragma unroll
    for (int o = 16; o > 0; o >>= 1) s += __shfl_xor_sync(0xFFFFFFFFu, s, o);
    float mean = s * (1.f / 256.f);
    float qv = 0.f;
    #pragma unroll
    for (int j = 0; j < 8; j++) { float d = v[j] - mean; qv += d * d; }
    #pragma unroll
    for (int o = 16; o > 0; o >>= 1) qv += __shfl_xor_sync(0xFFFFFFFFu, qv, o);
    float invs = rsqrtf(qv * (1.f / 256.f) + 1e-5f);
    #pragma unroll
    for (int j = 0; j < 8; j++) {
        int c = lane + j * 32;
        float o = (v[j] - mean) * invs * __ldg(w + c) + __ldg(b + c);
        size_t oi = (size_t)row * DMODEL + c;
        out[oi] = o;
        out_h[oi] = __float2half(o);
        if (pos != nullptr) q_h[oi] = __float2half(o + __ldg(pos + oi));
    }
}

// ---------------- output write: src then level_start_index (as floats) -------------
__global__ void write_out_kernel(float* __restrict__ out, int n)
{
    long long i = (long long)blockIdx.x * blockDim.x + threadIdx.x;
    if (i >= n) return;
    const long long tot = (long long)MROWS * DMODEL;
    if (i < tot) {
        out[i] = g_src[i];
    } else {
        int k = (int)(i - tot);
        float st;
        switch (k) {
            case 0: st = 0.f;      break;
            case 1: st = 10000.f;  break;
            case 2: st = 12500.f;  break;
            case 3: st = 13125.f;  break;
            default: st = 0.f;     break;
        }
        out[i] = st;
    }
}

// ---------------- host launch ----------------
extern "C" void kernel_launch(void* const* d_in, const int* in_sizes, int n_in,
                              void* d_out, int out_size)
{
    // setup_inputs() dict order is INTERLEAVED: src0, pos0, src1, pos1, ...
    const float* s0 = (const float*)d_in[0];
    const float* p0 = (const float*)d_in[1];
    const float* s1 = (const float*)d_in[2];
    const float* p1 = (const float*)d_in[3];
    const float* s2 = (const float*)d_in[4];
    const float* p2 = (const float*)d_in[5];
    const float* s3 = (const float*)d_in[6];
    const float* p3 = (const float*)d_in[7];
    const float* lvl_emb = (const float*)d_in[8];
    const float* so_w = (const float*)d_in[9];
    const float* so_b = (const float*)d_in[10];
    const float* aw_w = (const float*)d_in[11];
    const float* aw_b = (const float*)d_in[12];
    const float* vp_w = (const float*)d_in[13];
    const float* vp_b = (const float*)d_in[14];
    const float* op_w = (const float*)d_in[15];
    const float* op_b = (const float*)d_in[16];
    const float* n1_w = (const float*)d_in[17];
    const float* n1_b = (const float*)d_in[18];
    const float* f1_w = (const float*)d_in[19];
    const float* f1_b = (const float*)d_in[20];
    const float* f2_w = (const float*)d_in[21];
    const float* f2_b = (const float*)d_in[22];
    const float* n2_w = (const float*)d_in[23];
    const float* n2_b = (const float*)d_in[24];

    float *pg_src, *pg_pos, *pg_offaw, *pg_tmp;
    __half *pg_val_h, *pg_src_h, *pg_q_h, *pg_attn_h, *pg_h_h, *pg_w;
    cudaGetSymbolAddress((void**)&pg_src,   g_src);
    cudaGetSymbolAddress((void**)&pg_pos,   g_pos);
    cudaGetSymbolAddress((void**)&pg_offaw, g_offaw);
    cudaGetSymbolAddress((void**)&pg_tmp,   g_tmp);
    cudaGetSymbolAddress((void**)&pg_val_h, g_val_h);
    cudaGetSymbolAddress((void**)&pg_src_h, g_src_h);
    cudaGetSymbolAddress((void**)&pg_q_h,   g_q_h);
    cudaGetSymbolAddress((void**)&pg_attn_h, g_attn_h);
    cudaGetSymbolAddress((void**)&pg_h_h,   g_h_h);
    cudaGetSymbolAddress((void**)&pg_w,     g_w);

    // dynamic smem for GEMM: 3 stages x 20480 B
    const int GEMM_SMEM = 61440;
    cudaFuncSetAttribute(mma_gemm<false, 0>, cudaFuncAttributeMaxDynamicSharedMemorySize, GEMM_SMEM);
    cudaFuncSetAttribute(mma_gemm<false, 1>, cudaFuncAttributeMaxDynamicSharedMemorySize, GEMM_SMEM);
    cudaFuncSetAttribute(mma_gemm<true, 1>,  cudaFuncAttributeMaxDynamicSharedMemorySize, GEMM_SMEM);

    const long long totElem = (long long)MROWS * DMODEL;
    const int ew_grid = (int)((totElem + 255) / 256);

    // launch 1: all weight prep
    wprep_all_kernel<<<(NLAYERS_C * LW_STRIDE + 255) / 256, 256>>>(
        vp_w, so_w, aw_w, op_w, f1_w, f2_w, pg_w);
    // launch 2: flatten
    flatten_kernel<<<ew_grid, 256>>>(s0, s1, s2, s3, p0, p1, p2, p3, lvl_emb);

    const int mblk = (MROWS + 127) / 128;   // 416
    const dim3 blk(256);
    const int ln_grid = (MROWS * 32 + 255) / 256;
    const int deform_grid = (MROWS * NHEADS * 32 + 255) / 256;

    for (int i = 0; i < NLAYERS_C; i++) {
        size_t wb = (size_t)i * LW_STRIDE;
        const __half* vp_h = pg_w + wb + OFF_VP;
        const __half* sa_h = pg_w + wb + OFF_SOAW;
        const __half* op_h = pg_w + wb + OFF_OP;
        const __half* f1_h = pg_w + wb + OFF_F1;
        const __half* f2_h = pg_w + wb + OFF_F2;

        // value = src @ vp_w + vp_b  (fp16 out)
        mma_gemm<false, 1><<<dim3(mblk, 2), blk, GEMM_SMEM>>>(
            pg_src_h, vp_h, vp_b + (size_t)i * 256, vp_b + (size_t)i * 256, 256,
            nullptr, pg_val_h, MROWS, 256, 256);
        // [offsets | aw] = q @ [so_w | aw_w] (N=384 fused)
        mma_gemm<false, 0><<<dim3(mblk, 3), blk, GEMM_SMEM>>>(
            pg_q_h, sa_h, so_b + (size_t)i * 256, aw_b + (size_t)i * 128, 256,
            pg_offaw, nullptr, MROWS, 256, 384);
        // deformable sampling -> attn fp16
        deform_kernel<<<deform_grid, 256>>>(pg_val_h, pg_offaw, pg_attn_h);
        // output proj                                            [layer0: launch 6 -> ncu]
        mma_gemm<false, 0><<<dim3(mblk, 2), blk, GEMM_SMEM>>>(
            pg_attn_h, op_h, op_b + (size_t)i * 256, op_b + (size_t)i * 256, 256,
            pg_tmp, nullptr, MROWS, 256, 256);
        // src = LN(src + attn_proj)
        add_ln_kernel<<<ln_grid, 256>>>(pg_src, pg_tmp,
                                        n1_w + (size_t)i * DMODEL, n1_b + (size_t)i * DMODEL,
                                        nullptr, pg_src, pg_src_h, nullptr);
        // h = relu(src @ f1_w + f1_b)  (fp16 out)
        mma_gemm<true, 1><<<dim3(mblk, 8), blk, GEMM_SMEM>>>(
            pg_src_h, f1_h, f1_b + (size_t)i * DFFN, f1_b + (size_t)i * DFFN, DFFN,
            nullptr, pg_h_h, MROWS, 256, DFFN);
        // tmp = h @ f2_w + f2_b
        mma_gemm<false, 0><<<dim3(mblk, 2), blk, GEMM_SMEM>>>(
            pg_h_h, f2_h, f2_b + (size_t)i * 256, f2_b + (size_t)i * 256, 256,
            pg_tmp, nullptr, MROWS, 1024, 256);
        // src = LN(src + ffn), also emit q fp16 for next layer
        add_ln_kernel<<<ln_grid, 256>>>(pg_src, pg_tmp,
                                        n2_w + (size_t)i * DMODEL, n2_b + (size_t)i * DMODEL,
                                        pg_pos, pg_src, pg_src_h, pg_q_h);
    }

    write_out_kernel<<<(out_size + 255) / 256, 256>>>((float*)d_out, out_size);
}

// round 12
// speedup vs baseline: 1.5875x; 1.0435x over previous
#include <cuda_runtime.h>
#include <cuda_fp16.h>
#include <cstdint>
#include <math.h>

// ---------------- problem constants ----------------
#define L_TOT   13294          // 10000 + 2500 + 625 + 169
#define BATCH   4
#define MROWS   (BATCH * L_TOT)   // 53176
#define DMODEL  256
#define DFFN    1024
#define NLAYERS_C 6
#define NHEADS  8

// weight layout offsets (elements) within one layer block
#define OFF_VP    0
#define OFF_SOAW  65536          // combined so(256) + aw(128) rows => [384,256]
#define OFF_OP    163840
#define OFF_F1    229376
#define OFF_F2    491520
#define LW_STRIDE 753664

// ---------------- device scratch (static, allowed) ----------------
__device__ __align__(16) float g_src  [MROWS * DMODEL];
__device__ __align__(16) float g_pos  [MROWS * DMODEL];
__device__ __align__(16) float g_offaw[MROWS * 384];
__device__ __align__(16) float g_tmp  [MROWS * DMODEL];

__device__ __align__(16) __half g_val_h [MROWS * DMODEL];
__device__ __align__(16) __half g_src_h [MROWS * DMODEL];
__device__ __align__(16) __half g_q_h   [MROWS * DMODEL];
__device__ __align__(16) __half g_attn_h[MROWS * DMODEL];
__device__ __align__(16) __half g_h_h   [(size_t)MROWS * DFFN];
__device__ __align__(16) __half g_w     [NLAYERS_C * LW_STRIDE];

// ---------------- helpers ----------------
__device__ __forceinline__ uint32_t smem_u32(const void* p) {
    uint32_t a;
    asm("{ .reg .u64 t; cvta.to.shared.u64 t, %1; cvt.u32.u64 %0, t; }" : "=r"(a) : "l"(p));
    return a;
}

#define LDMX4(r, addr) \
    asm volatile("ldmatrix.sync.aligned.m8n8.x4.shared.b16 {%0,%1,%2,%3}, [%4];" \
        : "=r"((r)[0]), "=r"((r)[1]), "=r"((r)[2]), "=r"((r)[3]) : "r"(addr))

__device__ __forceinline__ void mma16816(float* c, const uint32_t* a, const uint32_t* b) {
    asm volatile(
        "mma.sync.aligned.m16n8k16.row.col.f32.f16.f16.f32 "
        "{%0,%1,%2,%3}, {%4,%5,%6,%7}, {%8,%9}, {%0,%1,%2,%3};\n"
        : "+f"(c[0]), "+f"(c[1]), "+f"(c[2]), "+f"(c[3])
        : "r"(a[0]), "r"(a[1]), "r"(a[2]), "r"(a[3]), "r"(b[0]), "r"(b[1]));
}

#define CP_ASYNC16(dst, src, sz) \
    asm volatile("cp.async.cg.shared.global [%0], [%1], 16, %2;" \
        :: "r"(dst), "l"(src), "r"(sz))
#define CP_COMMIT() asm volatile("cp.async.commit_group;" ::: "memory")
#define CP_WAIT0()  asm volatile("cp.async.wait_group 0;" ::: "memory")

// ---------------- GEMM body: CTA 128x128, BK=64, 2-stage cp.async -------------------
// C[M,N] = A[M,K] @ W[K,N] + bias.  A fp16 [M,K]; W fp16 [N,K].  fp32 accumulate.
// 8 warps (4m x 2n), warp tile 32x64 (2 m16 x 8 n8).
// Rows padded to 144 B in smem (conflict-free ldmatrix: 144/16=9, odd multiplier).
// bias col<bias_split -> bias[col], else bias2[col-split].
// outmode 0: fp32 out (opt relu); outmode 1: fp16 out (opt relu).
__device__ __forceinline__ void gemm_body(
    const __half* __restrict__ A, const __half* __restrict__ B,
    const float* __restrict__ bias, const float* __restrict__ bias2, int bias_split,
    float* __restrict__ Cf, __half* __restrict__ Ch,
    int Mr, int K, int N, int relu, int outmode, int row0, int col0, char* smem)
{
    const int ASZ = 128 * 144;         // 18432 B
    const int STG = 2 * ASZ;           // 36864 B per stage (A + B)

    const int tid  = threadIdx.x;
    const int lane = tid & 31;
    const int warp = tid >> 5;
    const int wm   = warp & 3;          // 0..3 (32 rows each)
    const int wn   = warp >> 2;         // 0..1 (64 cols each)

    const uint32_t smem_base = smem_u32(smem);

    const int rowb = tid >> 3;            // 0..31 (rows rowb + 32r)
    const int seg  = tid & 7;             // 16B segment within 128B row

    float acc[2][8][4];
    #pragma unroll
    for (int i = 0; i < 2; i++)
        #pragma unroll
        for (int j = 0; j < 8; j++)
            #pragma unroll
            for (int k = 0; k < 4; k++) acc[i][j][k] = 0.f;

    const int nch = K >> 6;   // BK=64; K multiple of 64 (256 or 1024)

    auto load_chunk = [&](int ch, int stage) {
        const int kb = ch << 6;
        const uint32_t sb = smem_base + stage * STG;
        #pragma unroll
        for (int r = 0; r < 4; r++) {
            const int rr = rowb + r * 32;
            // A row (guarded)
            {
                const int ok = (row0 + rr < Mr) ? 16 : 0;
                const size_t gg = (size_t)(row0 + rr) * K + kb + seg * 8;
                CP_ASYNC16(sb + rr * 144 + seg * 16, A + gg, ok);
            }
            // B row
            {
                const size_t gg = (size_t)(col0 + rr) * K + kb + seg * 8;
                CP_ASYNC16(sb + ASZ + rr * 144 + seg * 16, B + gg, 16);
            }
        }
    };

    load_chunk(0, 0);
    CP_COMMIT();

    int stage = 0;
    for (int ch = 0; ch < nch; ch++) {
        CP_WAIT0();
        __syncthreads();
        if (ch + 1 < nch) {
            load_chunk(ch + 1, stage ^ 1);
            CP_COMMIT();
        }
        const uint32_t sb = smem_base + stage * STG;

        #pragma unroll
        for (int ks = 0; ks < 4; ks++) {
            const int k0 = ks << 4;
            uint32_t af[2][4];
            #pragma unroll
            for (int mt = 0; mt < 2; mt++) {
                const int arow = wm * 32 + mt * 16 + (lane & 15);
                const int acol = k0 + ((lane >> 4) << 3);
                LDMX4(af[mt], sb + arow * 144 + acol * 2);
            }
            #pragma unroll
            for (int np = 0; np < 4; np++) {
                const int tr = wn * 64 + np * 16 + ((lane >> 4) << 3) + (lane & 7);
                const int tc = k0 + (((lane >> 3) & 1) << 3);
                uint32_t t[4];
                LDMX4(t, sb + ASZ + tr * 144 + tc * 2);
                uint32_t b0[2] = { t[0], t[1] };
                uint32_t b1[2] = { t[2], t[3] };
                #pragma unroll
                for (int mt = 0; mt < 2; mt++) {
                    mma16816(acc[mt][np * 2 + 0], af[mt], b0);
                    mma16816(acc[mt][np * 2 + 1], af[mt], b1);
                }
            }
        }
        stage ^= 1;
    }

    // epilogue
    const int g  = lane >> 2;
    const int tg = lane & 3;
    #pragma unroll
    for (int mt = 0; mt < 2; mt++) {
        #pragma unroll
        for (int nt = 0; nt < 8; nt++) {
            const int col = col0 + wn * 64 + nt * 8 + tg * 2;
            float b0, b1;
            if (col < bias_split) {
                b0 = __ldg(bias + col);
                b1 = __ldg(bias + col + 1);
            } else {
                b0 = __ldg(bias2 + col - bias_split);
                b1 = __ldg(bias2 + col - bias_split + 1);
            }
            #pragma unroll
            for (int half_i = 0; half_i < 2; half_i++) {
                const int row = row0 + wm * 32 + mt * 16 + g + half_i * 8;
                if (row < Mr) {
                    float v0 = acc[mt][nt][half_i * 2 + 0] + b0;
                    float v1 = acc[mt][nt][half_i * 2 + 1] + b1;
                    if (relu) { v0 = fmaxf(v0, 0.f); v1 = fmaxf(v1, 0.f); }
                    if (outmode == 0) {
                        *reinterpret_cast<float2*>(Cf + (size_t)row * N + col) = make_float2(v0, v1);
                    } else {
                        *reinterpret_cast<__half2*>(Ch + (size_t)row * N + col) =
                            __halves2half2(__float2half(v0), __float2half(v1));
                    }
                }
            }
        }
    }
}

template<bool RELU, int OUTMODE>
__global__ __launch_bounds__(256, 2)
void mma_gemm(const __half* __restrict__ A, const __half* __restrict__ B,
              const float* __restrict__ bias, const float* __restrict__ bias2, int bias_split,
              float* __restrict__ Cf, __half* __restrict__ Ch,
              int Mr, int K, int N)
{
    extern __shared__ char smem[];
    gemm_body(A, B, bias, bias2, bias_split, Cf, Ch, Mr, K, N,
              RELU ? 1 : 0, OUTMODE, blockIdx.x * 128, blockIdx.y * 128, smem);
}

// Dual GEMM: y < ysplit -> GEMM1 (fp16 out), else GEMM2 (fp32 out, split bias).
__global__ __launch_bounds__(256, 2)
void dual_gemm(const __half* __restrict__ A1, const __half* __restrict__ B1,
               const float* __restrict__ bias1, __half* __restrict__ Ch1, int N1, int ysplit,
               const __half* __restrict__ A2, const __half* __restrict__ B2,
               const float* __restrict__ bias2a, const float* __restrict__ bias2b,
               float* __restrict__ Cf2, int N2,
               int Mr, int K)
{
    extern __shared__ char smem[];
    const int y = blockIdx.y;
    if (y < ysplit) {
        gemm_body(A1, B1, bias1, bias1, N1, nullptr, Ch1, Mr, K, N1,
                  0, 1, blockIdx.x * 128, y * 128, smem);
    } else {
        gemm_body(A2, B2, bias2a, bias2b, 256, Cf2, nullptr, Mr, K, N2,
                  0, 0, blockIdx.x * 128, (y - ysplit) * 128, smem);
    }
}

// ---------------- weight prep: ALL weight types + layers, one launch ----------------
__global__ void wprep_all_kernel(const float* __restrict__ vp, const float* __restrict__ so,
                                 const float* __restrict__ aw, const float* __restrict__ op,
                                 const float* __restrict__ f1, const float* __restrict__ f2,
                                 __half* __restrict__ dst)
{
    int idx = blockIdx.x * blockDim.x + threadIdx.x;
    if (idx >= NLAYERS_C * LW_STRIDE) return;
    int l = idx / LW_STRIDE;
    int r = idx - l * LW_STRIDE;
    const float* W;
    int K, N, r0;
    if (r < 131072) {
        if (r < 65536) { W = vp; K = 256; N = 256; r0 = r; }
        else           { W = so; K = 256; N = 256; r0 = r - 65536; }
    } else if (r < 229376) {
        if (r < 163840) { W = aw; K = 256; N = 128; r0 = r - 131072; }
        else            { W = op; K = 256; N = 256; r0 = r - 163840; }
    } else {
        if (r < 491520) { W = f1; K = 256;  N = 1024; r0 = r - 229376; }
        else            { W = f2; K = 1024; N = 256;  r0 = r - 491520; }
    }
    int n = r0 / K, k = r0 - n * K;
    dst[idx] = __float2half(__ldg(W + (size_t)l * K * N + (size_t)k * N + n));
}

// ---------------- flatten: (B,D,H,W) -> (B,L,D); emits src fp16 + q fp16 -----------
__global__ void flatten_kernel(const float* __restrict__ s0, const float* __restrict__ s1,
                               const float* __restrict__ s2, const float* __restrict__ s3,
                               const float* __restrict__ p0, const float* __restrict__ p1,
                               const float* __restrict__ p2, const float* __restrict__ p3,
                               const float* __restrict__ lvl_emb)
{
    long long idx = (long long)blockIdx.x * blockDim.x + threadIdx.x;
    const long long tot = (long long)MROWS * DMODEL;
    if (idx >= tot) return;
    int d = (int)(idx & 255);
    int m = (int)(idx >> 8);
    int b = m / L_TOT;
    int n = m - b * L_TOT;
    int lvl, hw, HW;
    const float *sp, *pp;
    if (n < 10000)      { lvl = 0; hw = n;         HW = 10000; sp = s0; pp = p0; }
    else if (n < 12500) { lvl = 1; hw = n - 10000; HW = 2500;  sp = s1; pp = p1; }
    else if (n < 13125) { lvl = 2; hw = n - 12500; HW = 625;   sp = s2; pp = p2; }
    else                { lvl = 3; hw = n - 13125; HW = 169;   sp = s3; pp = p3; }
    size_t sidx = ((size_t)b * DMODEL + d) * HW + hw;
    float sv = __ldg(sp + sidx);
    float pv = __ldg(pp + sidx) + __ldg(lvl_emb + lvl * DMODEL + d);
    g_src[idx] = sv;
    g_pos[idx] = pv;
    g_src_h[idx] = __float2half(sv);
    g_q_h[idx]   = __float2half(sv + pv);
}

// ---------------- deformable attention sampling (one warp per (b,q,head)) -----------
__global__ void deform_kernel(const __half* __restrict__ value,
                              const float* __restrict__ offaw,
                              __half* __restrict__ out_h)
{
    int gw = (int)((blockIdx.x * blockDim.x + threadIdx.x) >> 5);
    if (gw >= MROWS * NHEADS) return;
    int lane = threadIdx.x & 31;
    int h = gw & 7;
    int m = gw >> 3;
    int b = m / L_TOT;
    int q = m - b * L_TOT;

    float ref_x, ref_y;
    {
        int idx, Wl, Hl;
        if (q < 10000)      { idx = q;         Wl = 100; Hl = 100; }
        else if (q < 12500) { idx = q - 10000; Wl = 50;  Hl = 50;  }
        else if (q < 13125) { idx = q - 12500; Wl = 25;  Hl = 25;  }
        else                { idx = q - 13125; Wl = 13;  Hl = 13;  }
        int yy = idx / Wl, xx = idx - yy * Wl;
        ref_x = (xx + 0.5f) / (float)Wl;
        ref_y = (yy + 0.5f) / (float)Hl;
    }

    const float* awp = offaw + (size_t)m * 384 + 256 + h * 16;
    float e[16];
    float mx = -1e30f;
    #pragma unroll
    for (int i = 0; i < 16; i++) { e[i] = __ldg(awp + i); mx = fmaxf(mx, e[i]); }
    float ssum = 0.f;
    #pragma unroll
    for (int i = 0; i < 16; i++) { e[i] = __expf(e[i] - mx); ssum += e[i]; }
    float inv = 1.f / ssum;

    const float*  offp  = offaw + (size_t)m * 384 + h * 32;
    const __half* vbase = value + (size_t)b * L_TOT * 256 + h * 32 + lane;

    const int Ws[4]     = {100, 50, 25, 13};
    const int Hs[4]     = {100, 50, 25, 13};
    const int starts[4] = {0, 10000, 12500, 13125};

    float acc = 0.f;
    #pragma unroll
    for (int l = 0; l < 4; l++) {
        const int   Wl = Ws[l], Hl = Hs[l], st = starts[l];
        const float fW = (float)Wl, fH = (float)Hl;
        #pragma unroll
        for (int p = 0; p < 4; p++) {
            float ox = __ldg(offp + l * 8 + p * 2);
            float oy = __ldg(offp + l * 8 + p * 2 + 1);
            float px = ref_x * fW + ox - 0.5f;
            float py = ref_y * fH + oy - 0.5f;
            float x0f = floorf(px), y0f = floorf(py);
            float wx1 = px - x0f, wy1 = py - y0f;
            int x0 = (int)x0f, y0 = (int)y0f;
            float wgt = e[l * 4 + p] * inv;
            #pragma unroll
            for (int t = 0; t < 4; t++) {
                int xi = x0 + (t & 1);
                int yi = y0 + (t >> 1);
                float w = ((t & 1) ? wx1 : 1.f - wx1) * ((t >> 1) ? wy1 : 1.f - wy1);
                if (xi >= 0 && xi < Wl && yi >= 0 && yi < Hl && w != 0.f) {
                    acc = fmaf(wgt * w,
                               __half2float(__ldg(vbase + (size_t)(st + yi * Wl + xi) * 256)),
                               acc);
                }
            }
        }
    }
    out_h[(size_t)m * 256 + h * 32 + lane] = __float2half(acc);
}

// ---------------- fused residual add + LayerNorm (one warp per row) -----------------
__global__ void add_ln_kernel(const float* __restrict__ X, const float* __restrict__ R,
                              const float* __restrict__ w, const float* __restrict__ b,
                              const float* __restrict__ pos,
                              float* __restrict__ out,
                              __half* __restrict__ out_h,
                              __half* __restrict__ q_h)
{
    int row = (int)((blockIdx.x * blockDim.x + threadIdx.x) >> 5);
    if (row >= MROWS) return;
    int lane = threadIdx.x & 31;
    const float* x = X + (size_t)row * DMODEL;
    const float* r = R + (size_t)row * DMODEL;
    float v[8];
    float s = 0.f;
    #pragma unroll
    for (int j = 0; j < 8; j++) {
        int c = lane + j * 32;
        v[j] = x[c] + r[c];
        s += v[j];
    }
    #pragma unroll
    for (int o = 16; o > 0; o >>= 1) s += __shfl_xor_sync(0xFFFFFFFFu, s, o);
    float mean = s * (1.f / 256.f);
    float qv = 0.f;
    #pragma unroll
    for (int j = 0; j < 8; j++) { float d = v[j] - mean; qv += d * d; }
    #pragma unroll
    for (int o = 16; o > 0; o >>= 1) qv += __shfl_xor_sync(0xFFFFFFFFu, qv, o);
    float invs = rsqrtf(qv * (1.f / 256.f) + 1e-5f);
    #pragma unroll
    for (int j = 0; j < 8; j++) {
        int c = lane + j * 32;
        float o = (v[j] - mean) * invs * __ldg(w + c) + __ldg(b + c);
        size_t oi = (size_t)row * DMODEL + c;
        out[oi] = o;
        out_h[oi] = __float2half(o);
        if (pos != nullptr) q_h[oi] = __float2half(o + __ldg(pos + oi));
    }
}

// ---------------- output write: src then level_start_index (as floats) -------------
__global__ void write_out_kernel(float* __restrict__ out, int n)
{
    long long i = (long long)blockIdx.x * blockDim.x + threadIdx.x;
    if (i >= n) return;
    const long long tot = (long long)MROWS * DMODEL;
    if (i < tot) {
        out[i] = g_src[i];
    } else {
        int k = (int)(i - tot);
        float st;
        switch (k) {
            case 0: st = 0.f;      break;
            case 1: st = 10000.f;  break;
            case 2: st = 12500.f;  break;
            case 3: st = 13125.f;  break;
            default: st = 0.f;     break;
        }
        out[i] = st;
    }
}

// ---------------- host launch ----------------
extern "C" void kernel_launch(void* const* d_in, const int* in_sizes, int n_in,
                              void* d_out, int out_size)
{
    // setup_inputs() dict order is INTERLEAVED: src0, pos0, src1, pos1, ...
    const float* s0 = (const float*)d_in[0];
    const float* p0 = (const float*)d_in[1];
    const float* s1 = (const float*)d_in[2];
    const float* p1 = (const float*)d_in[3];
    const float* s2 = (const float*)d_in[4];
    const float* p2 = (const float*)d_in[5];
    const float* s3 = (const float*)d_in[6];
    const float* p3 = (const float*)d_in[7];
    const float* lvl_emb = (const float*)d_in[8];
    const float* so_w = (const float*)d_in[9];
    const float* so_b = (const float*)d_in[10];
    const float* aw_w = (const float*)d_in[11];
    const float* aw_b = (const float*)d_in[12];
    const float* vp_w = (const float*)d_in[13];
    const float* vp_b = (const float*)d_in[14];
    const float* op_w = (const float*)d_in[15];
    const float* op_b = (const float*)d_in[16];
    const float* n1_w = (const float*)d_in[17];
    const float* n1_b = (const float*)d_in[18];
    const float* f1_w = (const float*)d_in[19];
    const float* f1_b = (const float*)d_in[20];
    const float* f2_w = (const float*)d_in[21];
    const float* f2_b = (const float*)d_in[22];
    const float* n2_w = (const float*)d_in[23];
    const float* n2_b = (const float*)d_in[24];

    float *pg_src, *pg_pos, *pg_offaw, *pg_tmp;
    __half *pg_val_h, *pg_src_h, *pg_q_h, *pg_attn_h, *pg_h_h, *pg_w;
    cudaGetSymbolAddress((void**)&pg_src,   g_src);
    cudaGetSymbolAddress((void**)&pg_pos,   g_pos);
    cudaGetSymbolAddress((void**)&pg_offaw, g_offaw);
    cudaGetSymbolAddress((void**)&pg_tmp,   g_tmp);
    cudaGetSymbolAddress((void**)&pg_val_h, g_val_h);
    cudaGetSymbolAddress((void**)&pg_src_h, g_src_h);
    cudaGetSymbolAddress((void**)&pg_q_h,   g_q_h);
    cudaGetSymbolAddress((void**)&pg_attn_h, g_attn_h);
    cudaGetSymbolAddress((void**)&pg_h_h,   g_h_h);
    cudaGetSymbolAddress((void**)&pg_w,     g_w);

    // dynamic smem: 2 stages x 36864 B
    const int GEMM_SMEM = 73728;
    cudaFuncSetAttribute(mma_gemm<false, 0>, cudaFuncAttributeMaxDynamicSharedMemorySize, GEMM_SMEM);
    cudaFuncSetAttribute(mma_gemm<false, 1>, cudaFuncAttributeMaxDynamicSharedMemorySize, GEMM_SMEM);
    cudaFuncSetAttribute(mma_gemm<true, 1>,  cudaFuncAttributeMaxDynamicSharedMemorySize, GEMM_SMEM);
    cudaFuncSetAttribute(dual_gemm,          cudaFuncAttributeMaxDynamicSharedMemorySize, GEMM_SMEM);

    const long long totElem = (long long)MROWS * DMODEL;
    const int ew_grid = (int)((totElem + 255) / 256);

    wprep_all_kernel<<<(NLAYERS_C * LW_STRIDE + 255) / 256, 256>>>(
        vp_w, so_w, aw_w, op_w, f1_w, f2_w, pg_w);
    flatten_kernel<<<ew_grid, 256>>>(s0, s1, s2, s3, p0, p1, p2, p3, lvl_emb);

    const int mblk = (MROWS + 127) / 128;   // 416
    const dim3 blk(256);
    const int ln_grid = (MROWS * 32 + 255) / 256;
    const int deform_grid = (MROWS * NHEADS * 32 + 255) / 256;

    for (int i = 0; i < NLAYERS_C; i++) {
        size_t wb = (size_t)i * LW_STRIDE;
        const __half* vp_h = pg_w + wb + OFF_VP;
        const __half* sa_h = pg_w + wb + OFF_SOAW;
        const __half* op_h = pg_w + wb + OFF_OP;
        const __half* f1_h = pg_w + wb + OFF_F1;
        const __half* f2_h = pg_w + wb + OFF_F2;

        // fused launch: value = src @ vp_w (fp16 out) || offaw = q @ soaw_w (fp32 out)
        dual_gemm<<<dim3(mblk, 5), blk, GEMM_SMEM>>>(
            pg_src_h, vp_h, vp_b + (size_t)i * 256, pg_val_h, 256, 2,
            pg_q_h, sa_h, so_b + (size_t)i * 256, aw_b + (size_t)i * 128,
            pg_offaw, 384, MROWS, 256);
        // deformable sampling -> attn fp16
        deform_kernel<<<deform_grid, 256>>>(pg_val_h, pg_offaw, pg_attn_h);
        // output proj
        mma_gemm<false, 0><<<dim3(mblk, 2), blk, GEMM_SMEM>>>(
            pg_attn_h, op_h, op_b + (size_t)i * 256, op_b + (size_t)i * 256, 256,
            pg_tmp, nullptr, MROWS, 256, 256);
        // src = LN(src + attn_proj)
        add_ln_kernel<<<ln_grid, 256>>>(pg_src, pg_tmp,
                                        n1_w + (size_t)i * DMODEL, n1_b + (size_t)i * DMODEL,
                                        nullptr, pg_src, pg_src_h, nullptr);
        // h = relu(src @ f1_w + f1_b)  (fp16 out)
        mma_gemm<true, 1><<<dim3(mblk, 8), blk, GEMM_SMEM>>>(
            pg_src_h, f1_h, f1_b + (size_t)i * DFFN, f1_b + (size_t)i * DFFN, DFFN,
            nullptr, pg_h_h, MROWS, 256, DFFN);
        // tmp = h @ f2_w + f2_b
        mma_gemm<false, 0><<<dim3(mblk, 2), blk, GEMM_SMEM>>>(
            pg_h_h, f2_h, f2_b + (size_t)i * 256, f2_b + (size_t)i * 256, 256,
            pg_tmp, nullptr, MROWS, 1024, 256);
        // src = LN(src + ffn), also emit q fp16 for next layer
        add_ln_kernel<<<ln_grid, 256>>>(pg_src, pg_tmp,
                                        n2_w + (size_t)i * DMODEL, n2_b + (size_t)i * DMODEL,
                                        pg_pos, pg_src, pg_src_h, pg_q_h);
    }

    write_out_kernel<<<(out_size + 255) / 256, 256>>>((float*)d_out, out_size);
}

// round 13
// speedup vs baseline: 2.4064x; 1.5158x over previous
#include <cuda_runtime.h>
#include <cuda_fp16.h>
#include <cstdint>
#include <math.h>

// ---------------- problem constants ----------------
#define L_TOT   13294          // 10000 + 2500 + 625 + 169
#define BATCH   4
#define MROWS   (BATCH * L_TOT)   // 53176
#define DMODEL  256
#define DFFN    1024
#define NLAYERS_C 6
#define NHEADS  8

// weight layout offsets (elements) within one layer block
#define OFF_VP    0
#define OFF_SOAW  65536          // combined so(256) + aw(128) rows => [384,256]
#define OFF_OP    163840
#define OFF_F1    229376
#define OFF_F2    491520
#define LW_STRIDE 753664

// ---------------- device scratch (static, allowed) ----------------
__device__ __align__(16) float g_src  [MROWS * DMODEL];
__device__ __align__(16) float g_pos  [MROWS * DMODEL];
__device__ __align__(16) float g_offaw[MROWS * 384];
__device__ __align__(16) float g_tmp  [MROWS * DMODEL];

__device__ __align__(16) __half g_val_h [MROWS * DMODEL];
__device__ __align__(16) __half g_src_h [MROWS * DMODEL];
__device__ __align__(16) __half g_q_h   [MROWS * DMODEL];
__device__ __align__(16) __half g_attn_h[MROWS * DMODEL];
__device__ __align__(16) __half g_h_h   [(size_t)MROWS * DFFN];
__device__ __align__(16) __half g_w     [NLAYERS_C * LW_STRIDE];

// ---------------- helpers ----------------
__device__ __forceinline__ uint32_t smem_u32(const void* p) {
    uint32_t a;
    asm("{ .reg .u64 t; cvta.to.shared.u64 t, %1; cvt.u32.u64 %0, t; }" : "=r"(a) : "l"(p));
    return a;
}

#define LDMX4(r, addr) \
    asm volatile("ldmatrix.sync.aligned.m8n8.x4.shared.b16 {%0,%1,%2,%3}, [%4];" \
        : "=r"((r)[0]), "=r"((r)[1]), "=r"((r)[2]), "=r"((r)[3]) : "r"(addr))

__device__ __forceinline__ void mma16816(float* c, const uint32_t* a, const uint32_t* b) {
    asm volatile(
        "mma.sync.aligned.m16n8k16.row.col.f32.f16.f16.f32 "
        "{%0,%1,%2,%3}, {%4,%5,%6,%7}, {%8,%9}, {%0,%1,%2,%3};\n"
        : "+f"(c[0]), "+f"(c[1]), "+f"(c[2]), "+f"(c[3])
        : "r"(a[0]), "r"(a[1]), "r"(a[2]), "r"(a[3]), "r"(b[0]), "r"(b[1]));
}

#define CP_ASYNC16(dst, src, sz) \
    asm volatile("cp.async.cg.shared.global [%0], [%1], 16, %2;" \
        :: "r"(dst), "l"(src), "r"(sz))
#define CP_COMMIT() asm volatile("cp.async.commit_group;" ::: "memory")
#define CP_WAIT0()  asm volatile("cp.async.wait_group 0;" ::: "memory")

// ---------------- GEMM body: CTA 128x128, BK=64, 2-stage cp.async -------------------
__device__ __forceinline__ void gemm_body(
    const __half* __restrict__ A, const __half* __restrict__ B,
    const float* __restrict__ bias, const float* __restrict__ bias2, int bias_split,
    float* __restrict__ Cf, __half* __restrict__ Ch,
    int Mr, int K, int N, int relu, int outmode, int row0, int col0, char* smem)
{
    const int ASZ = 128 * 144;         // 18432 B
    const int STG = 2 * ASZ;           // 36864 B per stage (A + B)

    const int tid  = threadIdx.x;
    const int lane = tid & 31;
    const int warp = tid >> 5;
    const int wm   = warp & 3;          // 0..3 (32 rows each)
    const int wn   = warp >> 2;         // 0..1 (64 cols each)

    const uint32_t smem_base = smem_u32(smem);

    const int rowb = tid >> 3;            // 0..31
    const int seg  = tid & 7;             // 16B segment

    float acc[2][8][4];
    #pragma unroll
    for (int i = 0; i < 2; i++)
        #pragma unroll
        for (int j = 0; j < 8; j++)
            #pragma unroll
            for (int k = 0; k < 4; k++) acc[i][j][k] = 0.f;

    const int nch = K >> 6;

    auto load_chunk = [&](int ch, int stage) {
        const int kb = ch << 6;
        const uint32_t sb = smem_base + stage * STG;
        #pragma unroll
        for (int r = 0; r < 4; r++) {
            const int rr = rowb + r * 32;
            {
                const int ok = (row0 + rr < Mr) ? 16 : 0;
                const size_t gg = (size_t)(row0 + rr) * K + kb + seg * 8;
                CP_ASYNC16(sb + rr * 144 + seg * 16, A + gg, ok);
            }
            {
                const size_t gg = (size_t)(col0 + rr) * K + kb + seg * 8;
                CP_ASYNC16(sb + ASZ + rr * 144 + seg * 16, B + gg, 16);
            }
        }
    };

    load_chunk(0, 0);
    CP_COMMIT();

    int stage = 0;
    for (int ch = 0; ch < nch; ch++) {
        CP_WAIT0();
        __syncthreads();
        if (ch + 1 < nch) {
            load_chunk(ch + 1, stage ^ 1);
            CP_COMMIT();
        }
        const uint32_t sb = smem_base + stage * STG;

        #pragma unroll
        for (int ks = 0; ks < 4; ks++) {
            const int k0 = ks << 4;
            uint32_t af[2][4];
            #pragma unroll
            for (int mt = 0; mt < 2; mt++) {
                const int arow = wm * 32 + mt * 16 + (lane & 15);
                const int acol = k0 + ((lane >> 4) << 3);
                LDMX4(af[mt], sb + arow * 144 + acol * 2);
            }
            #pragma unroll
            for (int np = 0; np < 4; np++) {
                const int tr = wn * 64 + np * 16 + ((lane >> 4) << 3) + (lane & 7);
                const int tc = k0 + (((lane >> 3) & 1) << 3);
                uint32_t t[4];
                LDMX4(t, sb + ASZ + tr * 144 + tc * 2);
                uint32_t b0[2] = { t[0], t[1] };
                uint32_t b1[2] = { t[2], t[3] };
                #pragma unroll
                for (int mt = 0; mt < 2; mt++) {
                    mma16816(acc[mt][np * 2 + 0], af[mt], b0);
                    mma16816(acc[mt][np * 2 + 1], af[mt], b1);
                }
            }
        }
        stage ^= 1;
    }

    // epilogue
    const int g  = lane >> 2;
    const int tg = lane & 3;
    #pragma unroll
    for (int mt = 0; mt < 2; mt++) {
        #pragma unroll
        for (int nt = 0; nt < 8; nt++) {
            const int col = col0 + wn * 64 + nt * 8 + tg * 2;
            float b0, b1;
            if (col < bias_split) {
                b0 = __ldg(bias + col);
                b1 = __ldg(bias + col + 1);
            } else {
                b0 = __ldg(bias2 + col - bias_split);
                b1 = __ldg(bias2 + col - bias_split + 1);
            }
            #pragma unroll
            for (int half_i = 0; half_i < 2; half_i++) {
                const int row = row0 + wm * 32 + mt * 16 + g + half_i * 8;
                if (row < Mr) {
                    float v0 = acc[mt][nt][half_i * 2 + 0] + b0;
                    float v1 = acc[mt][nt][half_i * 2 + 1] + b1;
                    if (relu) { v0 = fmaxf(v0, 0.f); v1 = fmaxf(v1, 0.f); }
                    if (outmode == 0) {
                        *reinterpret_cast<float2*>(Cf + (size_t)row * N + col) = make_float2(v0, v1);
                    } else {
                        *reinterpret_cast<__half2*>(Ch + (size_t)row * N + col) =
                            __halves2half2(__float2half(v0), __float2half(v1));
                    }
                }
            }
        }
    }
}

template<bool RELU, int OUTMODE>
__global__ __launch_bounds__(256, 2)
void mma_gemm(const __half* __restrict__ A, const __half* __restrict__ B,
              const float* __restrict__ bias, const float* __restrict__ bias2, int bias_split,
              float* __restrict__ Cf, __half* __restrict__ Ch,
              int Mr, int K, int N)
{
    extern __shared__ char smem[];
    gemm_body(A, B, bias, bias2, bias_split, Cf, Ch, Mr, K, N,
              RELU ? 1 : 0, OUTMODE, blockIdx.x * 128, blockIdx.y * 128, smem);
}

// Dual GEMM: y < ysplit -> GEMM1 (fp16 out), else GEMM2 (fp32 out, split bias).
__global__ __launch_bounds__(256, 2)
void dual_gemm(const __half* __restrict__ A1, const __half* __restrict__ B1,
               const float* __restrict__ bias1, __half* __restrict__ Ch1, int N1, int ysplit,
               const __half* __restrict__ A2, const __half* __restrict__ B2,
               const float* __restrict__ bias2a, const float* __restrict__ bias2b,
               float* __restrict__ Cf2, int N2,
               int Mr, int K)
{
    extern __shared__ char smem[];
    const int y = blockIdx.y;
    if (y < ysplit) {
        gemm_body(A1, B1, bias1, bias1, N1, nullptr, Ch1, Mr, K, N1,
                  0, 1, blockIdx.x * 128, y * 128, smem);
    } else {
        gemm_body(A2, B2, bias2a, bias2b, 256, Cf2, nullptr, Mr, K, N2,
                  0, 0, blockIdx.x * 128, (y - ysplit) * 128, smem);
    }
}

// ---------------- weight prep: ALL weight types + layers, one launch ----------------
__global__ void wprep_all_kernel(const float* __restrict__ vp, const float* __restrict__ so,
                                 const float* __restrict__ aw, const float* __restrict__ op,
                                 const float* __restrict__ f1, const float* __restrict__ f2,
                                 __half* __restrict__ dst)
{
    int idx = blockIdx.x * blockDim.x + threadIdx.x;
    if (idx >= NLAYERS_C * LW_STRIDE) return;
    int l = idx / LW_STRIDE;
    int r = idx - l * LW_STRIDE;
    const float* W;
    int K, N, r0;
    if (r < 131072) {
        if (r < 65536) { W = vp; K = 256; N = 256; r0 = r; }
        else           { W = so; K = 256; N = 256; r0 = r - 65536; }
    } else if (r < 229376) {
        if (r < 163840) { W = aw; K = 256; N = 128; r0 = r - 131072; }
        else            { W = op; K = 256; N = 256; r0 = r - 163840; }
    } else {
        if (r < 491520) { W = f1; K = 256;  N = 1024; r0 = r - 229376; }
        else            { W = f2; K = 1024; N = 256;  r0 = r - 491520; }
    }
    int n = r0 / K, k = r0 - n * K;
    dst[idx] = __float2half(__ldg(W + (size_t)l * K * N + (size_t)k * N + n));
}

// ---------------- flatten: (B,D,H,W) -> (B,L,D); emits src fp16 + q fp16 -----------
__global__ void flatten_kernel(const float* __restrict__ s0, const float* __restrict__ s1,
                               const float* __restrict__ s2, const float* __restrict__ s3,
                               const float* __restrict__ p0, const float* __restrict__ p1,
                               const float* __restrict__ p2, const float* __restrict__ p3,
                               const float* __restrict__ lvl_emb)
{
    long long idx = (long long)blockIdx.x * blockDim.x + threadIdx.x;
    const long long tot = (long long)MROWS * DMODEL;
    if (idx >= tot) return;
    int d = (int)(idx & 255);
    int m = (int)(idx >> 8);
    int b = m / L_TOT;
    int n = m - b * L_TOT;
    int lvl, hw, HW;
    const float *sp, *pp;
    if (n < 10000)      { lvl = 0; hw = n;         HW = 10000; sp = s0; pp = p0; }
    else if (n < 12500) { lvl = 1; hw = n - 10000; HW = 2500;  sp = s1; pp = p1; }
    else if (n < 13125) { lvl = 2; hw = n - 12500; HW = 625;   sp = s2; pp = p2; }
    else                { lvl = 3; hw = n - 13125; HW = 169;   sp = s3; pp = p3; }
    size_t sidx = ((size_t)b * DMODEL + d) * HW + hw;
    float sv = __ldg(sp + sidx);
    float pv = __ldg(pp + sidx) + __ldg(lvl_emb + lvl * DMODEL + d);
    g_src[idx] = sv;
    g_pos[idx] = pv;
    g_src_h[idx] = __float2half(sv);
    g_q_h[idx]   = __float2half(sv + pv);
}

// ---------------- deformable attention, two-phase (one warp per (b,q,head)) ---------
// Phase A: lanes compute the 16 sample points' clamped indices + folded weights once.
// Phase B: half-warp 0 = even points, half-warp 1 = odd points; lane gathers half2.
__global__ __launch_bounds__(256)
void deform_kernel(const __half* __restrict__ value,
                   const float* __restrict__ offaw,
                   __half* __restrict__ out_h)
{
    __shared__ int   s_idx[8][16][4];
    __shared__ float s_w  [8][16][4];

    int gw = (int)((blockIdx.x * blockDim.x + threadIdx.x) >> 5);
    if (gw >= MROWS * NHEADS) return;
    const int lane = threadIdx.x & 31;
    const int wip  = (threadIdx.x >> 5) & 7;   // warp in block
    const int h = gw & 7;
    const int m = gw >> 3;
    const int b = m / L_TOT;
    const int q = m - b * L_TOT;

    // ---- Phase A: point data (computed by both half-warps for pl = lane&15; lanes<16 store)
    {
        const int pl  = lane & 15;       // point id 0..15
        const int lvl = pl >> 2;         // levels interleave as l*4+p ; pl = l*4+p
        // reference point
        float ref_x, ref_y;
        {
            int idx, Wl0, Hl0;
            if (q < 10000)      { idx = q;         Wl0 = 100; Hl0 = 100; }
            else if (q < 12500) { idx = q - 10000; Wl0 = 50;  Hl0 = 50;  }
            else if (q < 13125) { idx = q - 12500; Wl0 = 25;  Hl0 = 25;  }
            else                { idx = q - 13125; Wl0 = 13;  Hl0 = 13;  }
            int yy = idx / Wl0, xx = idx - yy * Wl0;
            ref_x = (xx + 0.5f) / (float)Wl0;
            ref_y = (yy + 0.5f) / (float)Hl0;
        }
        // softmax weight for point pl (16-lane shuffle reduction, replicated in both halves)
        float logit = __ldg(offaw + (size_t)m * 384 + 256 + h * 16 + pl);
        float mx = logit;
        #pragma unroll
        for (int o = 8; o > 0; o >>= 1) mx = fmaxf(mx, __shfl_xor_sync(0xFFFFFFFFu, mx, o));
        float e = __expf(logit - mx);
        float ssum = e;
        #pragma unroll
        for (int o = 8; o > 0; o >>= 1) ssum += __shfl_xor_sync(0xFFFFFFFFu, ssum, o);
        float wgt = e / ssum;

        // offsets: point pl -> offset pair at index 2*pl within head's 32
        float ox = __ldg(offaw + (size_t)m * 384 + h * 32 + pl * 2);
        float oy = __ldg(offaw + (size_t)m * 384 + h * 32 + pl * 2 + 1);

        const int WlA[4] = {100, 50, 25, 13};
        const int stA[4] = {0, 10000, 12500, 13125};
        const int Wl = WlA[lvl], Hl = WlA[lvl], st = stA[lvl];
        const float fW = (float)Wl, fH = (float)Hl;

        float px = ref_x * fW + ox - 0.5f;
        float py = ref_y * fH + oy - 0.5f;
        float x0f = floorf(px), y0f = floorf(py);
        float wx1 = px - x0f, wy1 = py - y0f;
        int x0 = (int)x0f, y0 = (int)y0f;

        if (lane < 16) {
            #pragma unroll
            for (int t = 0; t < 4; t++) {
                int xi = x0 + (t & 1);
                int yi = y0 + (t >> 1);
                bool valid = (xi >= 0) & (xi < Wl) & (yi >= 0) & (yi < Hl);
                int xc = min(max(xi, 0), Wl - 1);
                int yc = min(max(yi, 0), Hl - 1);
                float w = ((t & 1) ? wx1 : 1.f - wx1) * ((t >> 1) ? wy1 : 1.f - wy1)
                          * wgt * (valid ? 1.f : 0.f);
                s_idx[wip][pl][t] = st + yc * Wl + xc;
                s_w  [wip][pl][t] = w;
            }
        }
    }
    __syncwarp();

    // ---- Phase B: gather. grp 0 -> even points, grp 1 -> odd points; half2 channels.
    const int grp = lane >> 4;
    const int c2  = lane & 15;   // half2 channel pair within head
    const __half2* vb = reinterpret_cast<const __half2*>(value + (size_t)b * L_TOT * 256)
                        + h * 16 + c2;
    float2 acc = make_float2(0.f, 0.f);
    #pragma unroll
    for (int pp = 0; pp < 8; pp++) {
        const int pt = pp * 2 + grp;
        #pragma unroll
        for (int t = 0; t < 4; t++) {
            float w  = s_w[wip][pt][t];
            int   ix = s_idx[wip][pt][t];
            __half2 v = __ldg(vb + (size_t)ix * 128);
            float2 vf = __half22float2(v);
            acc.x = fmaf(w, vf.x, acc.x);
            acc.y = fmaf(w, vf.y, acc.y);
        }
    }
    acc.x += __shfl_xor_sync(0xFFFFFFFFu, acc.x, 16);
    acc.y += __shfl_xor_sync(0xFFFFFFFFu, acc.y, 16);
    if (grp == 0) {
        *reinterpret_cast<__half2*>(out_h + (size_t)m * 256 + h * 32 + c2 * 2) =
            __halves2half2(__float2half(acc.x), __float2half(acc.y));
    }
}

// ---------------- fused residual add + LayerNorm (one warp per row) -----------------
__global__ void add_ln_kernel(const float* __restrict__ X, const float* __restrict__ R,
                              const float* __restrict__ w, const float* __restrict__ b,
                              const float* __restrict__ pos,
                              float* __restrict__ out,
                              __half* __restrict__ out_h,
                              __half* __restrict__ q_h)
{
    int row = (int)((blockIdx.x * blockDim.x + threadIdx.x) >> 5);
    if (row >= MROWS) return;
    int lane = threadIdx.x & 31;
    const float* x = X + (size_t)row * DMODEL;
    const float* r = R + (size_t)row * DMODEL;
    float v[8];
    float s = 0.f;
    #pragma unroll
    for (int j = 0; j < 8; j++) {
        int c = lane + j * 32;
        v[j] = x[c] + r[c];
        s += v[j];
    }
    #pragma unroll
    for (int o = 16; o > 0; o >>= 1) s += __shfl_xor_sync(0xFFFFFFFFu, s, o);
    float mean = s * (1.f / 256.f);
    float qv = 0.f;
    #pragma unroll
    for (int j = 0; j < 8; j++) { float d = v[j] - mean; qv += d * d; }
    #pragma unroll
    for (int o = 16; o > 0; o >>= 1) qv += __shfl_xor_sync(0xFFFFFFFFu, qv, o);
    float invs = rsqrtf(qv * (1.f / 256.f) + 1e-5f);
    #pragma unroll
    for (int j = 0; j < 8; j++) {
        int c = lane + j * 32;
        float o = (v[j] - mean) * invs * __ldg(w + c) + __ldg(b + c);
        size_t oi = (size_t)row * DMODEL + c;
        out[oi] = o;
        out_h[oi] = __float2half(o);
        if (pos != nullptr) q_h[oi] = __float2half(o + __ldg(pos + oi));
    }
}

// ---------------- output write: src then level_start_index (as floats) -------------
__global__ void write_out_kernel(float* __restrict__ out, int n)
{
    long long i = (long long)blockIdx.x * blockDim.x + threadIdx.x;
    if (i >= n) return;
    const long long tot = (long long)MROWS * DMODEL;
    if (i < tot) {
        out[i] = g_src[i];
    } else {
        int k = (int)(i - tot);
        float st;
        switch (k) {
            case 0: st = 0.f;      break;
            case 1: st = 10000.f;  break;
            case 2: st = 12500.f;  break;
            case 3: st = 13125.f;  break;
            default: st = 0.f;     break;
        }
        out[i] = st;
    }
}

// ---------------- host launch ----------------
extern "C" void kernel_launch(void* const* d_in, const int* in_sizes, int n_in,
                              void* d_out, int out_size)
{
    // setup_inputs() dict order is INTERLEAVED: src0, pos0, src1, pos1, ...
    const float* s0 = (const float*)d_in[0];
    const float* p0 = (const float*)d_in[1];
    const float* s1 = (const float*)d_in[2];
    const float* p1 = (const float*)d_in[3];
    const float* s2 = (const float*)d_in[4];
    const float* p2 = (const float*)d_in[5];
    const float* s3 = (const float*)d_in[6];
    const float* p3 = (const float*)d_in[7];
    const float* lvl_emb = (const float*)d_in[8];
    const float* so_w = (const float*)d_in[9];
    const float* so_b = (const float*)d_in[10];
    const float* aw_w = (const float*)d_in[11];
    const float* aw_b = (const float*)d_in[12];
    const float* vp_w = (const float*)d_in[13];
    const float* vp_b = (const float*)d_in[14];
    const float* op_w = (const float*)d_in[15];
    const float* op_b = (const float*)d_in[16];
    const float* n1_w = (const float*)d_in[17];
    const float* n1_b = (const float*)d_in[18];
    const float* f1_w = (const float*)d_in[19];
    const float* f1_b = (const float*)d_in[20];
    const float* f2_w = (const float*)d_in[21];
    const float* f2_b = (const float*)d_in[22];
    const float* n2_w = (const float*)d_in[23];
    const float* n2_b = (const float*)d_in[24];

    float *pg_src, *pg_pos, *pg_offaw, *pg_tmp;
    __half *pg_val_h, *pg_src_h, *pg_q_h, *pg_attn_h, *pg_h_h, *pg_w;
    cudaGetSymbolAddress((void**)&pg_src,   g_src);
    cudaGetSymbolAddress((void**)&pg_pos,   g_pos);
    cudaGetSymbolAddress((void**)&pg_offaw, g_offaw);
    cudaGetSymbolAddress((void**)&pg_tmp,   g_tmp);
    cudaGetSymbolAddress((void**)&pg_val_h, g_val_h);
    cudaGetSymbolAddress((void**)&pg_src_h, g_src_h);
    cudaGetSymbolAddress((void**)&pg_q_h,   g_q_h);
    cudaGetSymbolAddress((void**)&pg_attn_h, g_attn_h);
    cudaGetSymbolAddress((void**)&pg_h_h,   g_h_h);
    cudaGetSymbolAddress((void**)&pg_w,     g_w);

    // dynamic smem: 2 stages x 36864 B
    const int GEMM_SMEM = 73728;
    cudaFuncSetAttribute(mma_gemm<false, 0>, cudaFuncAttributeMaxDynamicSharedMemorySize, GEMM_SMEM);
    cudaFuncSetAttribute(mma_gemm<false, 1>, cudaFuncAttributeMaxDynamicSharedMemorySize, GEMM_SMEM);
    cudaFuncSetAttribute(mma_gemm<true, 1>,  cudaFuncAttributeMaxDynamicSharedMemorySize, GEMM_SMEM);
    cudaFuncSetAttribute(dual_gemm,          cudaFuncAttributeMaxDynamicSharedMemorySize, GEMM_SMEM);

    const long long totElem = (long long)MROWS * DMODEL;
    const int ew_grid = (int)((totElem + 255) / 256);

    wprep_all_kernel<<<(NLAYERS_C * LW_STRIDE + 255) / 256, 256>>>(
        vp_w, so_w, aw_w, op_w, f1_w, f2_w, pg_w);
    flatten_kernel<<<ew_grid, 256>>>(s0, s1, s2, s3, p0, p1, p2, p3, lvl_emb);

    const int mblk = (MROWS + 127) / 128;   // 416
    const dim3 blk(256);
    const int ln_grid = (MROWS * 32 + 255) / 256;
    const int deform_grid = (MROWS * NHEADS * 32 + 255) / 256;

    for (int i = 0; i < NLAYERS_C; i++) {
        size_t wb = (size_t)i * LW_STRIDE;
        const __half* vp_h = pg_w + wb + OFF_VP;
        const __half* sa_h = pg_w + wb + OFF_SOAW;
        const __half* op_h = pg_w + wb + OFF_OP;
        const __half* f1_h = pg_w + wb + OFF_F1;
        const __half* f2_h = pg_w + wb + OFF_F2;

        // fused launch: value = src @ vp_w (fp16 out) || offaw = q @ soaw_w (fp32 out)
        dual_gemm<<<dim3(mblk, 5), blk, GEMM_SMEM>>>(
            pg_src_h, vp_h, vp_b + (size_t)i * 256, pg_val_h, 256, 2,
            pg_q_h, sa_h, so_b + (size_t)i * 256, aw_b + (size_t)i * 128,
            pg_offaw, 384, MROWS, 256);
        // deformable sampling -> attn fp16
        deform_kernel<<<deform_grid, 256>>>(pg_val_h, pg_offaw, pg_attn_h);
        // output proj
        mma_gemm<false, 0><<<dim3(mblk, 2), blk, GEMM_SMEM>>>(
            pg_attn_h, op_h, op_b + (size_t)i * 256, op_b + (size_t)i * 256, 256,
            pg_tmp, nullptr, MROWS, 256, 256);
        // src = LN(src + attn_proj)
        add_ln_kernel<<<ln_grid, 256>>>(pg_src, pg_tmp,
                                        n1_w + (size_t)i * DMODEL, n1_b + (size_t)i * DMODEL,
                                        nullptr, pg_src, pg_src_h, nullptr);
        // h = relu(src @ f1_w + f1_b)  (fp16 out)
        mma_gemm<true, 1><<<dim3(mblk, 8), blk, GEMM_SMEM>>>(
            pg_src_h, f1_h, f1_b + (size_t)i * DFFN, f1_b + (size_t)i * DFFN, DFFN,
            nullptr, pg_h_h, MROWS, 256, DFFN);
        // tmp = h @ f2_w + f2_b
        mma_gemm<false, 0><<<dim3(mblk, 2), blk, GEMM_SMEM>>>(
            pg_h_h, f2_h, f2_b + (size_t)i * 256, f2_b + (size_t)i * 256, 256,
            pg_tmp, nullptr, MROWS, 1024, 256);
        // src = LN(src + ffn), also emit q fp16 for next layer
        add_ln_kernel<<<ln_grid, 256>>>(pg_src, pg_tmp,
                                        n2_w + (size_t)i * DMODEL, n2_b + (size_t)i * DMODEL,
                                        pg_pos, pg_src, pg_src_h, pg_q_h);
    }

    write_out_kernel<<<(out_size + 255) / 256, 256>>>((float*)d_out, out_size);
}

// round 14
// speedup vs baseline: 2.5027x; 1.0400x over previous
#include <cuda_runtime.h>
#include <cuda_fp16.h>
#include <cstdint>
#include <math.h>

// ---------------- problem constants ----------------
#define L_TOT   13294          // 10000 + 2500 + 625 + 169
#define BATCH   4
#define MROWS   (BATCH * L_TOT)   // 53176
#define DMODEL  256
#define DFFN    1024
#define NLAYERS_C 6
#define NHEADS  8

// weight layout offsets (elements) within one layer block
#define OFF_VP    0
#define OFF_SOAW  65536          // combined so(256) + aw(128) rows => [384,256]
#define OFF_OP    163840
#define OFF_F1    229376
#define OFF_F2    491520
#define LW_STRIDE 753664

// ---------------- device scratch (static, allowed) ----------------
__device__ __align__(16) float g_src  [MROWS * DMODEL];
__device__ __align__(16) float g_pos  [MROWS * DMODEL];
__device__ __align__(16) float g_offaw[MROWS * 384];

__device__ __align__(16) __half g_tmp_h [MROWS * DMODEL];
__device__ __align__(16) __half g_val_h [MROWS * DMODEL];
__device__ __align__(16) __half g_src_h [MROWS * DMODEL];
__device__ __align__(16) __half g_q_h   [MROWS * DMODEL];
__device__ __align__(16) __half g_attn_h[MROWS * DMODEL];
__device__ __align__(16) __half g_h_h   [(size_t)MROWS * DFFN];
__device__ __align__(16) __half g_w     [NLAYERS_C * LW_STRIDE];

// ---------------- helpers ----------------
__device__ __forceinline__ uint32_t smem_u32(const void* p) {
    uint32_t a;
    asm("{ .reg .u64 t; cvta.to.shared.u64 t, %1; cvt.u32.u64 %0, t; }" : "=r"(a) : "l"(p));
    return a;
}

#define LDMX4(r, addr) \
    asm volatile("ldmatrix.sync.aligned.m8n8.x4.shared.b16 {%0,%1,%2,%3}, [%4];" \
        : "=r"((r)[0]), "=r"((r)[1]), "=r"((r)[2]), "=r"((r)[3]) : "r"(addr))

__device__ __forceinline__ void mma16816(float* c, const uint32_t* a, const uint32_t* b) {
    asm volatile(
        "mma.sync.aligned.m16n8k16.row.col.f32.f16.f16.f32 "
        "{%0,%1,%2,%3}, {%4,%5,%6,%7}, {%8,%9}, {%0,%1,%2,%3};\n"
        : "+f"(c[0]), "+f"(c[1]), "+f"(c[2]), "+f"(c[3])
        : "r"(a[0]), "r"(a[1]), "r"(a[2]), "r"(a[3]), "r"(b[0]), "r"(b[1]));
}

#define CP_ASYNC16(dst, src, sz) \
    asm volatile("cp.async.cg.shared.global [%0], [%1], 16, %2;" \
        :: "r"(dst), "l"(src), "r"(sz))
#define CP_COMMIT() asm volatile("cp.async.commit_group;" ::: "memory")
#define CP_WAIT0()  asm volatile("cp.async.wait_group 0;" ::: "memory")

// ---------------- GEMM body: CTA 128x128, BK=64, 2-stage cp.async -------------------
__device__ __forceinline__ void gemm_body(
    const __half* __restrict__ A, const __half* __restrict__ B,
    const float* __restrict__ bias, const float* __restrict__ bias2, int bias_split,
    float* __restrict__ Cf, __half* __restrict__ Ch,
    int Mr, int K, int N, int relu, int outmode, int row0, int col0, char* smem)
{
    const int ASZ = 128 * 144;         // 18432 B
    const int STG = 2 * ASZ;           // 36864 B per stage (A + B)

    const int tid  = threadIdx.x;
    const int lane = tid & 31;
    const int warp = tid >> 5;
    const int wm   = warp & 3;          // 0..3 (32 rows each)
    const int wn   = warp >> 2;         // 0..1 (64 cols each)

    const uint32_t smem_base = smem_u32(smem);

    const int rowb = tid >> 3;            // 0..31
    const int seg  = tid & 7;             // 16B segment

    float acc[2][8][4];
    #pragma unroll
    for (int i = 0; i < 2; i++)
        #pragma unroll
        for (int j = 0; j < 8; j++)
            #pragma unroll
            for (int k = 0; k < 4; k++) acc[i][j][k] = 0.f;

    const int nch = K >> 6;

    auto load_chunk = [&](int ch, int stage) {
        const int kb = ch << 6;
        const uint32_t sb = smem_base + stage * STG;
        #pragma unroll
        for (int r = 0; r < 4; r++) {
            const int rr = rowb + r * 32;
            {
                const int ok = (row0 + rr < Mr) ? 16 : 0;
                const size_t gg = (size_t)(row0 + rr) * K + kb + seg * 8;
                CP_ASYNC16(sb + rr * 144 + seg * 16, A + gg, ok);
            }
            {
                const size_t gg = (size_t)(col0 + rr) * K + kb + seg * 8;
                CP_ASYNC16(sb + ASZ + rr * 144 + seg * 16, B + gg, 16);
            }
        }
    };

    load_chunk(0, 0);
    CP_COMMIT();

    int stage = 0;
    for (int ch = 0; ch < nch; ch++) {
        CP_WAIT0();
        __syncthreads();
        if (ch + 1 < nch) {
            load_chunk(ch + 1, stage ^ 1);
            CP_COMMIT();
        }
        const uint32_t sb = smem_base + stage * STG;

        #pragma unroll
        for (int ks = 0; ks < 4; ks++) {
            const int k0 = ks << 4;
            uint32_t af[2][4];
            #pragma unroll
            for (int mt = 0; mt < 2; mt++) {
                const int arow = wm * 32 + mt * 16 + (lane & 15);
                const int acol = k0 + ((lane >> 4) << 3);
                LDMX4(af[mt], sb + arow * 144 + acol * 2);
            }
            #pragma unroll
            for (int np = 0; np < 4; np++) {
                const int tr = wn * 64 + np * 16 + ((lane >> 4) << 3) + (lane & 7);
                const int tc = k0 + (((lane >> 3) & 1) << 3);
                uint32_t t[4];
                LDMX4(t, sb + ASZ + tr * 144 + tc * 2);
                uint32_t b0[2] = { t[0], t[1] };
                uint32_t b1[2] = { t[2], t[3] };
                #pragma unroll
                for (int mt = 0; mt < 2; mt++) {
                    mma16816(acc[mt][np * 2 + 0], af[mt], b0);
                    mma16816(acc[mt][np * 2 + 1], af[mt], b1);
                }
            }
        }
        stage ^= 1;
    }

    // epilogue
    const int g  = lane >> 2;
    const int tg = lane & 3;
    #pragma unroll
    for (int mt = 0; mt < 2; mt++) {
        #pragma unroll
        for (int nt = 0; nt < 8; nt++) {
            const int col = col0 + wn * 64 + nt * 8 + tg * 2;
            float b0, b1;
            if (col < bias_split) {
                b0 = __ldg(bias + col);
                b1 = __ldg(bias + col + 1);
            } else {
                b0 = __ldg(bias2 + col - bias_split);
                b1 = __ldg(bias2 + col - bias_split + 1);
            }
            #pragma unroll
            for (int half_i = 0; half_i < 2; half_i++) {
                const int row = row0 + wm * 32 + mt * 16 + g + half_i * 8;
                if (row < Mr) {
                    float v0 = acc[mt][nt][half_i * 2 + 0] + b0;
                    float v1 = acc[mt][nt][half_i * 2 + 1] + b1;
                    if (relu) { v0 = fmaxf(v0, 0.f); v1 = fmaxf(v1, 0.f); }
                    if (outmode == 0) {
                        *reinterpret_cast<float2*>(Cf + (size_t)row * N + col) = make_float2(v0, v1);
                    } else {
                        *reinterpret_cast<__half2*>(Ch + (size_t)row * N + col) =
                            __halves2half2(__float2half(v0), __float2half(v1));
                    }
                }
            }
        }
    }
}

template<bool RELU, int OUTMODE>
__global__ __launch_bounds__(256, 2)
void mma_gemm(const __half* __restrict__ A, const __half* __restrict__ B,
              const float* __restrict__ bias, const float* __restrict__ bias2, int bias_split,
              float* __restrict__ Cf, __half* __restrict__ Ch,
              int Mr, int K, int N)
{
    extern __shared__ char smem[];
    gemm_body(A, B, bias, bias2, bias_split, Cf, Ch, Mr, K, N,
              RELU ? 1 : 0, OUTMODE, blockIdx.x * 128, blockIdx.y * 128, smem);
}

// Dual GEMM: y < ysplit -> GEMM1 (fp16 out), else GEMM2 (fp32 out, split bias).
__global__ __launch_bounds__(256, 2)
void dual_gemm(const __half* __restrict__ A1, const __half* __restrict__ B1,
               const float* __restrict__ bias1, __half* __restrict__ Ch1, int N1, int ysplit,
               const __half* __restrict__ A2, const __half* __restrict__ B2,
               const float* __restrict__ bias2a, const float* __restrict__ bias2b,
               float* __restrict__ Cf2, int N2,
               int Mr, int K)
{
    extern __shared__ char smem[];
    const int y = blockIdx.y;
    if (y < ysplit) {
        gemm_body(A1, B1, bias1, bias1, N1, nullptr, Ch1, Mr, K, N1,
                  0, 1, blockIdx.x * 128, y * 128, smem);
    } else {
        gemm_body(A2, B2, bias2a, bias2b, 256, Cf2, nullptr, Mr, K, N2,
                  0, 0, blockIdx.x * 128, (y - ysplit) * 128, smem);
    }
}

// ---------------- weight prep: ALL weight types + layers, one launch ----------------
__global__ void wprep_all_kernel(const float* __restrict__ vp, const float* __restrict__ so,
                                 const float* __restrict__ aw, const float* __restrict__ op,
                                 const float* __restrict__ f1, const float* __restrict__ f2,
                                 __half* __restrict__ dst)
{
    int idx = blockIdx.x * blockDim.x + threadIdx.x;
    if (idx >= NLAYERS_C * LW_STRIDE) return;
    int l = idx / LW_STRIDE;
    int r = idx - l * LW_STRIDE;
    const float* W;
    int K, N, r0;
    if (r < 131072) {
        if (r < 65536) { W = vp; K = 256; N = 256; r0 = r; }
        else           { W = so; K = 256; N = 256; r0 = r - 65536; }
    } else if (r < 229376) {
        if (r < 163840) { W = aw; K = 256; N = 128; r0 = r - 131072; }
        else            { W = op; K = 256; N = 256; r0 = r - 163840; }
    } else {
        if (r < 491520) { W = f1; K = 256;  N = 1024; r0 = r - 229376; }
        else            { W = f2; K = 1024; N = 256;  r0 = r - 491520; }
    }
    int n = r0 / K, k = r0 - n * K;
    dst[idx] = __float2half(__ldg(W + (size_t)l * K * N + (size_t)k * N + n));
}

// ---------------- flatten: (B,D,H,W) -> (B,L,D); emits src fp16 + q fp16 -----------
__global__ void flatten_kernel(const float* __restrict__ s0, const float* __restrict__ s1,
                               const float* __restrict__ s2, const float* __restrict__ s3,
                               const float* __restrict__ p0, const float* __restrict__ p1,
                               const float* __restrict__ p2, const float* __restrict__ p3,
                               const float* __restrict__ lvl_emb)
{
    long long idx = (long long)blockIdx.x * blockDim.x + threadIdx.x;
    const long long tot = (long long)MROWS * DMODEL;
    if (idx >= tot) return;
    int d = (int)(idx & 255);
    int m = (int)(idx >> 8);
    int b = m / L_TOT;
    int n = m - b * L_TOT;
    int lvl, hw, HW;
    const float *sp, *pp;
    if (n < 10000)      { lvl = 0; hw = n;         HW = 10000; sp = s0; pp = p0; }
    else if (n < 12500) { lvl = 1; hw = n - 10000; HW = 2500;  sp = s1; pp = p1; }
    else if (n < 13125) { lvl = 2; hw = n - 12500; HW = 625;   sp = s2; pp = p2; }
    else                { lvl = 3; hw = n - 13125; HW = 169;   sp = s3; pp = p3; }
    size_t sidx = ((size_t)b * DMODEL + d) * HW + hw;
    float sv = __ldg(sp + sidx);
    float pv = __ldg(pp + sidx) + __ldg(lvl_emb + lvl * DMODEL + d);
    g_src[idx] = sv;
    g_pos[idx] = pv;
    g_src_h[idx] = __float2half(sv);
    g_q_h[idx]   = __float2half(sv + pv);
}

// ---------------- deformable attention, two-phase (one warp per (b,q,head)) ---------
// Phase A: 16 lanes compute per-point clamped index (byte offset) + folded weight once,
//          packed into float2 smem.
// Phase B: 4 groups x 8 lanes; group owns 4 points, lane gathers 4 channels (LDG.64).
__global__ __launch_bounds__(256)
void deform_kernel(const __half* __restrict__ value,
                   const float* __restrict__ offaw,
                   __half* __restrict__ out_h)
{
    __shared__ float2 s_pack[8][16][4];   // (w, byteoff-as-float-bits)

    int gw = (int)((blockIdx.x * blockDim.x + threadIdx.x) >> 5);
    if (gw >= MROWS * NHEADS) return;
    const int lane = threadIdx.x & 31;
    const int wip  = (threadIdx.x >> 5) & 7;
    const int h = gw & 7;
    const int m = gw >> 3;
    const int b = m / L_TOT;
    const int q = m - b * L_TOT;

    // ---- Phase A
    {
        const int pl  = lane & 15;
        const int lvl = pl >> 2;
        float ref_x, ref_y;
        {
            int idx, Wl0;
            if (q < 10000)      { idx = q;         Wl0 = 100; }
            else if (q < 12500) { idx = q - 10000; Wl0 = 50;  }
            else if (q < 13125) { idx = q - 12500; Wl0 = 25;  }
            else                { idx = q - 13125; Wl0 = 13;  }
            int yy = idx / Wl0, xx = idx - yy * Wl0;
            ref_x = (xx + 0.5f) / (float)Wl0;
            ref_y = (yy + 0.5f) / (float)Wl0;
        }
        float logit = __ldg(offaw + (size_t)m * 384 + 256 + h * 16 + pl);
        float mx = logit;
        #pragma unroll
        for (int o = 8; o > 0; o >>= 1) mx = fmaxf(mx, __shfl_xor_sync(0xFFFFFFFFu, mx, o));
        float e = __expf(logit - mx);
        float ssum = e;
        #pragma unroll
        for (int o = 8; o > 0; o >>= 1) ssum += __shfl_xor_sync(0xFFFFFFFFu, ssum, o);
        float wgt = e / ssum;

        float ox = __ldg(offaw + (size_t)m * 384 + h * 32 + pl * 2);
        float oy = __ldg(offaw + (size_t)m * 384 + h * 32 + pl * 2 + 1);

        const int WlA[4] = {100, 50, 25, 13};
        const int stA[4] = {0, 10000, 12500, 13125};
        const int Wl = WlA[lvl], Hl = WlA[lvl], st = stA[lvl];
        const float fW = (float)Wl, fH = (float)Hl;

        float px = ref_x * fW + ox - 0.5f;
        float py = ref_y * fH + oy - 0.5f;
        float x0f = floorf(px), y0f = floorf(py);
        float wx1 = px - x0f, wy1 = py - y0f;
        int x0 = (int)x0f, y0 = (int)y0f;

        if (lane < 16) {
            #pragma unroll
            for (int t = 0; t < 4; t++) {
                int xi = x0 + (t & 1);
                int yi = y0 + (t >> 1);
                bool valid = (xi >= 0) & (xi < Wl) & (yi >= 0) & (yi < Hl);
                int xc = min(max(xi, 0), Wl - 1);
                int yc = min(max(yi, 0), Hl - 1);
                float w = ((t & 1) ? wx1 : 1.f - wx1) * ((t >> 1) ? wy1 : 1.f - wy1)
                          * wgt * (valid ? 1.f : 0.f);
                int byteoff = (st + yc * Wl + xc) * 512;   // row stride 256 half = 512 B
                s_pack[wip][pl][t] = make_float2(w, __int_as_float(byteoff));
            }
        }
    }
    __syncwarp();

    // ---- Phase B: 4 groups x 8 lanes, LDG.64 per tap (4 channels)
    const int g4  = lane >> 3;          // group 0..3 -> points g4, g4+4, g4+8, g4+12
    const int ch8 = lane & 7;           // 8-byte channel slot (4 half channels)
    const char* vbase = reinterpret_cast<const char*>(value + (size_t)b * L_TOT * 256 + h * 32)
                        + ch8 * 8;
    float4 acc = make_float4(0.f, 0.f, 0.f, 0.f);
    #pragma unroll
    for (int pp = 0; pp < 4; pp++) {
        const int pt = pp * 4 + g4;
        #pragma unroll
        for (int t = 0; t < 4; t++) {
            float2 pk = s_pack[wip][pt][t];
            float w = pk.x;
            uint2 v = __ldg(reinterpret_cast<const uint2*>(vbase + __float_as_int(pk.y)));
            float2 f0 = __half22float2(*reinterpret_cast<__half2*>(&v.x));
            float2 f1 = __half22float2(*reinterpret_cast<__half2*>(&v.y));
            acc.x = fmaf(w, f0.x, acc.x);
            acc.y = fmaf(w, f0.y, acc.y);
            acc.z = fmaf(w, f1.x, acc.z);
            acc.w = fmaf(w, f1.y, acc.w);
        }
    }
    #pragma unroll
    for (int o = 8; o <= 16; o <<= 1) {
        acc.x += __shfl_xor_sync(0xFFFFFFFFu, acc.x, o);
        acc.y += __shfl_xor_sync(0xFFFFFFFFu, acc.y, o);
        acc.z += __shfl_xor_sync(0xFFFFFFFFu, acc.z, o);
        acc.w += __shfl_xor_sync(0xFFFFFFFFu, acc.w, o);
    }
    if (g4 == 0) {
        __half2 h0 = __halves2half2(__float2half(acc.x), __float2half(acc.y));
        __half2 h1 = __halves2half2(__float2half(acc.z), __float2half(acc.w));
        uint2 pkd;
        pkd.x = *reinterpret_cast<uint32_t*>(&h0);
        pkd.y = *reinterpret_cast<uint32_t*>(&h1);
        *reinterpret_cast<uint2*>(out_h + (size_t)m * 256 + h * 32 + ch8 * 4) = pkd;
    }
}

// ---------------- fused residual add + LayerNorm (one warp per row) -----------------
// X fp32, R fp16 increment; emits fp32 out + fp16; if pos, q fp16 = fp16(out + pos)
__global__ void add_ln_kernel(const float* __restrict__ X, const __half* __restrict__ R,
                              const float* __restrict__ w, const float* __restrict__ b,
                              const float* __restrict__ pos,
                              float* __restrict__ out,
                              __half* __restrict__ out_h,
                              __half* __restrict__ q_h)
{
    int row = (int)((blockIdx.x * blockDim.x + threadIdx.x) >> 5);
    if (row >= MROWS) return;
    int lane = threadIdx.x & 31;
    const float*  x = X + (size_t)row * DMODEL;
    const __half* r = R + (size_t)row * DMODEL;
    float v[8];
    float s = 0.f;
    #pragma unroll
    for (int j = 0; j < 8; j++) {
        int c = lane + j * 32;
        v[j] = x[c] + __half2float(__ldg(r + c));
        s += v[j];
    }
    #pragma unroll
    for (int o = 16; o > 0; o >>= 1) s += __shfl_xor_sync(0xFFFFFFFFu, s, o);
    float mean = s * (1.f / 256.f);
    float qv = 0.f;
    #pragma unroll
    for (int j = 0; j < 8; j++) { float d = v[j] - mean; qv += d * d; }
    #pragma unroll
    for (int o = 16; o > 0; o >>= 1) qv += __shfl_xor_sync(0xFFFFFFFFu, qv, o);
    float invs = rsqrtf(qv * (1.f / 256.f) + 1e-5f);
    #pragma unroll
    for (int j = 0; j < 8; j++) {
        int c = lane + j * 32;
        float o = (v[j] - mean) * invs * __ldg(w + c) + __ldg(b + c);
        size_t oi = (size_t)row * DMODEL + c;
        out[oi] = o;
        out_h[oi] = __float2half(o);
        if (pos != nullptr) q_h[oi] = __float2half(o + __ldg(pos + oi));
    }
}

// ---------------- output write: src then level_start_index (as floats) -------------
__global__ void write_out_kernel(float* __restrict__ out, int n)
{
    long long i = (long long)blockIdx.x * blockDim.x + threadIdx.x;
    if (i >= n) return;
    const long long tot = (long long)MROWS * DMODEL;
    if (i < tot) {
        out[i] = g_src[i];
    } else {
        int k = (int)(i - tot);
        float st;
        switch (k) {
            case 0: st = 0.f;      break;
            case 1: st = 10000.f;  break;
            case 2: st = 12500.f;  break;
            case 3: st = 13125.f;  break;
            default: st = 0.f;     break;
        }
        out[i] = st;
    }
}

// ---------------- host launch ----------------
extern "C" void kernel_launch(void* const* d_in, const int* in_sizes, int n_in,
                              void* d_out, int out_size)
{
    // setup_inputs() dict order is INTERLEAVED: src0, pos0, src1, pos1, ...
    const float* s0 = (const float*)d_in[0];
    const float* p0 = (const float*)d_in[1];
    const float* s1 = (const float*)d_in[2];
    const float* p1 = (const float*)d_in[3];
    const float* s2 = (const float*)d_in[4];
    const float* p2 = (const float*)d_in[5];
    const float* s3 = (const float*)d_in[6];
    const float* p3 = (const float*)d_in[7];
    const float* lvl_emb = (const float*)d_in[8];
    const float* so_w = (const float*)d_in[9];
    const float* so_b = (const float*)d_in[10];
    const float* aw_w = (const float*)d_in[11];
    const float* aw_b = (const float*)d_in[12];
    const float* vp_w = (const float*)d_in[13];
    const float* vp_b = (const float*)d_in[14];
    const float* op_w = (const float*)d_in[15];
    const float* op_b = (const float*)d_in[16];
    const float* n1_w = (const float*)d_in[17];
    const float* n1_b = (const float*)d_in[18];
    const float* f1_w = (const float*)d_in[19];
    const float* f1_b = (const float*)d_in[20];
    const float* f2_w = (const float*)d_in[21];
    const float* f2_b = (const float*)d_in[22];
    const float* n2_w = (const float*)d_in[23];
    const float* n2_b = (const float*)d_in[24];

    float *pg_src, *pg_pos, *pg_offaw;
    __half *pg_tmp_h, *pg_val_h, *pg_src_h, *pg_q_h, *pg_attn_h, *pg_h_h, *pg_w;
    cudaGetSymbolAddress((void**)&pg_src,   g_src);
    cudaGetSymbolAddress((void**)&pg_pos,   g_pos);
    cudaGetSymbolAddress((void**)&pg_offaw, g_offaw);
    cudaGetSymbolAddress((void**)&pg_tmp_h, g_tmp_h);
    cudaGetSymbolAddress((void**)&pg_val_h, g_val_h);
    cudaGetSymbolAddress((void**)&pg_src_h, g_src_h);
    cudaGetSymbolAddress((void**)&pg_q_h,   g_q_h);
    cudaGetSymbolAddress((void**)&pg_attn_h, g_attn_h);
    cudaGetSymbolAddress((void**)&pg_h_h,   g_h_h);
    cudaGetSymbolAddress((void**)&pg_w,     g_w);

    // dynamic smem: 2 stages x 36864 B
    const int GEMM_SMEM = 73728;
    cudaFuncSetAttribute(mma_gemm<false, 0>, cudaFuncAttributeMaxDynamicSharedMemorySize, GEMM_SMEM);
    cudaFuncSetAttribute(mma_gemm<false, 1>, cudaFuncAttributeMaxDynamicSharedMemorySize, GEMM_SMEM);
    cudaFuncSetAttribute(mma_gemm<true, 1>,  cudaFuncAttributeMaxDynamicSharedMemorySize, GEMM_SMEM);
    cudaFuncSetAttribute(dual_gemm,          cudaFuncAttributeMaxDynamicSharedMemorySize, GEMM_SMEM);

    const long long totElem = (long long)MROWS * DMODEL;
    const int ew_grid = (int)((totElem + 255) / 256);

    wprep_all_kernel<<<(NLAYERS_C * LW_STRIDE + 255) / 256, 256>>>(
        vp_w, so_w, aw_w, op_w, f1_w, f2_w, pg_w);
    flatten_kernel<<<ew_grid, 256>>>(s0, s1, s2, s3, p0, p1, p2, p3, lvl_emb);

    const int mblk = (MROWS + 127) / 128;   // 416
    const dim3 blk(256);
    const int ln_grid = (MROWS * 32 + 255) / 256;
    const int deform_grid = (MROWS * NHEADS * 32 + 255) / 256;

    for (int i = 0; i < NLAYERS_C; i++) {
        size_t wb = (size_t)i * LW_STRIDE;
        const __half* vp_h = pg_w + wb + OFF_VP;
        const __half* sa_h = pg_w + wb + OFF_SOAW;
        const __half* op_h = pg_w + wb + OFF_OP;
        const __half* f1_h = pg_w + wb + OFF_F1;
        const __half* f2_h = pg_w + wb + OFF_F2;

        // fused launch: value = src @ vp_w (fp16 out) || offaw = q @ soaw_w (fp32 out)
        dual_gemm<<<dim3(mblk, 5), blk, GEMM_SMEM>>>(
            pg_src_h, vp_h, vp_b + (size_t)i * 256, pg_val_h, 256, 2,
            pg_q_h, sa_h, so_b + (size_t)i * 256, aw_b + (size_t)i * 128,
            pg_offaw, 384, MROWS, 256);
        // deformable sampling -> attn fp16
        deform_kernel<<<deform_grid, 256>>>(pg_val_h, pg_offaw, pg_attn_h);
        // output proj (fp16 increment out)
        mma_gemm<false, 1><<<dim3(mblk, 2), blk, GEMM_SMEM>>>(
            pg_attn_h, op_h, op_b + (size_t)i * 256, op_b + (size_t)i * 256, 256,
            nullptr, pg_tmp_h, MROWS, 256, 256);
        // src = LN(src + attn_proj)
        add_ln_kernel<<<ln_grid, 256>>>(pg_src, pg_tmp_h,
                                        n1_w + (size_t)i * DMODEL, n1_b + (size_t)i * DMODEL,
                                        nullptr, pg_src, pg_src_h, nullptr);
        // h = relu(src @ f1_w + f1_b)  (fp16 out)
        mma_gemm<true, 1><<<dim3(mblk, 8), blk, GEMM_SMEM>>>(
            pg_src_h, f1_h, f1_b + (size_t)i * DFFN, f1_b + (size_t)i * DFFN, DFFN,
            nullptr, pg_h_h, MROWS, 256, DFFN);
        // tmp = h @ f2_w + f2_b  (fp16 increment out)
        mma_gemm<false, 1><<<dim3(mblk, 2), blk, GEMM_SMEM>>>(
            pg_h_h, f2_h, f2_b + (size_t)i * 256, f2_b + (size_t)i * 256, 256,
            nullptr, pg_tmp_h, MROWS, 1024, 256);
        // src = LN(src + ffn), also emit q fp16 for next layer
        add_ln_kernel<<<ln_grid, 256>>>(pg_src, pg_tmp_h,
                                        n2_w + (size_t)i * DMODEL, n2_b + (size_t)i * DMODEL,
                                        pg_pos, pg_src, pg_src_h, pg_q_h);
    }

    write_out_kernel<<<(out_size + 255) / 256, 256>>>((float*)d_out, out_size);
}

// round 15
// speedup vs baseline: 2.5896x; 1.0347x over previous
#include <cuda_runtime.h>
#include <cuda_fp16.h>
#include <cstdint>
#include <math.h>

// ---------------- problem constants ----------------
#define L_TOT   13294          // 10000 + 2500 + 625 + 169
#define BATCH   4
#define MROWS   (BATCH * L_TOT)   // 53176
#define DMODEL  256
#define DFFN    1024
#define NLAYERS_C 6
#define NHEADS  8

// weight layout offsets (elements) within one layer block
#define OFF_VP    0
#define OFF_SOAW  65536          // combined so(256) + aw(128) rows => [384,256]
#define OFF_OP    163840
#define OFF_F1    229376
#define OFF_F2    491520
#define LW_STRIDE 753664

// ---------------- device scratch (static, allowed) ----------------
__device__ __align__(16) float g_src  [MROWS * DMODEL];
__device__ __align__(16) float g_pos  [MROWS * DMODEL];
__device__ __align__(16) float g_offaw[MROWS * 384];

__device__ __align__(16) __half g_tmp_h [MROWS * DMODEL];
__device__ __align__(16) __half g_val_h [MROWS * DMODEL];
__device__ __align__(16) __half g_src_h [MROWS * DMODEL];
__device__ __align__(16) __half g_q_h   [MROWS * DMODEL];
__device__ __align__(16) __half g_attn_h[MROWS * DMODEL];
__device__ __align__(16) __half g_h_h   [(size_t)MROWS * DFFN];
__device__ __align__(16) __half g_w     [NLAYERS_C * LW_STRIDE];

// ---------------- helpers ----------------
__device__ __forceinline__ uint32_t smem_u32(const void* p) {
    uint32_t a;
    asm("{ .reg .u64 t; cvta.to.shared.u64 t, %1; cvt.u32.u64 %0, t; }" : "=r"(a) : "l"(p));
    return a;
}

#define LDMX4(r, addr) \
    asm volatile("ldmatrix.sync.aligned.m8n8.x4.shared.b16 {%0,%1,%2,%3}, [%4];" \
        : "=r"((r)[0]), "=r"((r)[1]), "=r"((r)[2]), "=r"((r)[3]) : "r"(addr))

__device__ __forceinline__ void mma16816(float* c, const uint32_t* a, const uint32_t* b) {
    asm volatile(
        "mma.sync.aligned.m16n8k16.row.col.f32.f16.f16.f32 "
        "{%0,%1,%2,%3}, {%4,%5,%6,%7}, {%8,%9}, {%0,%1,%2,%3};\n"
        : "+f"(c[0]), "+f"(c[1]), "+f"(c[2]), "+f"(c[3])
        : "r"(a[0]), "r"(a[1]), "r"(a[2]), "r"(a[3]), "r"(b[0]), "r"(b[1]));
}

#define CP_ASYNC16(dst, src, sz) \
    asm volatile("cp.async.cg.shared.global [%0], [%1], 16, %2;" \
        :: "r"(dst), "l"(src), "r"(sz))
#define CP_COMMIT() asm volatile("cp.async.commit_group;" ::: "memory")
#define CP_WAIT0()  asm volatile("cp.async.wait_group 0;" ::: "memory")

// ---------------- GEMM body: CTA 128x128, BK=64, 2-stage cp.async -------------------
__device__ __forceinline__ void gemm_body(
    const __half* __restrict__ A, const __half* __restrict__ B,
    const float* __restrict__ bias, const float* __restrict__ bias2, int bias_split,
    float* __restrict__ Cf, __half* __restrict__ Ch,
    int Mr, int K, int N, int relu, int outmode, int row0, int col0, char* smem)
{
    const int ASZ = 128 * 144;         // 18432 B
    const int STG = 2 * ASZ;           // 36864 B per stage (A + B)

    const int tid  = threadIdx.x;
    const int lane = tid & 31;
    const int warp = tid >> 5;
    const int wm   = warp & 3;          // 0..3 (32 rows each)
    const int wn   = warp >> 2;         // 0..1 (64 cols each)

    const uint32_t smem_base = smem_u32(smem);

    const int rowb = tid >> 3;            // 0..31
    const int seg  = tid & 7;             // 16B segment

    float acc[2][8][4];
    #pragma unroll
    for (int i = 0; i < 2; i++)
        #pragma unroll
        for (int j = 0; j < 8; j++)
            #pragma unroll
            for (int k = 0; k < 4; k++) acc[i][j][k] = 0.f;

    const int nch = K >> 6;

    auto load_chunk = [&](int ch, int stage) {
        const int kb = ch << 6;
        const uint32_t sb = smem_base + stage * STG;
        #pragma unroll
        for (int r = 0; r < 4; r++) {
            const int rr = rowb + r * 32;
            {
                const int ok = (row0 + rr < Mr) ? 16 : 0;
                const size_t gg = (size_t)(row0 + rr) * K + kb + seg * 8;
                CP_ASYNC16(sb + rr * 144 + seg * 16, A + gg, ok);
            }
            {
                const size_t gg = (size_t)(col0 + rr) * K + kb + seg * 8;
                CP_ASYNC16(sb + ASZ + rr * 144 + seg * 16, B + gg, 16);
            }
        }
    };

    load_chunk(0, 0);
    CP_COMMIT();

    int stage = 0;
    for (int ch = 0; ch < nch; ch++) {
        CP_WAIT0();
        __syncthreads();
        if (ch + 1 < nch) {
            load_chunk(ch + 1, stage ^ 1);
            CP_COMMIT();
        }
        const uint32_t sb = smem_base + stage * STG;

        #pragma unroll
        for (int ks = 0; ks < 4; ks++) {
            const int k0 = ks << 4;
            uint32_t af[2][4];
            #pragma unroll
            for (int mt = 0; mt < 2; mt++) {
                const int arow = wm * 32 + mt * 16 + (lane & 15);
                const int acol = k0 + ((lane >> 4) << 3);
                LDMX4(af[mt], sb + arow * 144 + acol * 2);
            }
            #pragma unroll
            for (int np = 0; np < 4; np++) {
                const int tr = wn * 64 + np * 16 + ((lane >> 4) << 3) + (lane & 7);
                const int tc = k0 + (((lane >> 3) & 1) << 3);
                uint32_t t[4];
                LDMX4(t, sb + ASZ + tr * 144 + tc * 2);
                uint32_t b0[2] = { t[0], t[1] };
                uint32_t b1[2] = { t[2], t[3] };
                #pragma unroll
                for (int mt = 0; mt < 2; mt++) {
                    mma16816(acc[mt][np * 2 + 0], af[mt], b0);
                    mma16816(acc[mt][np * 2 + 1], af[mt], b1);
                }
            }
        }
        stage ^= 1;
    }

    // epilogue
    const int g  = lane >> 2;
    const int tg = lane & 3;
    #pragma unroll
    for (int mt = 0; mt < 2; mt++) {
        #pragma unroll
        for (int nt = 0; nt < 8; nt++) {
            const int col = col0 + wn * 64 + nt * 8 + tg * 2;
            float b0, b1;
            if (col < bias_split) {
                b0 = __ldg(bias + col);
                b1 = __ldg(bias + col + 1);
            } else {
                b0 = __ldg(bias2 + col - bias_split);
                b1 = __ldg(bias2 + col - bias_split + 1);
            }
            #pragma unroll
            for (int half_i = 0; half_i < 2; half_i++) {
                const int row = row0 + wm * 32 + mt * 16 + g + half_i * 8;
                if (row < Mr) {
                    float v0 = acc[mt][nt][half_i * 2 + 0] + b0;
                    float v1 = acc[mt][nt][half_i * 2 + 1] + b1;
                    if (relu) { v0 = fmaxf(v0, 0.f); v1 = fmaxf(v1, 0.f); }
                    if (outmode == 0) {
                        *reinterpret_cast<float2*>(Cf + (size_t)row * N + col) = make_float2(v0, v1);
                    } else {
                        *reinterpret_cast<__half2*>(Ch + (size_t)row * N + col) =
                            __halves2half2(__float2half(v0), __float2half(v1));
                    }
                }
            }
        }
    }
}

template<bool RELU, int OUTMODE>
__global__ __launch_bounds__(256, 2)
void mma_gemm(const __half* __restrict__ A, const __half* __restrict__ B,
              const float* __restrict__ bias, const float* __restrict__ bias2, int bias_split,
              float* __restrict__ Cf, __half* __restrict__ Ch,
              int Mr, int K, int N)
{
    extern __shared__ char smem[];
    gemm_body(A, B, bias, bias2, bias_split, Cf, Ch, Mr, K, N,
              RELU ? 1 : 0, OUTMODE, blockIdx.x * 128, blockIdx.y * 128, smem);
}

// Dual GEMM: y < ysplit -> GEMM1 (fp16 out), else GEMM2 (fp32 out, split bias).
__global__ __launch_bounds__(256, 2)
void dual_gemm(const __half* __restrict__ A1, const __half* __restrict__ B1,
               const float* __restrict__ bias1, __half* __restrict__ Ch1, int N1, int ysplit,
               const __half* __restrict__ A2, const __half* __restrict__ B2,
               const float* __restrict__ bias2a, const float* __restrict__ bias2b,
               float* __restrict__ Cf2, int N2,
               int Mr, int K)
{
    extern __shared__ char smem[];
    const int y = blockIdx.y;
    if (y < ysplit) {
        gemm_body(A1, B1, bias1, bias1, N1, nullptr, Ch1, Mr, K, N1,
                  0, 1, blockIdx.x * 128, y * 128, smem);
    } else {
        gemm_body(A2, B2, bias2a, bias2b, 256, Cf2, nullptr, Mr, K, N2,
                  0, 0, blockIdx.x * 128, (y - ysplit) * 128, smem);
    }
}

// ---------------- weight prep: ALL weight types + layers, one launch ----------------
__global__ void wprep_all_kernel(const float* __restrict__ vp, const float* __restrict__ so,
                                 const float* __restrict__ aw, const float* __restrict__ op,
                                 const float* __restrict__ f1, const float* __restrict__ f2,
                                 __half* __restrict__ dst)
{
    int idx = blockIdx.x * blockDim.x + threadIdx.x;
    if (idx >= NLAYERS_C * LW_STRIDE) return;
    int l = idx / LW_STRIDE;
    int r = idx - l * LW_STRIDE;
    const float* W;
    int K, N, r0;
    if (r < 131072) {
        if (r < 65536) { W = vp; K = 256; N = 256; r0 = r; }
        else           { W = so; K = 256; N = 256; r0 = r - 65536; }
    } else if (r < 229376) {
        if (r < 163840) { W = aw; K = 256; N = 128; r0 = r - 131072; }
        else            { W = op; K = 256; N = 256; r0 = r - 163840; }
    } else {
        if (r < 491520) { W = f1; K = 256;  N = 1024; r0 = r - 229376; }
        else            { W = f2; K = 1024; N = 256;  r0 = r - 491520; }
    }
    int n = r0 / K, k = r0 - n * K;
    dst[idx] = __float2half(__ldg(W + (size_t)l * K * N + (size_t)k * N + n));
}

// ---------------- flatten: (B,D,H,W) -> (B,L,D); emits src fp16 + q fp16 -----------
__global__ void flatten_kernel(const float* __restrict__ s0, const float* __restrict__ s1,
                               const float* __restrict__ s2, const float* __restrict__ s3,
                               const float* __restrict__ p0, const float* __restrict__ p1,
                               const float* __restrict__ p2, const float* __restrict__ p3,
                               const float* __restrict__ lvl_emb)
{
    long long idx = (long long)blockIdx.x * blockDim.x + threadIdx.x;
    const long long tot = (long long)MROWS * DMODEL;
    if (idx >= tot) return;
    int d = (int)(idx & 255);
    int m = (int)(idx >> 8);
    int b = m / L_TOT;
    int n = m - b * L_TOT;
    int lvl, hw, HW;
    const float *sp, *pp;
    if (n < 10000)      { lvl = 0; hw = n;         HW = 10000; sp = s0; pp = p0; }
    else if (n < 12500) { lvl = 1; hw = n - 10000; HW = 2500;  sp = s1; pp = p1; }
    else if (n < 13125) { lvl = 2; hw = n - 12500; HW = 625;   sp = s2; pp = p2; }
    else                { lvl = 3; hw = n - 13125; HW = 169;   sp = s3; pp = p3; }
    size_t sidx = ((size_t)b * DMODEL + d) * HW + hw;
    float sv = __ldg(sp + sidx);
    float pv = __ldg(pp + sidx) + __ldg(lvl_emb + lvl * DMODEL + d);
    g_src[idx] = sv;
    g_pos[idx] = pv;
    g_src_h[idx] = __float2half(sv);
    g_q_h[idx]   = __float2half(sv + pv);
}

// ---------------- deformable attention, two-phase (one warp per (b,q,head)) ---------
// Phase A: 16 lanes compute per-point byte offset + weight (packed half2) once.
// Phase B: 4 groups x 8 lanes; group owns 4 points, lane gathers 4 channels (LDG.64),
//          per-point HFMA2 accumulation, fp32 across points.
__global__ __launch_bounds__(256)
void deform_kernel(const __half* __restrict__ value,
                   const float* __restrict__ offaw,
                   __half* __restrict__ out_h)
{
    __shared__ uint2 s_pk[8][16][4];   // (w as half2-broadcast bits, byteoff)

    int gw = (int)((blockIdx.x * blockDim.x + threadIdx.x) >> 5);
    if (gw >= MROWS * NHEADS) return;
    const int lane = threadIdx.x & 31;
    const int wip  = (threadIdx.x >> 5) & 7;
    const int h = gw & 7;
    const int m = gw >> 3;
    const int b = m / L_TOT;
    const int q = m - b * L_TOT;

    // ---- Phase A
    {
        const int pl  = lane & 15;
        const int lvl = pl >> 2;
        float ref_x, ref_y;
        {
            int idx, Wl0;
            if (q < 10000)      { idx = q;         Wl0 = 100; }
            else if (q < 12500) { idx = q - 10000; Wl0 = 50;  }
            else if (q < 13125) { idx = q - 12500; Wl0 = 25;  }
            else                { idx = q - 13125; Wl0 = 13;  }
            int yy = idx / Wl0, xx = idx - yy * Wl0;
            ref_x = (xx + 0.5f) / (float)Wl0;
            ref_y = (yy + 0.5f) / (float)Wl0;
        }
        // softmax over 16 logits (|logit| small -> no max subtraction needed)
        float logit = __ldg(offaw + (size_t)m * 384 + 256 + h * 16 + pl);
        float e = __expf(logit);
        float ssum = e;
        #pragma unroll
        for (int o = 8; o > 0; o >>= 1) ssum += __shfl_xor_sync(0xFFFFFFFFu, ssum, o);
        float wgt = e / ssum;

        float ox = __ldg(offaw + (size_t)m * 384 + h * 32 + pl * 2);
        float oy = __ldg(offaw + (size_t)m * 384 + h * 32 + pl * 2 + 1);

        const int WlA[4] = {100, 50, 25, 13};
        const int stA[4] = {0, 10000, 12500, 13125};
        const int Wl = WlA[lvl], Hl = WlA[lvl], st = stA[lvl];
        const float fW = (float)Wl, fH = (float)Hl;

        float px = ref_x * fW + ox - 0.5f;
        float py = ref_y * fH + oy - 0.5f;
        float x0f = floorf(px), y0f = floorf(py);
        float wx1 = px - x0f, wy1 = py - y0f;
        int x0 = (int)x0f, y0 = (int)y0f;

        if (lane < 16) {
            #pragma unroll
            for (int t = 0; t < 4; t++) {
                int xi = x0 + (t & 1);
                int yi = y0 + (t >> 1);
                bool valid = (xi >= 0) & (xi < Wl) & (yi >= 0) & (yi < Hl);
                int xc = min(max(xi, 0), Wl - 1);
                int yc = min(max(yi, 0), Hl - 1);
                float w = ((t & 1) ? wx1 : 1.f - wx1) * ((t >> 1) ? wy1 : 1.f - wy1)
                          * wgt * (valid ? 1.f : 0.f);
                uint32_t byteoff = (uint32_t)(st + yc * Wl + xc) * 512u;
                __half2 wh = __half2half2(__float2half(w));
                s_pk[wip][pl][t] = make_uint2(*reinterpret_cast<uint32_t*>(&wh), byteoff);
            }
        }
    }
    __syncwarp();

    // ---- Phase B: 4 groups x 8 lanes; per-point half2 accumulation
    const int g4  = lane >> 3;          // group 0..3 -> points pp*4+g4
    const int ch8 = lane & 7;           // 8-byte channel slot (4 half channels)
    const char* vbase = reinterpret_cast<const char*>(value + (size_t)b * L_TOT * 256 + h * 32)
                        + ch8 * 8;
    float4 acc = make_float4(0.f, 0.f, 0.f, 0.f);
    #pragma unroll
    for (int pp = 0; pp < 4; pp++) {
        const int pt = pp * 4 + g4;
        __half2 a0 = __half2half2(__float2half(0.f));
        __half2 a1 = a0;
        #pragma unroll
        for (int t = 0; t < 4; t++) {
            uint2 pk = s_pk[wip][pt][t];
            uint2 v = __ldg(reinterpret_cast<const uint2*>(vbase + pk.y));
            __half2 wh = *reinterpret_cast<__half2*>(&pk.x);
            a0 = __hfma2(wh, *reinterpret_cast<__half2*>(&v.x), a0);
            a1 = __hfma2(wh, *reinterpret_cast<__half2*>(&v.y), a1);
        }
        float2 f0 = __half22float2(a0);
        float2 f1 = __half22float2(a1);
        acc.x += f0.x; acc.y += f0.y; acc.z += f1.x; acc.w += f1.y;
    }
    #pragma unroll
    for (int o = 8; o <= 16; o <<= 1) {
        acc.x += __shfl_xor_sync(0xFFFFFFFFu, acc.x, o);
        acc.y += __shfl_xor_sync(0xFFFFFFFFu, acc.y, o);
        acc.z += __shfl_xor_sync(0xFFFFFFFFu, acc.z, o);
        acc.w += __shfl_xor_sync(0xFFFFFFFFu, acc.w, o);
    }
    if (g4 == 0) {
        __half2 h0 = __halves2half2(__float2half(acc.x), __float2half(acc.y));
        __half2 h1 = __halves2half2(__float2half(acc.z), __float2half(acc.w));
        uint2 pkd;
        pkd.x = *reinterpret_cast<uint32_t*>(&h0);
        pkd.y = *reinterpret_cast<uint32_t*>(&h1);
        *reinterpret_cast<uint2*>(out_h + (size_t)m * 256 + h * 32 + ch8 * 4) = pkd;
    }
}

// ---------------- fused residual add + LayerNorm (one warp per row) -----------------
// X fp32, R fp16 increment; emits fp32 out + fp16; if pos, q fp16 = fp16(out + pos)
__global__ void add_ln_kernel(const float* __restrict__ X, const __half* __restrict__ R,
                              const float* __restrict__ w, const float* __restrict__ b,
                              const float* __restrict__ pos,
                              float* __restrict__ out,
                              __half* __restrict__ out_h,
                              __half* __restrict__ q_h)
{
    int row = (int)((blockIdx.x * blockDim.x + threadIdx.x) >> 5);
    if (row >= MROWS) return;
    int lane = threadIdx.x & 31;
    const float*  x = X + (size_t)row * DMODEL;
    const __half* r = R + (size_t)row * DMODEL;
    float v[8];
    float s = 0.f;
    #pragma unroll
    for (int j = 0; j < 8; j++) {
        int c = lane + j * 32;
        v[j] = x[c] + __half2float(__ldg(r + c));
        s += v[j];
    }
    #pragma unroll
    for (int o = 16; o > 0; o >>= 1) s += __shfl_xor_sync(0xFFFFFFFFu, s, o);
    float mean = s * (1.f / 256.f);
    float qv = 0.f;
    #pragma unroll
    for (int j = 0; j < 8; j++) { float d = v[j] - mean; qv += d * d; }
    #pragma unroll
    for (int o = 16; o > 0; o >>= 1) qv += __shfl_xor_sync(0xFFFFFFFFu, qv, o);
    float invs = rsqrtf(qv * (1.f / 256.f) + 1e-5f);
    #pragma unroll
    for (int j = 0; j < 8; j++) {
        int c = lane + j * 32;
        float o = (v[j] - mean) * invs * __ldg(w + c) + __ldg(b + c);
        size_t oi = (size_t)row * DMODEL + c;
        out[oi] = o;
        out_h[oi] = __float2half(o);
        if (pos != nullptr) q_h[oi] = __float2half(o + __ldg(pos + oi));
    }
}

// ---------------- output write: src then level_start_index (as floats) -------------
__global__ void write_out_kernel(float* __restrict__ out, int n)
{
    long long i = (long long)blockIdx.x * blockDim.x + threadIdx.x;
    if (i >= n) return;
    const long long tot = (long long)MROWS * DMODEL;
    if (i < tot) {
        out[i] = g_src[i];
    } else {
        int k = (int)(i - tot);
        float st;
        switch (k) {
            case 0: st = 0.f;      break;
            case 1: st = 10000.f;  break;
            case 2: st = 12500.f;  break;
            case 3: st = 13125.f;  break;
            default: st = 0.f;     break;
        }
        out[i] = st;
    }
}

// ---------------- host launch ----------------
extern "C" void kernel_launch(void* const* d_in, const int* in_sizes, int n_in,
                              void* d_out, int out_size)
{
    // setup_inputs() dict order is INTERLEAVED: src0, pos0, src1, pos1, ...
    const float* s0 = (const float*)d_in[0];
    const float* p0 = (const float*)d_in[1];
    const float* s1 = (const float*)d_in[2];
    const float* p1 = (const float*)d_in[3];
    const float* s2 = (const float*)d_in[4];
    const float* p2 = (const float*)d_in[5];
    const float* s3 = (const float*)d_in[6];
    const float* p3 = (const float*)d_in[7];
    const float* lvl_emb = (const float*)d_in[8];
    const float* so_w = (const float*)d_in[9];
    const float* so_b = (const float*)d_in[10];
    const float* aw_w = (const float*)d_in[11];
    const float* aw_b = (const float*)d_in[12];
    const float* vp_w = (const float*)d_in[13];
    const float* vp_b = (const float*)d_in[14];
    const float* op_w = (const float*)d_in[15];
    const float* op_b = (const float*)d_in[16];
    const float* n1_w = (const float*)d_in[17];
    const float* n1_b = (const float*)d_in[18];
    const float* f1_w = (const float*)d_in[19];
    const float* f1_b = (const float*)d_in[20];
    const float* f2_w = (const float*)d_in[21];
    const float* f2_b = (const float*)d_in[22];
    const float* n2_w = (const float*)d_in[23];
    const float* n2_b = (const float*)d_in[24];

    float *pg_src, *pg_pos, *pg_offaw;
    __half *pg_tmp_h, *pg_val_h, *pg_src_h, *pg_q_h, *pg_attn_h, *pg_h_h, *pg_w;
    cudaGetSymbolAddress((void**)&pg_src,   g_src);
    cudaGetSymbolAddress((void**)&pg_pos,   g_pos);
    cudaGetSymbolAddress((void**)&pg_offaw, g_offaw);
    cudaGetSymbolAddress((void**)&pg_tmp_h, g_tmp_h);
    cudaGetSymbolAddress((void**)&pg_val_h, g_val_h);
    cudaGetSymbolAddress((void**)&pg_src_h, g_src_h);
    cudaGetSymbolAddress((void**)&pg_q_h,   g_q_h);
    cudaGetSymbolAddress((void**)&pg_attn_h, g_attn_h);
    cudaGetSymbolAddress((void**)&pg_h_h,   g_h_h);
    cudaGetSymbolAddress((void**)&pg_w,     g_w);

    // dynamic smem: 2 stages x 36864 B
    const int GEMM_SMEM = 73728;
    cudaFuncSetAttribute(mma_gemm<false, 0>, cudaFuncAttributeMaxDynamicSharedMemorySize, GEMM_SMEM);
    cudaFuncSetAttribute(mma_gemm<false, 1>, cudaFuncAttributeMaxDynamicSharedMemorySize, GEMM_SMEM);
    cudaFuncSetAttribute(mma_gemm<true, 1>,  cudaFuncAttributeMaxDynamicSharedMemorySize, GEMM_SMEM);
    cudaFuncSetAttribute(dual_gemm,          cudaFuncAttributeMaxDynamicSharedMemorySize, GEMM_SMEM);

    const long long totElem = (long long)MROWS * DMODEL;
    const int ew_grid = (int)((totElem + 255) / 256);

    wprep_all_kernel<<<(NLAYERS_C * LW_STRIDE + 255) / 256, 256>>>(
        vp_w, so_w, aw_w, op_w, f1_w, f2_w, pg_w);
    flatten_kernel<<<ew_grid, 256>>>(s0, s1, s2, s3, p0, p1, p2, p3, lvl_emb);

    const int mblk = (MROWS + 127) / 128;   // 416
    const dim3 blk(256);
    const int ln_grid = (MROWS * 32 + 255) / 256;
    const int deform_grid = (MROWS * NHEADS * 32 + 255) / 256;

    for (int i = 0; i < NLAYERS_C; i++) {
        size_t wb = (size_t)i * LW_STRIDE;
        const __half* vp_h = pg_w + wb + OFF_VP;
        const __half* sa_h = pg_w + wb + OFF_SOAW;
        const __half* op_h = pg_w + wb + OFF_OP;
        const __half* f1_h = pg_w + wb + OFF_F1;
        const __half* f2_h = pg_w + wb + OFF_F2;

        // fused launch: value = src @ vp_w (fp16 out) || offaw = q @ soaw_w (fp32 out)
        dual_gemm<<<dim3(mblk, 5), blk, GEMM_SMEM>>>(
            pg_src_h, vp_h, vp_b + (size_t)i * 256, pg_val_h, 256, 2,
            pg_q_h, sa_h, so_b + (size_t)i * 256, aw_b + (size_t)i * 128,
            pg_offaw, 384, MROWS, 256);
        // deformable sampling -> attn fp16
        deform_kernel<<<deform_grid, 256>>>(pg_val_h, pg_offaw, pg_attn_h);
        // output proj (fp16 increment out)
        mma_gemm<false, 1><<<dim3(mblk, 2), blk, GEMM_SMEM>>>(
            pg_attn_h, op_h, op_b + (size_t)i * 256, op_b + (size_t)i * 256, 256,
            nullptr, pg_tmp_h, MROWS, 256, 256);
        // src = LN(src + attn_proj)
        add_ln_kernel<<<ln_grid, 256>>>(pg_src, pg_tmp_h,
                                        n1_w + (size_t)i * DMODEL, n1_b + (size_t)i * DMODEL,
                                        nullptr, pg_src, pg_src_h, nullptr);
        // h = relu(src @ f1_w + f1_b)  (fp16 out)
        mma_gemm<true, 1><<<dim3(mblk, 8), blk, GEMM_SMEM>>>(
            pg_src_h, f1_h, f1_b + (size_t)i * DFFN, f1_b + (size_t)i * DFFN, DFFN,
            nullptr, pg_h_h, MROWS, 256, DFFN);
        // tmp = h @ f2_w + f2_b  (fp16 increment out)
        mma_gemm<false, 1><<<dim3(mblk, 2), blk, GEMM_SMEM>>>(
            pg_h_h, f2_h, f2_b + (size_t)i * 256, f2_b + (size_t)i * 256, 256,
            nullptr, pg_tmp_h, MROWS, 1024, 256);
        // src = LN(src + ffn), also emit q fp16 for next layer
        add_ln_kernel<<<ln_grid, 256>>>(pg_src, pg_tmp_h,
                                        n2_w + (size_t)i * DMODEL, n2_b + (size_t)i * DMODEL,
                                        pg_pos, pg_src, pg_src_h, pg_q_h);
    }

    write_out_kernel<<<(out_size + 255) / 256, 256>>>((float*)d_out, out_size);
}

// round 16
// speedup vs baseline: 2.6395x; 1.0193x over previous
#include <cuda_runtime.h>
#include <cuda_fp16.h>
#include <cstdint>
#include <math.h>

// ---------------- problem constants ----------------
#define L_TOT   13294          // 10000 + 2500 + 625 + 169
#define BATCH   4
#define MROWS   (BATCH * L_TOT)   // 53176
#define DMODEL  256
#define DFFN    1024
#define NLAYERS_C 6
#define NHEADS  8

// weight layout offsets (elements) within one layer block
#define OFF_VP    0
#define OFF_SOAW  65536          // combined so(256) + aw(128) rows => [384,256]
#define OFF_OP    163840
#define OFF_F1    229376
#define OFF_F2    491520
#define LW_STRIDE 753664

// ---------------- device scratch (static, allowed) ----------------
__device__ __align__(16) float g_src  [MROWS * DMODEL];
__device__ __align__(16) float g_pos  [MROWS * DMODEL];
__device__ __align__(16) float g_offaw[MROWS * 384];

__device__ __align__(16) __half g_tmp_h [MROWS * DMODEL];
__device__ __align__(16) __half g_val_h [MROWS * DMODEL];
__device__ __align__(16) __half g_src_h [MROWS * DMODEL];
__device__ __align__(16) __half g_q_h   [MROWS * DMODEL];
__device__ __align__(16) __half g_attn_h[MROWS * DMODEL];
__device__ __align__(16) __half g_h_h   [(size_t)MROWS * DFFN];
__device__ __align__(16) __half g_w     [NLAYERS_C * LW_STRIDE];

// ---------------- helpers ----------------
__device__ __forceinline__ uint32_t smem_u32(const void* p) {
    uint32_t a;
    asm("{ .reg .u64 t; cvta.to.shared.u64 t, %1; cvt.u32.u64 %0, t; }" : "=r"(a) : "l"(p));
    return a;
}

#define LDMX4(r, addr) \
    asm volatile("ldmatrix.sync.aligned.m8n8.x4.shared.b16 {%0,%1,%2,%3}, [%4];" \
        : "=r"((r)[0]), "=r"((r)[1]), "=r"((r)[2]), "=r"((r)[3]) : "r"(addr))

__device__ __forceinline__ void mma16816(float* c, const uint32_t* a, const uint32_t* b) {
    asm volatile(
        "mma.sync.aligned.m16n8k16.row.col.f32.f16.f16.f32 "
        "{%0,%1,%2,%3}, {%4,%5,%6,%7}, {%8,%9}, {%0,%1,%2,%3};\n"
        : "+f"(c[0]), "+f"(c[1]), "+f"(c[2]), "+f"(c[3])
        : "r"(a[0]), "r"(a[1]), "r"(a[2]), "r"(a[3]), "r"(b[0]), "r"(b[1]));
}

#define CP_ASYNC16(dst, src, sz) \
    asm volatile("cp.async.cg.shared.global [%0], [%1], 16, %2;" \
        :: "r"(dst), "l"(src), "r"(sz))
#define CP_COMMIT() asm volatile("cp.async.commit_group;" ::: "memory")
#define CP_WAIT0()  asm volatile("cp.async.wait_group 0;" ::: "memory")

// ---------------- GEMM body: CTA 128x128, BK=64, 2-stage cp.async -------------------
__device__ __forceinline__ void gemm_body(
    const __half* __restrict__ A, const __half* __restrict__ B,
    const float* __restrict__ bias, const float* __restrict__ bias2, int bias_split,
    float* __restrict__ Cf, __half* __restrict__ Ch,
    int Mr, int K, int N, int relu, int outmode, int row0, int col0, char* smem)
{
    const int ASZ = 128 * 144;         // 18432 B
    const int STG = 2 * ASZ;           // 36864 B per stage (A + B)

    const int tid  = threadIdx.x;
    const int lane = tid & 31;
    const int warp = tid >> 5;
    const int wm   = warp & 3;          // 0..3 (32 rows each)
    const int wn   = warp >> 2;         // 0..1 (64 cols each)

    const uint32_t smem_base = smem_u32(smem);

    const int rowb = tid >> 3;            // 0..31
    const int seg  = tid & 7;             // 16B segment

    float acc[2][8][4];
    #pragma unroll
    for (int i = 0; i < 2; i++)
        #pragma unroll
        for (int j = 0; j < 8; j++)
            #pragma unroll
            for (int k = 0; k < 4; k++) acc[i][j][k] = 0.f;

    const int nch = K >> 6;

    auto load_chunk = [&](int ch, int stage) {
        const int kb = ch << 6;
        const uint32_t sb = smem_base + stage * STG;
        #pragma unroll
        for (int r = 0; r < 4; r++) {
            const int rr = rowb + r * 32;
            {
                const int ok = (row0 + rr < Mr) ? 16 : 0;
                const size_t gg = (size_t)(row0 + rr) * K + kb + seg * 8;
                CP_ASYNC16(sb + rr * 144 + seg * 16, A + gg, ok);
            }
            {
                const size_t gg = (size_t)(col0 + rr) * K + kb + seg * 8;
                CP_ASYNC16(sb + ASZ + rr * 144 + seg * 16, B + gg, 16);
            }
        }
    };

    load_chunk(0, 0);
    CP_COMMIT();

    int stage = 0;
    for (int ch = 0; ch < nch; ch++) {
        CP_WAIT0();
        __syncthreads();
        if (ch + 1 < nch) {
            load_chunk(ch + 1, stage ^ 1);
            CP_COMMIT();
        }
        const uint32_t sb = smem_base + stage * STG;

        #pragma unroll
        for (int ks = 0; ks < 4; ks++) {
            const int k0 = ks << 4;
            uint32_t af[2][4];
            #pragma unroll
            for (int mt = 0; mt < 2; mt++) {
                const int arow = wm * 32 + mt * 16 + (lane & 15);
                const int acol = k0 + ((lane >> 4) << 3);
                LDMX4(af[mt], sb + arow * 144 + acol * 2);
            }
            #pragma unroll
            for (int np = 0; np < 4; np++) {
                const int tr = wn * 64 + np * 16 + ((lane >> 4) << 3) + (lane & 7);
                const int tc = k0 + (((lane >> 3) & 1) << 3);
                uint32_t t[4];
                LDMX4(t, sb + ASZ + tr * 144 + tc * 2);
                uint32_t b0[2] = { t[0], t[1] };
                uint32_t b1[2] = { t[2], t[3] };
                #pragma unroll
                for (int mt = 0; mt < 2; mt++) {
                    mma16816(acc[mt][np * 2 + 0], af[mt], b0);
                    mma16816(acc[mt][np * 2 + 1], af[mt], b1);
                }
            }
        }
        stage ^= 1;
    }

    // epilogue
    const int g  = lane >> 2;
    const int tg = lane & 3;
    #pragma unroll
    for (int mt = 0; mt < 2; mt++) {
        #pragma unroll
        for (int nt = 0; nt < 8; nt++) {
            const int col = col0 + wn * 64 + nt * 8 + tg * 2;
            float b0, b1;
            if (col < bias_split) {
                b0 = __ldg(bias + col);
                b1 = __ldg(bias + col + 1);
            } else {
                b0 = __ldg(bias2 + col - bias_split);
                b1 = __ldg(bias2 + col - bias_split + 1);
            }
            #pragma unroll
            for (int half_i = 0; half_i < 2; half_i++) {
                const int row = row0 + wm * 32 + mt * 16 + g + half_i * 8;
                if (row < Mr) {
                    float v0 = acc[mt][nt][half_i * 2 + 0] + b0;
                    float v1 = acc[mt][nt][half_i * 2 + 1] + b1;
                    if (relu) { v0 = fmaxf(v0, 0.f); v1 = fmaxf(v1, 0.f); }
                    if (outmode == 0) {
                        *reinterpret_cast<float2*>(Cf + (size_t)row * N + col) = make_float2(v0, v1);
                    } else {
                        *reinterpret_cast<__half2*>(Ch + (size_t)row * N + col) =
                            __halves2half2(__float2half(v0), __float2half(v1));
                    }
                }
            }
        }
    }
}

template<bool RELU, int OUTMODE>
__global__ __launch_bounds__(256, 2)
void mma_gemm(const __half* __restrict__ A, const __half* __restrict__ B,
              const float* __restrict__ bias, const float* __restrict__ bias2, int bias_split,
              float* __restrict__ Cf, __half* __restrict__ Ch,
              int Mr, int K, int N)
{
    extern __shared__ char smem[];
    gemm_body(A, B, bias, bias2, bias_split, Cf, Ch, Mr, K, N,
              RELU ? 1 : 0, OUTMODE, blockIdx.x * 128, blockIdx.y * 128, smem);
}

// Dual GEMM: y < ysplit -> GEMM1 (fp16 out), else GEMM2 (fp32 out, split bias).
__global__ __launch_bounds__(256, 2)
void dual_gemm(const __half* __restrict__ A1, const __half* __restrict__ B1,
               const float* __restrict__ bias1, __half* __restrict__ Ch1, int N1, int ysplit,
               const __half* __restrict__ A2, const __half* __restrict__ B2,
               const float* __restrict__ bias2a, const float* __restrict__ bias2b,
               float* __restrict__ Cf2, int N2,
               int Mr, int K)
{
    extern __shared__ char smem[];
    const int y = blockIdx.y;
    if (y < ysplit) {
        gemm_body(A1, B1, bias1, bias1, N1, nullptr, Ch1, Mr, K, N1,
                  0, 1, blockIdx.x * 128, y * 128, smem);
    } else {
        gemm_body(A2, B2, bias2a, bias2b, 256, Cf2, nullptr, Mr, K, N2,
                  0, 0, blockIdx.x * 128, (y - ysplit) * 128, smem);
    }
}

// ---------------- weight prep: ALL weight types + layers, one launch ----------------
__global__ void wprep_all_kernel(const float* __restrict__ vp, const float* __restrict__ so,
                                 const float* __restrict__ aw, const float* __restrict__ op,
                                 const float* __restrict__ f1, const float* __restrict__ f2,
                                 __half* __restrict__ dst)
{
    int idx = blockIdx.x * blockDim.x + threadIdx.x;
    if (idx >= NLAYERS_C * LW_STRIDE) return;
    int l = idx / LW_STRIDE;
    int r = idx - l * LW_STRIDE;
    const float* W;
    int K, N, r0;
    if (r < 131072) {
        if (r < 65536) { W = vp; K = 256; N = 256; r0 = r; }
        else           { W = so; K = 256; N = 256; r0 = r - 65536; }
    } else if (r < 229376) {
        if (r < 163840) { W = aw; K = 256; N = 128; r0 = r - 131072; }
        else            { W = op; K = 256; N = 256; r0 = r - 163840; }
    } else {
        if (r < 491520) { W = f1; K = 256;  N = 1024; r0 = r - 229376; }
        else            { W = f2; K = 1024; N = 256;  r0 = r - 491520; }
    }
    int n = r0 / K, k = r0 - n * K;
    dst[idx] = __float2half(__ldg(W + (size_t)l * K * N + (size_t)k * N + n));
}

// ---------------- flatten: (B,D,H,W) -> (B,L,D); emits src fp16 + q fp16 -----------
__global__ void flatten_kernel(const float* __restrict__ s0, const float* __restrict__ s1,
                               const float* __restrict__ s2, const float* __restrict__ s3,
                               const float* __restrict__ p0, const float* __restrict__ p1,
                               const float* __restrict__ p2, const float* __restrict__ p3,
                               const float* __restrict__ lvl_emb)
{
    long long idx = (long long)blockIdx.x * blockDim.x + threadIdx.x;
    const long long tot = (long long)MROWS * DMODEL;
    if (idx >= tot) return;
    int d = (int)(idx & 255);
    int m = (int)(idx >> 8);
    int b = m / L_TOT;
    int n = m - b * L_TOT;
    int lvl, hw, HW;
    const float *sp, *pp;
    if (n < 10000)      { lvl = 0; hw = n;         HW = 10000; sp = s0; pp = p0; }
    else if (n < 12500) { lvl = 1; hw = n - 10000; HW = 2500;  sp = s1; pp = p1; }
    else if (n < 13125) { lvl = 2; hw = n - 12500; HW = 625;   sp = s2; pp = p2; }
    else                { lvl = 3; hw = n - 13125; HW = 169;   sp = s3; pp = p3; }
    size_t sidx = ((size_t)b * DMODEL + d) * HW + hw;
    float sv = __ldg(sp + sidx);
    float pv = __ldg(pp + sidx) + __ldg(lvl_emb + lvl * DMODEL + d);
    g_src[idx] = sv;
    g_pos[idx] = pv;
    g_src_h[idx] = __float2half(sv);
    g_q_h[idx]   = __float2half(sv + pv);
}

// ---------------- deformable attention, two-phase (one warp per (b,q,head)) ---------
// Phase A: 16 lanes pack per-point taps as two uint4 (w-half2, byteoff pairs).
// Phase B: 4 groups x 8 lanes; per-2-point half2 accumulation, fp32 across pairs.
__global__ __launch_bounds__(256)
void deform_kernel(const __half* __restrict__ value,
                   const float* __restrict__ offaw,
                   __half* __restrict__ out_h)
{
    __shared__ uint4 s_pk[8][16][2];   // [warp][point][tap-pair]: (w01,off0,w1?,off1)

    int gw = (int)((blockIdx.x * blockDim.x + threadIdx.x) >> 5);
    if (gw >= MROWS * NHEADS) return;
    const int lane = threadIdx.x & 31;
    const int wip  = (threadIdx.x >> 5) & 7;
    const int h = gw & 7;
    const int m = gw >> 3;
    const int b = m / L_TOT;
    const int q = m - b * L_TOT;

    // ---- Phase A
    {
        const int pl  = lane & 15;
        const int lvl = pl >> 2;
        float ref_x, ref_y;
        {
            int idx, Wl0;
            if (q < 10000)      { idx = q;         Wl0 = 100; }
            else if (q < 12500) { idx = q - 10000; Wl0 = 50;  }
            else if (q < 13125) { idx = q - 12500; Wl0 = 25;  }
            else                { idx = q - 13125; Wl0 = 13;  }
            int yy = idx / Wl0, xx = idx - yy * Wl0;
            ref_x = (xx + 0.5f) / (float)Wl0;
            ref_y = (yy + 0.5f) / (float)Wl0;
        }
        float logit = __ldg(offaw + (size_t)m * 384 + 256 + h * 16 + pl);
        float e = __expf(logit);
        float ssum = e;
        #pragma unroll
        for (int o = 8; o > 0; o >>= 1) ssum += __shfl_xor_sync(0xFFFFFFFFu, ssum, o);
        float wgt = e / ssum;

        float ox = __ldg(offaw + (size_t)m * 384 + h * 32 + pl * 2);
        float oy = __ldg(offaw + (size_t)m * 384 + h * 32 + pl * 2 + 1);

        const int WlA[4] = {100, 50, 25, 13};
        const int stA[4] = {0, 10000, 12500, 13125};
        const int Wl = WlA[lvl], Hl = WlA[lvl], st = stA[lvl];
        const float fW = (float)Wl, fH = (float)Hl;

        float px = ref_x * fW + ox - 0.5f;
        float py = ref_y * fH + oy - 0.5f;
        float x0f = floorf(px), y0f = floorf(py);
        float wx1 = px - x0f, wy1 = py - y0f;
        int x0 = (int)x0f, y0 = (int)y0f;

        if (lane < 16) {
            uint32_t wb[4], ob[4];
            #pragma unroll
            for (int t = 0; t < 4; t++) {
                int xi = x0 + (t & 1);
                int yi = y0 + (t >> 1);
                bool valid = (xi >= 0) & (xi < Wl) & (yi >= 0) & (yi < Hl);
                int xc = min(max(xi, 0), Wl - 1);
                int yc = min(max(yi, 0), Hl - 1);
                float w = ((t & 1) ? wx1 : 1.f - wx1) * ((t >> 1) ? wy1 : 1.f - wy1)
                          * wgt * (valid ? 1.f : 0.f);
                __half2 wh = __half2half2(__float2half(w));
                wb[t] = *reinterpret_cast<uint32_t*>(&wh);
                ob[t] = (uint32_t)(st + yc * Wl + xc) * 512u;
            }
            s_pk[wip][pl][0] = make_uint4(wb[0], ob[0], wb[1], ob[1]);
            s_pk[wip][pl][1] = make_uint4(wb[2], ob[2], wb[3], ob[3]);
        }
    }
    __syncwarp();

    // ---- Phase B: 4 groups x 8 lanes; half2 accumulation over 2-point spans
    const int g4  = lane >> 3;          // group 0..3 -> points pp*4+g4
    const int ch8 = lane & 7;           // 8-byte channel slot (4 half channels)
    const char* vbase = reinterpret_cast<const char*>(value + (size_t)b * L_TOT * 256 + h * 32)
                        + ch8 * 8;
    float4 acc = make_float4(0.f, 0.f, 0.f, 0.f);
    __half2 a0 = __half2half2(__float2half(0.f));
    __half2 a1 = a0;
    #pragma unroll
    for (int pp = 0; pp < 4; pp++) {
        const int pt = pp * 4 + g4;
        const uint4 kA = s_pk[wip][pt][0];
        const uint4 kB = s_pk[wip][pt][1];
        uint2 v;
        v = __ldg(reinterpret_cast<const uint2*>(vbase + kA.y));
        a0 = __hfma2(*reinterpret_cast<const __half2*>(&kA.x), *reinterpret_cast<__half2*>(&v.x), a0);
        a1 = __hfma2(*reinterpret_cast<const __half2*>(&kA.x), *reinterpret_cast<__half2*>(&v.y), a1);
        v = __ldg(reinterpret_cast<const uint2*>(vbase + kA.w));
        a0 = __hfma2(*reinterpret_cast<const __half2*>(&kA.z), *reinterpret_cast<__half2*>(&v.x), a0);
        a1 = __hfma2(*reinterpret_cast<const __half2*>(&kA.z), *reinterpret_cast<__half2*>(&v.y), a1);
        v = __ldg(reinterpret_cast<const uint2*>(vbase + kB.y));
        a0 = __hfma2(*reinterpret_cast<const __half2*>(&kB.x), *reinterpret_cast<__half2*>(&v.x), a0);
        a1 = __hfma2(*reinterpret_cast<const __half2*>(&kB.x), *reinterpret_cast<__half2*>(&v.y), a1);
        v = __ldg(reinterpret_cast<const uint2*>(vbase + kB.w));
        a0 = __hfma2(*reinterpret_cast<const __half2*>(&kB.z), *reinterpret_cast<__half2*>(&v.x), a0);
        a1 = __hfma2(*reinterpret_cast<const __half2*>(&kB.z), *reinterpret_cast<__half2*>(&v.y), a1);
        if (pp & 1) {
            float2 f0 = __half22float2(a0);
            float2 f1 = __half22float2(a1);
            acc.x += f0.x; acc.y += f0.y; acc.z += f1.x; acc.w += f1.y;
            a0 = __half2half2(__float2half(0.f));
            a1 = a0;
        }
    }
    #pragma unroll
    for (int o = 8; o <= 16; o <<= 1) {
        acc.x += __shfl_xor_sync(0xFFFFFFFFu, acc.x, o);
        acc.y += __shfl_xor_sync(0xFFFFFFFFu, acc.y, o);
        acc.z += __shfl_xor_sync(0xFFFFFFFFu, acc.z, o);
        acc.w += __shfl_xor_sync(0xFFFFFFFFu, acc.w, o);
    }
    if (g4 == 0) {
        __half2 h0 = __halves2half2(__float2half(acc.x), __float2half(acc.y));
        __half2 h1 = __halves2half2(__float2half(acc.z), __float2half(acc.w));
        uint2 pkd;
        pkd.x = *reinterpret_cast<uint32_t*>(&h0);
        pkd.y = *reinterpret_cast<uint32_t*>(&h1);
        *reinterpret_cast<uint2*>(out_h + (size_t)m * 256 + h * 32 + ch8 * 4) = pkd;
    }
}

// ---------------- fused residual add + LayerNorm (one warp per row) -----------------
// X fp32, R fp16 increment; emits fp32 out + fp16; if pos, q fp16 = fp16(out + pos)
__global__ void add_ln_kernel(const float* __restrict__ X, const __half* __restrict__ R,
                              const float* __restrict__ w, const float* __restrict__ b,
                              const float* __restrict__ pos,
                              float* __restrict__ out,
                              __half* __restrict__ out_h,
                              __half* __restrict__ q_h)
{
    int row = (int)((blockIdx.x * blockDim.x + threadIdx.x) >> 5);
    if (row >= MROWS) return;
    int lane = threadIdx.x & 31;
    const float*  x = X + (size_t)row * DMODEL;
    const __half* r = R + (size_t)row * DMODEL;
    float v[8];
    float s = 0.f;
    #pragma unroll
    for (int j = 0; j < 8; j++) {
        int c = lane + j * 32;
        v[j] = x[c] + __half2float(__ldg(r + c));
        s += v[j];
    }
    #pragma unroll
    for (int o = 16; o > 0; o >>= 1) s += __shfl_xor_sync(0xFFFFFFFFu, s, o);
    float mean = s * (1.f / 256.f);
    float qv = 0.f;
    #pragma unroll
    for (int j = 0; j < 8; j++) { float d = v[j] - mean; qv += d * d; }
    #pragma unroll
    for (int o = 16; o > 0; o >>= 1) qv += __shfl_xor_sync(0xFFFFFFFFu, qv, o);
    float invs = rsqrtf(qv * (1.f / 256.f) + 1e-5f);
    #pragma unroll
    for (int j = 0; j < 8; j++) {
        int c = lane + j * 32;
        float o = (v[j] - mean) * invs * __ldg(w + c) + __ldg(b + c);
        size_t oi = (size_t)row * DMODEL + c;
        out[oi] = o;
        out_h[oi] = __float2half(o);
        if (pos != nullptr) q_h[oi] = __float2half(o + __ldg(pos + oi));
    }
}

// ---------------- tail write: level_start_index as floats at out[MROWS*DMODEL..] ----
__global__ void write_tail_kernel(float* __restrict__ out, int n)
{
    int i = threadIdx.x;
    const long long tot = (long long)MROWS * DMODEL;
    if (tot + i < n) {
        float st = (i == 0) ? 0.f : (i == 1) ? 10000.f : (i == 2) ? 12500.f : 13125.f;
        if (i < 4) out[tot + i] = st;
    }
}

// ---------------- host launch ----------------
extern "C" void kernel_launch(void* const* d_in, const int* in_sizes, int n_in,
                              void* d_out, int out_size)
{
    // setup_inputs() dict order is INTERLEAVED: src0, pos0, src1, pos1, ...
    const float* s0 = (const float*)d_in[0];
    const float* p0 = (const float*)d_in[1];
    const float* s1 = (const float*)d_in[2];
    const float* p1 = (const float*)d_in[3];
    const float* s2 = (const float*)d_in[4];
    const float* p2 = (const float*)d_in[5];
    const float* s3 = (const float*)d_in[6];
    const float* p3 = (const float*)d_in[7];
    const float* lvl_emb = (const float*)d_in[8];
    const float* so_w = (const float*)d_in[9];
    const float* so_b = (const float*)d_in[10];
    const float* aw_w = (const float*)d_in[11];
    const float* aw_b = (const float*)d_in[12];
    const float* vp_w = (const float*)d_in[13];
    const float* vp_b = (const float*)d_in[14];
    const float* op_w = (const float*)d_in[15];
    const float* op_b = (const float*)d_in[16];
    const float* n1_w = (const float*)d_in[17];
    const float* n1_b = (const float*)d_in[18];
    const float* f1_w = (const float*)d_in[19];
    const float* f1_b = (const float*)d_in[20];
    const float* f2_w = (const float*)d_in[21];
    const float* f2_b = (const float*)d_in[22];
    const float* n2_w = (const float*)d_in[23];
    const float* n2_b = (const float*)d_in[24];

    float *pg_src, *pg_pos, *pg_offaw;
    __half *pg_tmp_h, *pg_val_h, *pg_src_h, *pg_q_h, *pg_attn_h, *pg_h_h, *pg_w;
    cudaGetSymbolAddress((void**)&pg_src,   g_src);
    cudaGetSymbolAddress((void**)&pg_pos,   g_pos);
    cudaGetSymbolAddress((void**)&pg_offaw, g_offaw);
    cudaGetSymbolAddress((void**)&pg_tmp_h, g_tmp_h);
    cudaGetSymbolAddress((void**)&pg_val_h, g_val_h);
    cudaGetSymbolAddress((void**)&pg_src_h, g_src_h);
    cudaGetSymbolAddress((void**)&pg_q_h,   g_q_h);
    cudaGetSymbolAddress((void**)&pg_attn_h, g_attn_h);
    cudaGetSymbolAddress((void**)&pg_h_h,   g_h_h);
    cudaGetSymbolAddress((void**)&pg_w,     g_w);

    // dynamic smem: 2 stages x 36864 B
    const int GEMM_SMEM = 73728;
    cudaFuncSetAttribute(mma_gemm<false, 0>, cudaFuncAttributeMaxDynamicSharedMemorySize, GEMM_SMEM);
    cudaFuncSetAttribute(mma_gemm<false, 1>, cudaFuncAttributeMaxDynamicSharedMemorySize, GEMM_SMEM);
    cudaFuncSetAttribute(mma_gemm<true, 1>,  cudaFuncAttributeMaxDynamicSharedMemorySize, GEMM_SMEM);
    cudaFuncSetAttribute(dual_gemm,          cudaFuncAttributeMaxDynamicSharedMemorySize, GEMM_SMEM);

    const long long totElem = (long long)MROWS * DMODEL;
    const int ew_grid = (int)((totElem + 255) / 256);

    wprep_all_kernel<<<(NLAYERS_C * LW_STRIDE + 255) / 256, 256>>>(
        vp_w, so_w, aw_w, op_w, f1_w, f2_w, pg_w);
    flatten_kernel<<<ew_grid, 256>>>(s0, s1, s2, s3, p0, p1, p2, p3, lvl_emb);

    const int mblk = (MROWS + 127) / 128;   // 416
    const dim3 blk(256);
    const int ln_grid = (MROWS * 32 + 255) / 256;
    const int deform_grid = (MROWS * NHEADS * 32 + 255) / 256;

    for (int i = 0; i < NLAYERS_C; i++) {
        size_t wb = (size_t)i * LW_STRIDE;
        const __half* vp_h = pg_w + wb + OFF_VP;
        const __half* sa_h = pg_w + wb + OFF_SOAW;
        const __half* op_h = pg_w + wb + OFF_OP;
        const __half* f1_h = pg_w + wb + OFF_F1;
        const __half* f2_h = pg_w + wb + OFF_F2;
        const bool last = (i == NLAYERS_C - 1);

        // fused launch: value = src @ vp_w (fp16 out) || offaw = q @ soaw_w (fp32 out)
        dual_gemm<<<dim3(mblk, 5), blk, GEMM_SMEM>>>(
            pg_src_h, vp_h, vp_b + (size_t)i * 256, pg_val_h, 256, 2,
            pg_q_h, sa_h, so_b + (size_t)i * 256, aw_b + (size_t)i * 128,
            pg_offaw, 384, MROWS, 256);
        // deformable sampling -> attn fp16
        deform_kernel<<<deform_grid, 256>>>(pg_val_h, pg_offaw, pg_attn_h);
        // output proj (fp16 increment out)
        mma_gemm<false, 1><<<dim3(mblk, 2), blk, GEMM_SMEM>>>(
            pg_attn_h, op_h, op_b + (size_t)i * 256, op_b + (size_t)i * 256, 256,
            nullptr, pg_tmp_h, MROWS, 256, 256);
        // src = LN(src + attn_proj)
        add_ln_kernel<<<ln_grid, 256>>>(pg_src, pg_tmp_h,
                                        n1_w + (size_t)i * DMODEL, n1_b + (size_t)i * DMODEL,
                                        nullptr, pg_src, pg_src_h, nullptr);
        // h = relu(src @ f1_w + f1_b)  (fp16 out)
        mma_gemm<true, 1><<<dim3(mblk, 8), blk, GEMM_SMEM>>>(
            pg_src_h, f1_h, f1_b + (size_t)i * DFFN, f1_b + (size_t)i * DFFN, DFFN,
            nullptr, pg_h_h, MROWS, 256, DFFN);
        // tmp = h @ f2_w + f2_b  (fp16 increment out)
        mma_gemm<false, 1><<<dim3(mblk, 2), blk, GEMM_SMEM>>>(
            pg_h_h, f2_h, f2_b + (size_t)i * 256, f2_b + (size_t)i * 256, 256,
            nullptr, pg_tmp_h, MROWS, 1024, 256);
        // src = LN(src + ffn); last layer writes fp32 directly into d_out
        add_ln_kernel<<<ln_grid, 256>>>(pg_src, pg_tmp_h,
                                        n2_w + (size_t)i * DMODEL, n2_b + (size_t)i * DMODEL,
                                        last ? nullptr : pg_pos,
                                        last ? (float*)d_out : pg_src,
                                        pg_src_h,
                                        last ? nullptr : pg_q_h);
    }

    write_tail_kernel<<<1, 32>>>((float*)d_out, out_size);
}